// round 5
// baseline (speedup 1.0000x reference)
#include <cuda_runtime.h>
#include <cuda_bf16.h>
#include <mma.h>
#include <cstdint>

using namespace nvcuda;

#define Bb     2
#define Ss     1024
#define Dd     1024
#define Hh     16
#define HDh    64
#define NT     (Bb*Ss)
#define Ee     31
#define INTERi 1024
#define EPSf   1e-5f
#define SLOTS  (NT*3)

// ---------------- scratch ----------------
__device__ float g_xn  [NT*Dd];
__device__ float g_qb  [NT*Dd];
__device__ float g_kb  [NT*Dd];
__device__ float g_vb  [NT*Dd];
__device__ float g_ctx [NT*Dd];
__device__ float g_attn[NT*Dd];
__device__ float g_an  [NT*Dd];
__device__ float g_t1  [NT*INTERi];
__device__ float g_h   [SLOTS*INTERi];
__device__ float g_part[SLOTS*Dd];
__device__ int   g_topi[SLOTS];
__device__ float g_topv[SLOTS];
__device__ int   g_cnt[Ee];
__device__ int   g_off[Ee];
__device__ int   g_cur[Ee];
__device__ int   g_slot_tok [SLOTS];
__device__ int   g_slot_rank[SLOTS];
__device__ float g_slot_gate[SLOTS];

__device__ __forceinline__ float gelu_f(float v) {
    return 0.5f * v * (1.0f + erff(v * 0.70710678118654752f));
}

__device__ __forceinline__ void split2(float x, float y, uint32_t& hi, uint32_t& lo) {
    __nv_bfloat16 hx = __float2bfloat16(x), hy = __float2bfloat16(y);
    __nv_bfloat16 lx = __float2bfloat16(x - __bfloat162float(hx));
    __nv_bfloat16 ly = __float2bfloat16(y - __bfloat162float(hy));
    __nv_bfloat162 H = __halves2bfloat162(hx, hy);
    __nv_bfloat162 L = __halves2bfloat162(lx, ly);
    hi = *(uint32_t*)&H; lo = *(uint32_t*)&L;
}

// ================= wmma bf16 split GEMM core =================
// CTA tile 128x128, K chunk 32, 256 threads (8 warps), warp tile 64x32.
typedef wmma::fragment<wmma::accumulator, 16, 16, 16, float> FragC;
typedef wmma::fragment<wmma::matrix_a, 16, 16, 16, __nv_bfloat16, wmma::row_major> FragA;
typedef wmma::fragment<wmma::matrix_b, 16, 16, 16, __nv_bfloat16, wmma::row_major> FragB;

#define LDA 40      // A smem leading dim (elems), 32 + 8 pad
#define LDB 136     // B smem leading dim (elems), 128 + 8 pad
#define LDC 132     // C staging leading dim (floats)
#define OFF_AH 0
#define OFF_AL (128*LDA*2)                 // 10240
#define OFF_BH (2*128*LDA*2)               // 20480
#define OFF_BL (OFF_BH + 32*LDB*2)         // 29184
#define DYN_SMEM (128*LDC*4)               // 67584 (epilogue staging is the max)

// Mainloop: accumulate full K=1024. A rows gathered via rowmap (-1 => zero row).
__device__ __forceinline__ void wm_mainloop(
    const float* __restrict__ Asrc, const float* __restrict__ Bsrc, int nb,
    const int* rowmap, char* sm, FragC accs[4][2])
{
    int tid = threadIdx.x, wid = tid >> 5;
    int wm = wid & 1, wn = wid >> 1;
    __nv_bfloat16* Ah = (__nv_bfloat16*)(sm + OFF_AH);
    __nv_bfloat16* Al = (__nv_bfloat16*)(sm + OFF_AL);
    __nv_bfloat16* Bh = (__nv_bfloat16*)(sm + OFF_BH);
    __nv_bfloat16* Bl = (__nv_bfloat16*)(sm + OFF_BL);
#pragma unroll
    for (int mt = 0; mt < 4; mt++)
#pragma unroll
        for (int nt = 0; nt < 2; nt++)
            wmma::fill_fragment(accs[mt][nt], 0.0f);

    for (int t = 0; t < 32; t++) {
        int k0 = t * 32;
        __syncthreads();
        // A chunk: 128 rows x 32 k (2048 float2 slots)
#pragma unroll
        for (int i = 0; i < 8; i++) {
            int slot = tid + i * 256;
            int row = slot >> 4, kp = slot & 15;
            int r = rowmap[row];
            float2 av = make_float2(0.f, 0.f);
            if (r >= 0) av = *(const float2*)(Asrc + (size_t)r * 1024 + k0 + 2 * kp);
            uint32_t hi, lo; split2(av.x, av.y, hi, lo);
            *(uint32_t*)((char*)Ah + row * (LDA*2) + kp * 4) = hi;
            *(uint32_t*)((char*)Al + row * (LDA*2) + kp * 4) = lo;
        }
        // B chunk: 32 k x 128 n (2048 float2 slots)
#pragma unroll
        for (int i = 0; i < 8; i++) {
            int slot = tid + i * 256;
            int k = slot >> 6, np = slot & 63;
            float2 bv = *(const float2*)(Bsrc + (size_t)(k0 + k) * 1024 + nb + 2 * np);
            uint32_t hi, lo; split2(bv.x, bv.y, hi, lo);
            *(uint32_t*)((char*)Bh + k * (LDB*2) + np * 4) = hi;
            *(uint32_t*)((char*)Bl + k * (LDB*2) + np * 4) = lo;
        }
        __syncthreads();
#pragma unroll
        for (int ks = 0; ks < 2; ks++) {
            FragB bh0, bh1, bl0, bl1;
            const __nv_bfloat16* bbase = Bh + (ks * 16) * LDB + wn * 32;
            const __nv_bfloat16* bbasl = Bl + (ks * 16) * LDB + wn * 32;
            wmma::load_matrix_sync(bh0, bbase,      LDB);
            wmma::load_matrix_sync(bh1, bbase + 16, LDB);
            wmma::load_matrix_sync(bl0, bbasl,      LDB);
            wmma::load_matrix_sync(bl1, bbasl + 16, LDB);
#pragma unroll
            for (int mt = 0; mt < 4; mt++) {
                FragA ah, al;
                const __nv_bfloat16* abase = Ah + (wm * 64 + mt * 16) * LDA + ks * 16;
                const __nv_bfloat16* abasl = Al + (wm * 64 + mt * 16) * LDA + ks * 16;
                wmma::load_matrix_sync(ah, abase, LDA);
                wmma::load_matrix_sync(al, abasl, LDA);
                wmma::mma_sync(accs[mt][0], ah, bh0, accs[mt][0]);
                wmma::mma_sync(accs[mt][0], ah, bl0, accs[mt][0]);
                wmma::mma_sync(accs[mt][0], al, bh0, accs[mt][0]);
                wmma::mma_sync(accs[mt][1], ah, bh1, accs[mt][1]);
                wmma::mma_sync(accs[mt][1], ah, bl1, accs[mt][1]);
                wmma::mma_sync(accs[mt][1], al, bh1, accs[mt][1]);
            }
        }
    }
    // stage C to smem for epilogue
    __syncthreads();
    float* Cs = (float*)sm;
#pragma unroll
    for (int mt = 0; mt < 4; mt++)
#pragma unroll
        for (int nt = 0; nt < 2; nt++)
            wmma::store_matrix_sync(Cs + (wm * 64 + mt * 16) * LDC + wn * 32 + nt * 16,
                                    accs[mt][nt], LDC, wmma::mem_row_major);
    __syncthreads();
}

#define WM_PROLOGUE(ROWEXPR)                                                   \
    extern __shared__ __align__(16) char dynsm[];                              \
    __shared__ int s_rowmap[128];                                              \
    int tid = threadIdx.x;                                                     \
    if (tid < 128) s_rowmap[tid] = (ROWEXPR);                                  \
    __syncthreads();                                                           \
    FragC accs[4][2];

// Epilogue indexing: thread owns 1 row (tid>>1) and 64 cols ((tid&1)*64)
#define EPI_VARS                                                               \
    float* Cs = (float*)dynsm;                                                 \
    int em = tid >> 1;                                                         \
    int en = (tid & 1) * 64;                                                   \
    const float* crow = Cs + em * LDC + en;

// ---------------- generic GEMM: modes 0 plain, 1 gelu, 2 +res1(+res2) ----
__global__ __launch_bounds__(256) void wm_gemm_kernel(
    const float* __restrict__ A, const float* __restrict__ Bm,
    const float* __restrict__ bias, float* __restrict__ C,
    int mode, const float* __restrict__ res1, const float* __restrict__ res2)
{
    int mb = blockIdx.y * 128, nb = blockIdx.x * 128;
    WM_PROLOGUE(mb + tid)
    wm_mainloop(A, Bm, nb, s_rowmap, dynsm, accs);
    EPI_VARS
    int m = mb + em;
    float* orow = C + (size_t)m * 1024 + nb + en;
#pragma unroll
    for (int j = 0; j < 64; j += 4) {
        int n = nb + en + j;
        float4 v;
        v.x = crow[j+0] + bias[n+0];
        v.y = crow[j+1] + bias[n+1];
        v.z = crow[j+2] + bias[n+2];
        v.w = crow[j+3] + bias[n+3];
        if (mode == 1) {
            v.x = gelu_f(v.x); v.y = gelu_f(v.y); v.z = gelu_f(v.z); v.w = gelu_f(v.w);
        } else if (mode == 2) {
            float4 r = *(const float4*)(res1 + (size_t)m * 1024 + n);
            v.x += r.x; v.y += r.y; v.z += r.z; v.w += r.w;
            if (res2) {
                float4 r2 = *(const float4*)(res2 + (size_t)m * 1024 + n);
                v.x += r2.x; v.y += r2.y; v.z += r2.z; v.w += r2.w;
            }
        }
        *(float4*)(orow + j) = v;
    }
}

// ---------------- fused QKV GEMM, scatter to [B,H,S,HD] ----------------
__global__ __launch_bounds__(256) void wm_qkv_kernel(
    const float* __restrict__ A,
    const float* __restrict__ qw, const float* __restrict__ qbias,
    const float* __restrict__ kw, const float* __restrict__ kbias,
    const float* __restrict__ vw, const float* __restrict__ vbias,
    float* __restrict__ qo, float* __restrict__ ko, float* __restrict__ vo)
{
    const float* Bm; const float* bias; float* C;
    if (blockIdx.z == 0)      { Bm = qw; bias = qbias; C = qo; }
    else if (blockIdx.z == 1) { Bm = kw; bias = kbias; C = ko; }
    else                      { Bm = vw; bias = vbias; C = vo; }
    int mb = blockIdx.y * 128, nb = blockIdx.x * 128;
    WM_PROLOGUE(mb + tid)
    wm_mainloop(A, Bm, nb, s_rowmap, dynsm, accs);
    EPI_VARS
    int m = mb + em;
    int b = m >> 10, s = m & 1023;
#pragma unroll
    for (int j = 0; j < 64; j += 4) {
        int n = nb + en + j;
        int h = n >> 6, hd = n & 63;
        float4 v;
        v.x = crow[j+0] + bias[n+0];
        v.y = crow[j+1] + bias[n+1];
        v.z = crow[j+2] + bias[n+2];
        v.w = crow[j+3] + bias[n+3];
        *(float4*)&C[(size_t)(((b * Hh + h) * Ss + s)) * 64 + hd] = v;
    }
}

// ---------------- expert GEMM 1 ----------------
__global__ __launch_bounds__(256) void wm_egemm1_kernel(
    const float* __restrict__ re_w1, const float* __restrict__ re_b1)
{
    int e = blockIdx.z;
    int cnt = g_cnt[e];
    int mb = blockIdx.y * 128;
    if (mb >= cnt) return;
    int off = g_off[e];
    int nb = blockIdx.x * 128;
    const float* Bm = re_w1 + (size_t)e * (Dd * INTERi);
    WM_PROLOGUE((mb + tid < cnt) ? g_slot_tok[off + mb + tid] : -1)
    wm_mainloop(g_an, Bm, nb, s_rowmap, dynsm, accs);
    const float* bias = re_b1 + e * INTERi;
    EPI_VARS
    int row = mb + em;
    if (row < cnt) {
        float* hrow = g_h + (size_t)(off + row) * INTERi + nb + en;
#pragma unroll
        for (int j = 0; j < 64; j += 4) {
            int n = nb + en + j;
            float4 v;
            v.x = gelu_f(crow[j+0] + bias[n+0]);
            v.y = gelu_f(crow[j+1] + bias[n+1]);
            v.z = gelu_f(crow[j+2] + bias[n+2]);
            v.w = gelu_f(crow[j+3] + bias[n+3]);
            *(float4*)(hrow + j) = v;
        }
    }
}

// ---------------- expert GEMM 2 ----------------
__global__ __launch_bounds__(256) void wm_egemm2_kernel(
    const float* __restrict__ re_w2, const float* __restrict__ re_b2)
{
    int e = blockIdx.z;
    int cnt = g_cnt[e];
    int mb = blockIdx.y * 128;
    if (mb >= cnt) return;
    int off = g_off[e];
    int nb = blockIdx.x * 128;
    const float* Bm = re_w2 + (size_t)e * (INTERi * Dd);
    WM_PROLOGUE((mb + tid < cnt) ? (off + mb + tid) : -1)
    wm_mainloop(g_h, Bm, nb, s_rowmap, dynsm, accs);
    const float* bias = re_b2 + e * Dd;
    EPI_VARS
    int row = mb + em;
    if (row < cnt) {
        int slot = off + row;
        int tok = g_slot_tok[slot];
        int rnk = g_slot_rank[slot];
        float gate = g_slot_gate[slot];
        float* outp = g_part + (size_t)(tok * 3 + rnk) * Dd + nb + en;
#pragma unroll
        for (int j = 0; j < 64; j += 4) {
            int n = nb + en + j;
            float4 v;
            v.x = gate * (crow[j+0] + bias[n+0]);
            v.y = gate * (crow[j+1] + bias[n+1]);
            v.z = gate * (crow[j+2] + bias[n+2]);
            v.w = gate * (crow[j+3] + bias[n+3]);
            *(float4*)(outp + j) = v;
        }
    }
}

// ---------------- small kernels ----------------
__global__ void reset_kernel() {
    int t = threadIdx.x;
    if (t < Ee) { g_cnt[t] = 0; g_cur[t] = 0; }
}

__global__ void rmsnorm_kernel(const float* __restrict__ in,
                               const float* __restrict__ gamma,
                               float* __restrict__ out) {
    int row = blockIdx.x;
    const float* p = in + row * Dd;
    float ss = 0.f;
    for (int d = threadIdx.x; d < Dd; d += blockDim.x) { float v = p[d]; ss += v * v; }
    for (int o = 16; o; o >>= 1) ss += __shfl_xor_sync(0xffffffffu, ss, o);
    __shared__ float red[8];
    int w = threadIdx.x >> 5;
    if ((threadIdx.x & 31) == 0) red[w] = ss;
    __syncthreads();
    if (threadIdx.x < 8) {
        float v = red[threadIdx.x];
        for (int o = 4; o; o >>= 1) v += __shfl_xor_sync(0xffu, v, o);
        if (threadIdx.x == 0) red[0] = v;
    }
    __syncthreads();
    float rinv = rsqrtf(red[0] * (1.0f / Dd) + EPSf);
    for (int d = threadIdx.x; d < Dd; d += blockDim.x)
        out[row * Dd + d] = p[d] * rinv * gamma[d];
}

__global__ void rope_kernel(float* __restrict__ p, const float* __restrict__ theta) {
    int v = blockIdx.x * 8 + (threadIdx.x >> 5);
    int s = v & (Ss - 1);
    float* basep = p + v * HDh;
    int i = threadIdx.x & 31;
    float x1 = basep[2 * i], x2 = basep[2 * i + 1];
    float ang = (float)s * theta[i];
    float c = cosf(ang), sn = sinf(ang);
    __syncwarp();
    basep[i]      = x1 * c - x2 * sn;
    basep[32 + i] = x1 * sn + x2 * c;
}

__global__ void attn_kernel(const float* __restrict__ Q, const float* __restrict__ Kt,
                            const float* __restrict__ V, float* __restrict__ ctx) {
    int bh = blockIdx.y;
    int b = bh / Hh, h = bh % Hh;
    int qbase = (gridDim.x - 1 - blockIdx.x) * 128;
    int t = threadIdx.x;
    int q = qbase + t;
    const float4* qrow = (const float4*)(Q + (bh * Ss + q) * HDh);
    float4 qr[16];
#pragma unroll
    for (int i = 0; i < 16; i++) qr[i] = qrow[i];
    float4 o[16];
#pragma unroll
    for (int i = 0; i < 16; i++) o[i] = make_float4(0.f, 0.f, 0.f, 0.f);
    float m = -1e30f, l = 0.f;
    __shared__ __align__(16) float4 ks[1024];
    __shared__ __align__(16) float4 vs[1024];
    int ntiles = qbase / 64 + 2;
    const float scale = 0.125f;
    for (int tile = 0; tile < ntiles; tile++) {
        int kb = tile * 64;
        const float4* kp = (const float4*)(Kt + (bh * Ss + kb) * HDh);
        const float4* vp = (const float4*)(V  + (bh * Ss + kb) * HDh);
        __syncthreads();
        for (int i = t; i < 1024; i += 128) { ks[i] = kp[i]; vs[i] = vp[i]; }
        __syncthreads();
        int jmax = q - kb + 1;
        if (jmax > 64) jmax = 64;
        for (int j = 0; j < jmax; j++) {
            float s_ = 0.f;
#pragma unroll
            for (int i = 0; i < 16; i++) {
                float4 kv = ks[j * 16 + i];
                s_ += qr[i].x * kv.x + qr[i].y * kv.y + qr[i].z * kv.z + qr[i].w * kv.w;
            }
            s_ *= scale;
            if (s_ <= m) {
                float p = __expf(s_ - m);
                l += p;
#pragma unroll
                for (int i = 0; i < 16; i++) {
                    float4 vv = vs[j * 16 + i];
                    o[i].x += p * vv.x; o[i].y += p * vv.y;
                    o[i].z += p * vv.z; o[i].w += p * vv.w;
                }
            } else {
                float corr = __expf(m - s_);
                m = s_;
                l = l * corr + 1.f;
#pragma unroll
                for (int i = 0; i < 16; i++) {
                    float4 vv = vs[j * 16 + i];
                    o[i].x = o[i].x * corr + vv.x; o[i].y = o[i].y * corr + vv.y;
                    o[i].z = o[i].z * corr + vv.z; o[i].w = o[i].w * corr + vv.w;
                }
            }
        }
    }
    float rl = 1.f / l;
    float4* outp = (float4*)(ctx + (b * Ss + q) * Dd + h * HDh);
#pragma unroll
    for (int i = 0; i < 16; i++)
        outp[i] = make_float4(o[i].x * rl, o[i].y * rl, o[i].z * rl, o[i].w * rl);
}

__global__ void router_kernel(const float* __restrict__ an, const float* __restrict__ W,
                              const float* __restrict__ bias) {
    int tkn = blockIdx.x;
    __shared__ float xs[Dd];
    for (int d = threadIdx.x; d < Dd; d += 32) xs[d] = an[tkn * Dd + d];
    __syncwarp();
    int e = threadIdx.x;
    float logit = -1e30f;
    if (e < Ee) {
        float acc = bias[e];
        for (int d = 0; d < Dd; d++) acc += xs[d] * W[d * Ee + e];
        logit = acc;
    }
    float mx = logit;
    for (int o = 16; o; o >>= 1) mx = fmaxf(mx, __shfl_xor_sync(0xffffffffu, mx, o));
    float ex = (e < Ee) ? __expf(logit - mx) : 0.f;
    float sm = ex;
    for (int o = 16; o; o >>= 1) sm += __shfl_xor_sync(0xffffffffu, sm, o);
    float pw = ex / sm;
    for (int it = 0; it < 3; it++) {
        float bv = pw; int bi = e;
        for (int o = 16; o; o >>= 1) {
            float ov = __shfl_xor_sync(0xffffffffu, bv, o);
            int   oi = __shfl_xor_sync(0xffffffffu, bi, o);
            if (ov > bv || (ov == bv && oi < bi)) { bv = ov; bi = oi; }
        }
        if (threadIdx.x == 0) {
            g_topi[tkn * 3 + it] = bi;
            g_topv[tkn * 3 + it] = bv;
            atomicAdd(&g_cnt[bi], 1);
        }
        if (e == bi) pw = -1.f;
    }
}

__global__ void scan_kernel() {
    if (threadIdx.x == 0) {
        int s = 0;
        for (int e = 0; e < Ee; e++) { g_off[e] = s; s += g_cnt[e]; }
    }
}

__global__ void fill_kernel() {
    int i = blockIdx.x * 256 + threadIdx.x;
    if (i >= SLOTS) return;
    int tkn = i / 3, r = i - tkn * 3;
    int e = g_topi[i];
    int pos = atomicAdd(&g_cur[e], 1);
    int slot = g_off[e] + pos;
    g_slot_tok[slot] = tkn;
    g_slot_rank[slot] = r;
    g_slot_gate[slot] = g_topv[i];
}

__global__ void final_kernel(float* __restrict__ out) {
    int i = blockIdx.x * 256 + threadIdx.x;
    int t = i >> 10, n = i & 1023;
    float v = out[i];
    v += g_part[(size_t)(t * 3 + 0) * Dd + n];
    v += g_part[(size_t)(t * 3 + 1) * Dd + n];
    v += g_part[(size_t)(t * 3 + 2) * Dd + n];
    out[i] = v;
}

// ---------------- launch ----------------
extern "C" void kernel_launch(void* const* d_in, const int* in_sizes, int n_in,
                              void* d_out, int out_size) {
    const float* x      = (const float*)d_in[0];
    const float* theta  = (const float*)d_in[2];
    const float* gamma1 = (const float*)d_in[3];
    const float* gamma2 = (const float*)d_in[4];
    const float* q_w  = (const float*)d_in[5];  const float* q_b  = (const float*)d_in[6];
    const float* k_w  = (const float*)d_in[7];  const float* k_b  = (const float*)d_in[8];
    const float* v_w  = (const float*)d_in[9];  const float* v_b  = (const float*)d_in[10];
    const float* o_w  = (const float*)d_in[11]; const float* o_b  = (const float*)d_in[12];
    const float* r_w  = (const float*)d_in[13]; const float* r_b  = (const float*)d_in[14];
    const float* sw1  = (const float*)d_in[15]; const float* sb1  = (const float*)d_in[16];
    const float* sw2  = (const float*)d_in[17]; const float* sb2  = (const float*)d_in[18];
    const float* rw1  = (const float*)d_in[19]; const float* rb1  = (const float*)d_in[20];
    const float* rw2  = (const float*)d_in[21]; const float* rb2  = (const float*)d_in[22];
    float* out = (float*)d_out;

    float *xn, *qb, *kb, *vb, *ctx, *attn, *an, *t1;
    cudaGetSymbolAddress((void**)&xn,   g_xn);
    cudaGetSymbolAddress((void**)&qb,   g_qb);
    cudaGetSymbolAddress((void**)&kb,   g_kb);
    cudaGetSymbolAddress((void**)&vb,   g_vb);
    cudaGetSymbolAddress((void**)&ctx,  g_ctx);
    cudaGetSymbolAddress((void**)&attn, g_attn);
    cudaGetSymbolAddress((void**)&an,   g_an);
    cudaGetSymbolAddress((void**)&t1,   g_t1);

    cudaFuncSetAttribute(wm_gemm_kernel,   cudaFuncAttributeMaxDynamicSharedMemorySize, DYN_SMEM);
    cudaFuncSetAttribute(wm_qkv_kernel,    cudaFuncAttributeMaxDynamicSharedMemorySize, DYN_SMEM);
    cudaFuncSetAttribute(wm_egemm1_kernel, cudaFuncAttributeMaxDynamicSharedMemorySize, DYN_SMEM);
    cudaFuncSetAttribute(wm_egemm2_kernel, cudaFuncAttributeMaxDynamicSharedMemorySize, DYN_SMEM);

    dim3 thr(256);
    dim3 grid8x16(8, 16);

    reset_kernel<<<1, 32>>>();
    rmsnorm_kernel<<<NT, 256>>>(x, gamma1, xn);

    wm_qkv_kernel<<<dim3(8, 16, 3), thr, DYN_SMEM>>>(xn, q_w, q_b, k_w, k_b, v_w, v_b, qb, kb, vb);

    rope_kernel<<<Bb * Hh * Ss / 8, 256>>>(qb, theta);
    rope_kernel<<<Bb * Hh * Ss / 8, 256>>>(kb, theta);

    attn_kernel<<<dim3(Ss / 128, Bb * Hh), 128>>>(qb, kb, vb, ctx);

    wm_gemm_kernel<<<grid8x16, thr, DYN_SMEM>>>(ctx, o_w, o_b, attn, 2, xn, nullptr);
    rmsnorm_kernel<<<NT, 256>>>(attn, gamma2, an);

    wm_gemm_kernel<<<grid8x16, thr, DYN_SMEM>>>(an, sw1, sb1, t1, 1, nullptr, nullptr);
    wm_gemm_kernel<<<grid8x16, thr, DYN_SMEM>>>(t1, sw2, sb2, out, 2, an, attn);

    router_kernel<<<NT, 32>>>(an, r_w, r_b);
    scan_kernel<<<1, 32>>>();
    fill_kernel<<<(SLOTS + 255) / 256, 256>>>();

    wm_egemm1_kernel<<<dim3(8, 16, Ee), thr, DYN_SMEM>>>(rw1, rb1);
    wm_egemm2_kernel<<<dim3(8, 16, Ee), thr, DYN_SMEM>>>(rw2, rb2);

    final_kernel<<<(NT * Dd) / 256, 256>>>(out);
}

// round 7
// speedup vs baseline: 1.6950x; 1.6950x over previous
#include <cuda_runtime.h>
#include <cuda_bf16.h>
#include <cuda_pipeline.h>
#include <mma.h>
#include <cstdint>

using namespace nvcuda;

#define Bb     2
#define Ss     1024
#define Dd     1024
#define Hh     16
#define HDh    64
#define NT     (Bb*Ss)
#define Ee     31
#define INTERi 1024
#define EPSf   1e-5f
#define SLOTS  (NT*3)

typedef __nv_bfloat16 bf16;

// ---------------- fp32 scratch ----------------
__device__ float g_xn  [NT*Dd];
__device__ float g_qb  [NT*Dd];
__device__ float g_kb  [NT*Dd];
__device__ float g_vb  [NT*Dd];
__device__ float g_attn[NT*Dd];
__device__ float g_an  [NT*Dd];
__device__ float g_part[SLOTS*Dd];
__device__ int   g_topi[SLOTS];
__device__ float g_topv[SLOTS];
__device__ int   g_cnt[Ee];
__device__ int   g_off[Ee];
__device__ int   g_cur[Ee];
__device__ int   g_slot_tok [SLOTS];
__device__ int   g_slot_rank[SLOTS];
__device__ float g_slot_gate[SLOTS];

// ---------------- bf16 hi/lo activations ----------------
__device__ bf16 g_xnh[NT*Dd],  g_xnl[NT*Dd];
__device__ bf16 g_ctxh[NT*Dd], g_ctxl[NT*Dd];
__device__ bf16 g_anh[NT*Dd],  g_anl[NT*Dd];
__device__ bf16 g_t1h[NT*INTERi], g_t1l[NT*INTERi];
__device__ bf16 g_hh[SLOTS*INTERi], g_hl[SLOTS*INTERi];

// ---------------- bf16 hi/lo weights ----------------
__device__ bf16 g_qwh[Dd*Dd], g_qwl[Dd*Dd];
__device__ bf16 g_kwh[Dd*Dd], g_kwl[Dd*Dd];
__device__ bf16 g_vwh[Dd*Dd], g_vwl[Dd*Dd];
__device__ bf16 g_owh[Dd*Dd], g_owl[Dd*Dd];
__device__ bf16 g_s1h[Dd*INTERi], g_s1l[Dd*INTERi];
__device__ bf16 g_s2h[INTERi*Dd], g_s2l[INTERi*Dd];
__device__ bf16 g_r1h[Ee*Dd*INTERi], g_r1l[Ee*Dd*INTERi];
__device__ bf16 g_r2h[Ee*INTERi*Dd], g_r2l[Ee*INTERi*Dd];

__device__ __forceinline__ float gelu_f(float v) {
    return 0.5f * v * (1.0f + erff(v * 0.70710678118654752f));
}

__device__ __forceinline__ void split2(float x, float y, uint32_t& hi, uint32_t& lo) {
    bf16 hx = __float2bfloat16(x), hy = __float2bfloat16(y);
    bf16 lx = __float2bfloat16(x - __bfloat162float(hx));
    bf16 ly = __float2bfloat16(y - __bfloat162float(hy));
    __nv_bfloat162 H = __halves2bfloat162(hx, hy);
    __nv_bfloat162 L = __halves2bfloat162(lx, ly);
    hi = *(uint32_t*)&H; lo = *(uint32_t*)&L;
}

// ---------------- weight conversion ----------------
__global__ void convw_kernel(const float4* __restrict__ src,
                             uint64_t* __restrict__ h, uint64_t* __restrict__ l, int n4) {
    int i = blockIdx.x * 256 + threadIdx.x;
    if (i >= n4) return;
    float4 v = src[i];
    uint32_t h0, l0, h1, l1;
    split2(v.x, v.y, h0, l0);
    split2(v.z, v.w, h1, l1);
    h[i] = (uint64_t)h0 | ((uint64_t)h1 << 32);
    l[i] = (uint64_t)l0 | ((uint64_t)l1 << 32);
}

// ================= wmma bf16 split GEMM core =================
typedef wmma::fragment<wmma::accumulator, 16, 16, 16, float> FragC;
typedef wmma::fragment<wmma::matrix_a, 16, 16, 16, bf16, wmma::row_major> FragA;
typedef wmma::fragment<wmma::matrix_b, 16, 16, 16, bf16, wmma::row_major> FragB;

#define LDA 40
#define LDB 136
#define LDC 132
#define OFF_AH 0
#define OFF_AL 10240
#define OFF_BH 20480
#define OFF_BL 29184
#define STAGE  37888
#define DYN_SMEM (2*STAGE)

__device__ __forceinline__ void stage_fill(
    const bf16* __restrict__ Ahg, const bf16* __restrict__ Alg,
    const bf16* __restrict__ Bhg, const bf16* __restrict__ Blg,
    int nb, int k0, const int* rowmap, char* st, int tid)
{
#pragma unroll
    for (int i = 0; i < 2; i++) {
        int s = tid + i * 256;
        int row = s >> 2, q = s & 3;
        int r = rowmap[row];
        char* dh = st + OFF_AH + row * (LDA * 2) + q * 16;
        char* dl = st + OFF_AL + row * (LDA * 2) + q * 16;
        if (r >= 0) {
            __pipeline_memcpy_async(dh, Ahg + (size_t)r * 1024 + k0 + q * 8, 16);
            __pipeline_memcpy_async(dl, Alg + (size_t)r * 1024 + k0 + q * 8, 16);
        } else {
            *(uint4*)dh = make_uint4(0u, 0u, 0u, 0u);
            *(uint4*)dl = make_uint4(0u, 0u, 0u, 0u);
        }
    }
#pragma unroll
    for (int i = 0; i < 2; i++) {
        int s = tid + i * 256;
        int k = s >> 4, q = s & 15;
        char* dh = st + OFF_BH + k * (LDB * 2) + q * 16;
        char* dl = st + OFF_BL + k * (LDB * 2) + q * 16;
        __pipeline_memcpy_async(dh, Bhg + (size_t)(k0 + k) * 1024 + nb + q * 8, 16);
        __pipeline_memcpy_async(dl, Blg + (size_t)(k0 + k) * 1024 + nb + q * 8, 16);
    }
}

__device__ __forceinline__ void wm_mainloop(
    const bf16* __restrict__ Ahg, const bf16* __restrict__ Alg,
    const bf16* __restrict__ Bhg, const bf16* __restrict__ Blg,
    int nb, const int* rowmap, char* sm, FragC accs[4][2])
{
    int tid = threadIdx.x, wid = tid >> 5;
    int wm = wid & 1, wn = wid >> 1;
#pragma unroll
    for (int mt = 0; mt < 4; mt++)
#pragma unroll
        for (int nt = 0; nt < 2; nt++)
            wmma::fill_fragment(accs[mt][nt], 0.0f);

    stage_fill(Ahg, Alg, Bhg, Blg, nb, 0, rowmap, sm, tid);
    __pipeline_commit();

    for (int t = 0; t < 32; t++) {
        char* cur = sm + (t & 1) * STAGE;
        if (t < 31) {
            stage_fill(Ahg, Alg, Bhg, Blg, nb, (t + 1) * 32, rowmap,
                       sm + ((t + 1) & 1) * STAGE, tid);
            __pipeline_commit();
            __pipeline_wait_prior(1);
        } else {
            __pipeline_wait_prior(0);
        }
        __syncthreads();
        const bf16* Ah = (const bf16*)(cur + OFF_AH);
        const bf16* Al = (const bf16*)(cur + OFF_AL);
        const bf16* Bh = (const bf16*)(cur + OFF_BH);
        const bf16* Bl = (const bf16*)(cur + OFF_BL);
#pragma unroll
        for (int ks = 0; ks < 2; ks++) {
            FragB bh0, bh1, bl0, bl1;
            const bf16* bbase = Bh + (ks * 16) * LDB + wn * 32;
            const bf16* bbasl = Bl + (ks * 16) * LDB + wn * 32;
            wmma::load_matrix_sync(bh0, bbase,      LDB);
            wmma::load_matrix_sync(bh1, bbase + 16, LDB);
            wmma::load_matrix_sync(bl0, bbasl,      LDB);
            wmma::load_matrix_sync(bl1, bbasl + 16, LDB);
#pragma unroll
            for (int mt = 0; mt < 4; mt++) {
                FragA ah, al;
                wmma::load_matrix_sync(ah, Ah + (wm * 64 + mt * 16) * LDA + ks * 16, LDA);
                wmma::load_matrix_sync(al, Al + (wm * 64 + mt * 16) * LDA + ks * 16, LDA);
                wmma::mma_sync(accs[mt][0], ah, bh0, accs[mt][0]);
                wmma::mma_sync(accs[mt][0], ah, bl0, accs[mt][0]);
                wmma::mma_sync(accs[mt][0], al, bh0, accs[mt][0]);
                wmma::mma_sync(accs[mt][1], ah, bh1, accs[mt][1]);
                wmma::mma_sync(accs[mt][1], ah, bl1, accs[mt][1]);
                wmma::mma_sync(accs[mt][1], al, bh1, accs[mt][1]);
            }
        }
        __syncthreads();
    }
    float* Cs = (float*)sm;
#pragma unroll
    for (int mt = 0; mt < 4; mt++)
#pragma unroll
        for (int nt = 0; nt < 2; nt++)
            wmma::store_matrix_sync(Cs + (wm * 64 + mt * 16) * LDC + wn * 32 + nt * 16,
                                    accs[mt][nt], LDC, wmma::mem_row_major);
    __syncthreads();
}

#define WM_PROLOGUE(ROWEXPR)                                                   \
    extern __shared__ __align__(16) char dynsm[];                              \
    __shared__ int s_rowmap[128];                                              \
    int tid = threadIdx.x;                                                     \
    if (tid < 128) s_rowmap[tid] = (ROWEXPR);                                  \
    __syncthreads();                                                           \
    FragC accs[4][2];

#define EPI_VARS                                                               \
    float* Cs = (float*)dynsm;                                                 \
    int em = tid >> 1;                                                         \
    int en = (tid & 1) * 64;                                                   \
    const float* crow = Cs + em * LDC + en;

// ---------------- generic GEMM: mode 0 plain->Cf, 1 gelu->Ch/Cl, 2 +res->Cf --
__global__ __launch_bounds__(256) void wm_gemm_kernel(
    const bf16* __restrict__ Ahg, const bf16* __restrict__ Alg,
    const bf16* __restrict__ Bhg, const bf16* __restrict__ Blg,
    const float* __restrict__ bias, int mode,
    const float* __restrict__ res1, const float* __restrict__ res2,
    float* __restrict__ Cf, bf16* __restrict__ Ch, bf16* __restrict__ Cl)
{
    int mb = blockIdx.y * 128, nb = blockIdx.x * 128;
    WM_PROLOGUE(mb + tid)
    wm_mainloop(Ahg, Alg, Bhg, Blg, nb, s_rowmap, dynsm, accs);
    EPI_VARS
    int m = mb + em;
    if (mode == 1) {
        uint32_t* oh = (uint32_t*)(Ch + (size_t)m * 1024 + nb + en);
        uint32_t* ol = (uint32_t*)(Cl + (size_t)m * 1024 + nb + en);
#pragma unroll
        for (int j = 0; j < 64; j += 2) {
            int n = nb + en + j;
            float v0 = gelu_f(crow[j]     + bias[n]);
            float v1 = gelu_f(crow[j + 1] + bias[n + 1]);
            uint32_t h, l; split2(v0, v1, h, l);
            oh[j >> 1] = h; ol[j >> 1] = l;
        }
    } else {
        float* orow = Cf + (size_t)m * 1024 + nb + en;
#pragma unroll
        for (int j = 0; j < 64; j += 4) {
            int n = nb + en + j;
            float4 v;
            v.x = crow[j+0] + bias[n+0];
            v.y = crow[j+1] + bias[n+1];
            v.z = crow[j+2] + bias[n+2];
            v.w = crow[j+3] + bias[n+3];
            if (mode == 2) {
                float4 r = *(const float4*)(res1 + (size_t)m * 1024 + n);
                v.x += r.x; v.y += r.y; v.z += r.z; v.w += r.w;
                if (res2) {
                    float4 r2 = *(const float4*)(res2 + (size_t)m * 1024 + n);
                    v.x += r2.x; v.y += r2.y; v.z += r2.z; v.w += r2.w;
                }
            }
            *(float4*)(orow + j) = v;
        }
    }
}

// ---------------- fused QKV GEMM, scatter to [B,H,S,HD] ----------------
__global__ __launch_bounds__(256) void wm_qkv_kernel(
    const float* __restrict__ qbias, const float* __restrict__ kbias,
    const float* __restrict__ vbias)
{
    const bf16 *Bh_, *Bl_; const float* bias; float* C;
    if (blockIdx.z == 0)      { Bh_ = g_qwh; Bl_ = g_qwl; bias = qbias; C = g_qb; }
    else if (blockIdx.z == 1) { Bh_ = g_kwh; Bl_ = g_kwl; bias = kbias; C = g_kb; }
    else                      { Bh_ = g_vwh; Bl_ = g_vwl; bias = vbias; C = g_vb; }
    int mb = blockIdx.y * 128, nb = blockIdx.x * 128;
    WM_PROLOGUE(mb + tid)
    wm_mainloop(g_xnh, g_xnl, Bh_, Bl_, nb, s_rowmap, dynsm, accs);
    EPI_VARS
    int m = mb + em;
    int b = m >> 10, s = m & 1023;
#pragma unroll
    for (int j = 0; j < 64; j += 4) {
        int n = nb + en + j;
        int h = n >> 6, hd = n & 63;
        float4 v;
        v.x = crow[j+0] + bias[n+0];
        v.y = crow[j+1] + bias[n+1];
        v.z = crow[j+2] + bias[n+2];
        v.w = crow[j+3] + bias[n+3];
        *(float4*)&C[(size_t)(((b * Hh + h) * Ss + s)) * 64 + hd] = v;
    }
}

// ---------------- expert GEMM 1: h = gelu(gather(an) @ W1[e]) -> bf16 hi/lo --
__global__ __launch_bounds__(256) void wm_egemm1_kernel(const float* __restrict__ re_b1)
{
    int e = blockIdx.z;
    int cnt = g_cnt[e];
    int mb = blockIdx.y * 128;
    if (mb >= cnt) return;
    int off = g_off[e];
    int nb = blockIdx.x * 128;
    WM_PROLOGUE((mb + tid < cnt) ? g_slot_tok[off + mb + tid] : -1)
    wm_mainloop(g_anh, g_anl,
                g_r1h + (size_t)e * (Dd * INTERi), g_r1l + (size_t)e * (Dd * INTERi),
                nb, s_rowmap, dynsm, accs);
    const float* bias = re_b1 + e * INTERi;
    EPI_VARS
    int row = mb + em;
    if (row < cnt) {
        uint32_t* oh = (uint32_t*)(g_hh + (size_t)(off + row) * INTERi + nb + en);
        uint32_t* ol = (uint32_t*)(g_hl + (size_t)(off + row) * INTERi + nb + en);
#pragma unroll
        for (int j = 0; j < 64; j += 2) {
            int n = nb + en + j;
            float v0 = gelu_f(crow[j]     + bias[n]);
            float v1 = gelu_f(crow[j + 1] + bias[n + 1]);
            uint32_t h, l; split2(v0, v1, h, l);
            oh[j >> 1] = h; ol[j >> 1] = l;
        }
    }
}

// ---------------- expert GEMM 2 ----------------
__global__ __launch_bounds__(256) void wm_egemm2_kernel(const float* __restrict__ re_b2)
{
    int e = blockIdx.z;
    int cnt = g_cnt[e];
    int mb = blockIdx.y * 128;
    if (mb >= cnt) return;
    int off = g_off[e];
    int nb = blockIdx.x * 128;
    WM_PROLOGUE((mb + tid < cnt) ? (off + mb + tid) : -1)
    wm_mainloop(g_hh, g_hl,
                g_r2h + (size_t)e * (INTERi * Dd), g_r2l + (size_t)e * (INTERi * Dd),
                nb, s_rowmap, dynsm, accs);
    const float* bias = re_b2 + e * Dd;
    EPI_VARS
    int row = mb + em;
    if (row < cnt) {
        int slot = off + row;
        int tok = g_slot_tok[slot];
        int rnk = g_slot_rank[slot];
        float gate = g_slot_gate[slot];
        float* outp = g_part + (size_t)(tok * 3 + rnk) * Dd + nb + en;
#pragma unroll
        for (int j = 0; j < 64; j += 4) {
            int n = nb + en + j;
            float4 v;
            v.x = gate * (crow[j+0] + bias[n+0]);
            v.y = gate * (crow[j+1] + bias[n+1]);
            v.z = gate * (crow[j+2] + bias[n+2]);
            v.w = gate * (crow[j+3] + bias[n+3]);
            *(float4*)(outp + j) = v;
        }
    }
}

// ---------------- small kernels ----------------
__global__ void reset_kernel() {
    int t = threadIdx.x;
    if (t < Ee) { g_cnt[t] = 0; g_cur[t] = 0; }
}

__global__ void rmsnorm_kernel(const float* __restrict__ in,
                               const float* __restrict__ gamma,
                               float* __restrict__ out,
                               bf16* __restrict__ oh, bf16* __restrict__ ol) {
    int row = blockIdx.x;
    const float* p = in + row * Dd;
    float ss = 0.f;
    for (int d = threadIdx.x; d < Dd; d += blockDim.x) { float v = p[d]; ss += v * v; }
    for (int o = 16; o; o >>= 1) ss += __shfl_xor_sync(0xffffffffu, ss, o);
    __shared__ float red[8];
    int w = threadIdx.x >> 5;
    if ((threadIdx.x & 31) == 0) red[w] = ss;
    __syncthreads();
    if (threadIdx.x < 8) {
        float v = red[threadIdx.x];
        for (int o = 4; o; o >>= 1) v += __shfl_xor_sync(0xffu, v, o);
        if (threadIdx.x == 0) red[0] = v;
    }
    __syncthreads();
    float rinv = rsqrtf(red[0] * (1.0f / Dd) + EPSf);
    for (int d = threadIdx.x * 2; d < Dd; d += blockDim.x * 2) {
        float v0 = p[d] * rinv * gamma[d];
        float v1 = p[d + 1] * rinv * gamma[d + 1];
        out[row * Dd + d]     = v0;
        out[row * Dd + d + 1] = v1;
        uint32_t h, l; split2(v0, v1, h, l);
        *(uint32_t*)&oh[row * Dd + d] = h;
        *(uint32_t*)&ol[row * Dd + d] = l;
    }
}

__global__ void rope_kernel(float* __restrict__ p, const float* __restrict__ theta) {
    int v = blockIdx.x * 8 + (threadIdx.x >> 5);
    int s = v & (Ss - 1);
    float* basep = p + v * HDh;
    int i = threadIdx.x & 31;
    float x1 = basep[2 * i], x2 = basep[2 * i + 1];
    float ang = (float)s * theta[i];
    float c = cosf(ang), sn = sinf(ang);
    __syncwarp();
    basep[i]      = x1 * c - x2 * sn;
    basep[32 + i] = x1 * sn + x2 * c;
}

__global__ void attn_kernel(const float* __restrict__ Q, const float* __restrict__ Kt,
                            const float* __restrict__ V) {
    int bh = blockIdx.y;
    int b = bh / Hh, h = bh % Hh;
    int qbase = (gridDim.x - 1 - blockIdx.x) * 128;
    int t = threadIdx.x;
    int q = qbase + t;
    const float4* qrow = (const float4*)(Q + (bh * Ss + q) * HDh);
    float4 qr[16];
#pragma unroll
    for (int i = 0; i < 16; i++) qr[i] = qrow[i];
    float4 o[16];
#pragma unroll
    for (int i = 0; i < 16; i++) o[i] = make_float4(0.f, 0.f, 0.f, 0.f);
    float m = -1e30f, l = 0.f;
    __shared__ __align__(16) float4 ks[1024];
    __shared__ __align__(16) float4 vs[1024];
    int ntiles = qbase / 64 + 2;
    const float scale = 0.125f;
    for (int tile = 0; tile < ntiles; tile++) {
        int kb = tile * 64;
        const float4* kp = (const float4*)(Kt + (bh * Ss + kb) * HDh);
        const float4* vp = (const float4*)(V  + (bh * Ss + kb) * HDh);
        __syncthreads();
        for (int i = t; i < 1024; i += 128) { ks[i] = kp[i]; vs[i] = vp[i]; }
        __syncthreads();
        int jmax = q - kb + 1;
        if (jmax > 64) jmax = 64;
        for (int j = 0; j < jmax; j++) {
            float s_ = 0.f;
#pragma unroll
            for (int i = 0; i < 16; i++) {
                float4 kv = ks[j * 16 + i];
                s_ += qr[i].x * kv.x + qr[i].y * kv.y + qr[i].z * kv.z + qr[i].w * kv.w;
            }
            s_ *= scale;
            if (s_ <= m) {
                float p = __expf(s_ - m);
                l += p;
#pragma unroll
                for (int i = 0; i < 16; i++) {
                    float4 vv = vs[j * 16 + i];
                    o[i].x += p * vv.x; o[i].y += p * vv.y;
                    o[i].z += p * vv.z; o[i].w += p * vv.w;
                }
            } else {
                float corr = __expf(m - s_);
                m = s_;
                l = l * corr + 1.f;
#pragma unroll
                for (int i = 0; i < 16; i++) {
                    float4 vv = vs[j * 16 + i];
                    o[i].x = o[i].x * corr + vv.x; o[i].y = o[i].y * corr + vv.y;
                    o[i].z = o[i].z * corr + vv.z; o[i].w = o[i].w * corr + vv.w;
                }
            }
        }
    }
    float rl = 1.f / l;
    size_t cbase = (size_t)(b * Ss + q) * Dd + h * HDh;
    uint32_t* ch = (uint32_t*)(g_ctxh + cbase);
    uint32_t* cl = (uint32_t*)(g_ctxl + cbase);
#pragma unroll
    for (int i = 0; i < 16; i++) {
        uint32_t h0, l0, h1, l1;
        split2(o[i].x * rl, o[i].y * rl, h0, l0);
        split2(o[i].z * rl, o[i].w * rl, h1, l1);
        ch[2 * i] = h0; ch[2 * i + 1] = h1;
        cl[2 * i] = l0; cl[2 * i + 1] = l1;
    }
}

__global__ void router_kernel(const float* __restrict__ an, const float* __restrict__ W,
                              const float* __restrict__ bias) {
    int tkn = blockIdx.x;
    __shared__ float xs[Dd];
    for (int d = threadIdx.x; d < Dd; d += 32) xs[d] = an[tkn * Dd + d];
    __syncwarp();
    int e = threadIdx.x;
    float logit = -1e30f;
    if (e < Ee) {
        float acc = bias[e];
        for (int d = 0; d < Dd; d++) acc += xs[d] * W[d * Ee + e];
        logit = acc;
    }
    float mx = logit;
    for (int o = 16; o; o >>= 1) mx = fmaxf(mx, __shfl_xor_sync(0xffffffffu, mx, o));
    float ex = (e < Ee) ? __expf(logit - mx) : 0.f;
    float sm = ex;
    for (int o = 16; o; o >>= 1) sm += __shfl_xor_sync(0xffffffffu, sm, o);
    float pw = ex / sm;
    for (int it = 0; it < 3; it++) {
        float bv = pw; int bi = e;
        for (int o = 16; o; o >>= 1) {
            float ov = __shfl_xor_sync(0xffffffffu, bv, o);
            int   oi = __shfl_xor_sync(0xffffffffu, bi, o);
            if (ov > bv || (ov == bv && oi < bi)) { bv = ov; bi = oi; }
        }
        if (threadIdx.x == 0) {
            g_topi[tkn * 3 + it] = bi;
            g_topv[tkn * 3 + it] = bv;
            atomicAdd(&g_cnt[bi], 1);
        }
        if (e == bi) pw = -1.f;
    }
}

__global__ void scan_kernel() {
    if (threadIdx.x == 0) {
        int s = 0;
        for (int e = 0; e < Ee; e++) { g_off[e] = s; s += g_cnt[e]; }
    }
}

__global__ void fill_kernel() {
    int i = blockIdx.x * 256 + threadIdx.x;
    if (i >= SLOTS) return;
    int tkn = i / 3, r = i - tkn * 3;
    int e = g_topi[i];
    int pos = atomicAdd(&g_cur[e], 1);
    int slot = g_off[e] + pos;
    g_slot_tok[slot] = tkn;
    g_slot_rank[slot] = r;
    g_slot_gate[slot] = g_topv[i];
}

__global__ void final_kernel(float* __restrict__ out) {
    int i = blockIdx.x * 256 + threadIdx.x;
    int t = i >> 10, n = i & 1023;
    float v = out[i];
    v += g_part[(size_t)(t * 3 + 0) * Dd + n];
    v += g_part[(size_t)(t * 3 + 1) * Dd + n];
    v += g_part[(size_t)(t * 3 + 2) * Dd + n];
    out[i] = v;
}

// ---------------- launch ----------------
extern "C" void kernel_launch(void* const* d_in, const int* in_sizes, int n_in,
                              void* d_out, int out_size) {
    const float* x      = (const float*)d_in[0];
    const float* theta  = (const float*)d_in[2];
    const float* gamma1 = (const float*)d_in[3];
    const float* gamma2 = (const float*)d_in[4];
    const float* q_w  = (const float*)d_in[5];  const float* q_b  = (const float*)d_in[6];
    const float* k_w  = (const float*)d_in[7];  const float* k_b  = (const float*)d_in[8];
    const float* v_w  = (const float*)d_in[9];  const float* v_b  = (const float*)d_in[10];
    const float* o_w  = (const float*)d_in[11]; const float* o_b  = (const float*)d_in[12];
    const float* r_w  = (const float*)d_in[13]; const float* r_b  = (const float*)d_in[14];
    const float* sw1  = (const float*)d_in[15]; const float* sb1  = (const float*)d_in[16];
    const float* sw2  = (const float*)d_in[17]; const float* sb2  = (const float*)d_in[18];
    const float* rw1  = (const float*)d_in[19]; const float* rb1  = (const float*)d_in[20];
    const float* rw2  = (const float*)d_in[21]; const float* rb2  = (const float*)d_in[22];
    float* out = (float*)d_out;

    // resolve symbols
    float *xn, *qb, *kb, *vb, *attn, *an;
    bf16 *xnh, *xnl, *ctxh, *ctxl, *anh, *anl, *t1h, *t1l;
    bf16 *qwh, *qwl, *kwh, *kwl, *vwh, *vwl, *owh, *owl, *s1h, *s1l, *s2h, *s2l;
    bf16 *r1h, *r1l, *r2h, *r2l;
    cudaGetSymbolAddress((void**)&xn,   g_xn);
    cudaGetSymbolAddress((void**)&qb,   g_qb);
    cudaGetSymbolAddress((void**)&kb,   g_kb);
    cudaGetSymbolAddress((void**)&vb,   g_vb);
    cudaGetSymbolAddress((void**)&attn, g_attn);
    cudaGetSymbolAddress((void**)&an,   g_an);
    cudaGetSymbolAddress((void**)&xnh,  g_xnh);  cudaGetSymbolAddress((void**)&xnl, g_xnl);
    cudaGetSymbolAddress((void**)&ctxh, g_ctxh); cudaGetSymbolAddress((void**)&ctxl, g_ctxl);
    cudaGetSymbolAddress((void**)&anh,  g_anh);  cudaGetSymbolAddress((void**)&anl, g_anl);
    cudaGetSymbolAddress((void**)&t1h,  g_t1h);  cudaGetSymbolAddress((void**)&t1l, g_t1l);
    cudaGetSymbolAddress((void**)&qwh,  g_qwh);  cudaGetSymbolAddress((void**)&qwl, g_qwl);
    cudaGetSymbolAddress((void**)&kwh,  g_kwh);  cudaGetSymbolAddress((void**)&kwl, g_kwl);
    cudaGetSymbolAddress((void**)&vwh,  g_vwh);  cudaGetSymbolAddress((void**)&vwl, g_vwl);
    cudaGetSymbolAddress((void**)&owh,  g_owh);  cudaGetSymbolAddress((void**)&owl, g_owl);
    cudaGetSymbolAddress((void**)&s1h,  g_s1h);  cudaGetSymbolAddress((void**)&s1l, g_s1l);
    cudaGetSymbolAddress((void**)&s2h,  g_s2h);  cudaGetSymbolAddress((void**)&s2l, g_s2l);
    cudaGetSymbolAddress((void**)&r1h,  g_r1h);  cudaGetSymbolAddress((void**)&r1l, g_r1l);
    cudaGetSymbolAddress((void**)&r2h,  g_r2h);  cudaGetSymbolAddress((void**)&r2l, g_r2l);

    cudaFuncSetAttribute(wm_gemm_kernel,   cudaFuncAttributeMaxDynamicSharedMemorySize, DYN_SMEM);
    cudaFuncSetAttribute(wm_qkv_kernel,    cudaFuncAttributeMaxDynamicSharedMemorySize, DYN_SMEM);
    cudaFuncSetAttribute(wm_egemm1_kernel, cudaFuncAttributeMaxDynamicSharedMemorySize, DYN_SMEM);
    cudaFuncSetAttribute(wm_egemm2_kernel, cudaFuncAttributeMaxDynamicSharedMemorySize, DYN_SMEM);

    // weight conversion (per launch; deterministic)
    const int D4 = Dd * Dd / 4;           // 262144
    const int E4 = Ee * Dd * INTERi / 4;  // 8126464
    convw_kernel<<<(D4 + 255) / 256, 256>>>((const float4*)q_w, (uint64_t*)qwh, (uint64_t*)qwl, D4);
    convw_kernel<<<(D4 + 255) / 256, 256>>>((const float4*)k_w, (uint64_t*)kwh, (uint64_t*)kwl, D4);
    convw_kernel<<<(D4 + 255) / 256, 256>>>((const float4*)v_w, (uint64_t*)vwh, (uint64_t*)vwl, D4);
    convw_kernel<<<(D4 + 255) / 256, 256>>>((const float4*)o_w, (uint64_t*)owh, (uint64_t*)owl, D4);
    convw_kernel<<<(D4 + 255) / 256, 256>>>((const float4*)sw1, (uint64_t*)s1h, (uint64_t*)s1l, D4);
    convw_kernel<<<(D4 + 255) / 256, 256>>>((const float4*)sw2, (uint64_t*)s2h, (uint64_t*)s2l, D4);
    convw_kernel<<<(E4 + 255) / 256, 256>>>((const float4*)rw1, (uint64_t*)r1h, (uint64_t*)r1l, E4);
    convw_kernel<<<(E4 + 255) / 256, 256>>>((const float4*)rw2, (uint64_t*)r2h, (uint64_t*)r2l, E4);

    dim3 thr(256);
    dim3 grid8x16(8, 16);

    reset_kernel<<<1, 32>>>();
    rmsnorm_kernel<<<NT, 256>>>(x, gamma1, xn, xnh, xnl);

    wm_qkv_kernel<<<dim3(8, 16, 3), thr, DYN_SMEM>>>(q_b, k_b, v_b);

    rope_kernel<<<Bb * Hh * Ss / 8, 256>>>(qb, theta);
    rope_kernel<<<Bb * Hh * Ss / 8, 256>>>(kb, theta);

    attn_kernel<<<dim3(Ss / 128, Bb * Hh), 128>>>(qb, kb, vb);

    // O proj: attn = ctx @ o_w + o_b + xn
    wm_gemm_kernel<<<grid8x16, thr, DYN_SMEM>>>(ctxh, ctxl, owh, owl, o_b, 2, xn, nullptr,
                                                attn, nullptr, nullptr);
    rmsnorm_kernel<<<NT, 256>>>(attn, gamma2, an, anh, anl);

    // shared MLP
    wm_gemm_kernel<<<grid8x16, thr, DYN_SMEM>>>(anh, anl, s1h, s1l, sb1, 1, nullptr, nullptr,
                                                nullptr, t1h, t1l);
    wm_gemm_kernel<<<grid8x16, thr, DYN_SMEM>>>(t1h, t1l, s2h, s2l, sb2, 2, an, attn,
                                                out, nullptr, nullptr);

    router_kernel<<<NT, 32>>>(an, r_w, r_b);
    scan_kernel<<<1, 32>>>();
    fill_kernel<<<(SLOTS + 255) / 256, 256>>>();

    wm_egemm1_kernel<<<dim3(8, 16, Ee), thr, DYN_SMEM>>>(rb1);
    wm_egemm2_kernel<<<dim3(8, 16, Ee), thr, DYN_SMEM>>>(rb2);

    final_kernel<<<(NT * Dd) / 256, 256>>>(out);
}

// round 10
// speedup vs baseline: 2.1053x; 1.2421x over previous
#include <cuda_runtime.h>
#include <cuda_bf16.h>
#include <cuda_pipeline.h>
#include <mma.h>
#include <cstdint>

using namespace nvcuda;

#define Bb     2
#define Ss     1024
#define Dd     1024
#define Hh     16
#define HDh    64
#define NT     (Bb*Ss)
#define Ee     31
#define INTERi 1024
#define EPSf   1e-5f
#define SLOTS  (NT*3)

typedef __nv_bfloat16 bf16;

// ---------------- fp32 scratch ----------------
__device__ float g_xn  [NT*Dd];
__device__ float g_qb  [NT*Dd];
__device__ float g_kb  [NT*Dd];
__device__ float g_attn[NT*Dd];
__device__ float g_an  [NT*Dd];
__device__ float g_part[SLOTS*Dd];
__device__ int   g_topi[SLOTS];
__device__ float g_topv[SLOTS];
__device__ int   g_cnt[Ee];
__device__ int   g_off[Ee];
__device__ int   g_cur[Ee];
__device__ int   g_slot_tok [SLOTS];
__device__ int   g_slot_rank[SLOTS];
__device__ float g_slot_gate[SLOTS];

// ---------------- bf16 hi/lo activations ----------------
__device__ bf16 g_xnh[NT*Dd],  g_xnl[NT*Dd];
__device__ bf16 g_qsh[NT*Dd],  g_qsl[NT*Dd];
__device__ bf16 g_ksh[NT*Dd],  g_ksl[NT*Dd];
__device__ bf16 g_vsh[NT*Dd],  g_vsl[NT*Dd];
__device__ bf16 g_ctxh[NT*Dd], g_ctxl[NT*Dd];
__device__ bf16 g_anh[NT*Dd],  g_anl[NT*Dd];
__device__ bf16 g_t1h[NT*INTERi], g_t1l[NT*INTERi];
__device__ bf16 g_hh[SLOTS*INTERi], g_hl[SLOTS*INTERi];

// ---------------- bf16 hi/lo weights ----------------
__device__ bf16 g_qwh[Dd*Dd], g_qwl[Dd*Dd];
__device__ bf16 g_kwh[Dd*Dd], g_kwl[Dd*Dd];
__device__ bf16 g_vwh[Dd*Dd], g_vwl[Dd*Dd];
__device__ bf16 g_owh[Dd*Dd], g_owl[Dd*Dd];
__device__ bf16 g_s1h[Dd*INTERi], g_s1l[Dd*INTERi];
__device__ bf16 g_s2h[INTERi*Dd], g_s2l[INTERi*Dd];
__device__ bf16 g_r1h[Ee*Dd*INTERi], g_r1l[Ee*Dd*INTERi];
__device__ bf16 g_r2h[Ee*INTERi*Dd], g_r2l[Ee*INTERi*Dd];

__device__ __forceinline__ float gelu_f(float v) {
    return 0.5f * v * (1.0f + erff(v * 0.70710678118654752f));
}

__device__ __forceinline__ void split2(float x, float y, uint32_t& hi, uint32_t& lo) {
    bf16 hx = __float2bfloat16(x), hy = __float2bfloat16(y);
    bf16 lx = __float2bfloat16(x - __bfloat162float(hx));
    bf16 ly = __float2bfloat16(y - __bfloat162float(hy));
    __nv_bfloat162 H = __halves2bfloat162(hx, hy);
    __nv_bfloat162 L = __halves2bfloat162(lx, ly);
    hi = *(uint32_t*)&H; lo = *(uint32_t*)&L;
}

__device__ __forceinline__ uint32_t s2u(const void* p) {
    uint32_t a;
    asm("{ .reg .u64 t; cvta.to.shared.u64 t, %1; cvt.u32.u64 %0, t; }" : "=r"(a) : "l"(p));
    return a;
}

// ---------------- raw mma/ldmatrix helpers ----------------
__device__ __forceinline__ void ldsm4(uint32_t& r0, uint32_t& r1, uint32_t& r2, uint32_t& r3, uint32_t addr) {
    asm volatile("ldmatrix.sync.aligned.m8n8.x4.shared.b16 {%0,%1,%2,%3}, [%4];"
        : "=r"(r0), "=r"(r1), "=r"(r2), "=r"(r3) : "r"(addr));
}
__device__ __forceinline__ void ldsm4t(uint32_t& r0, uint32_t& r1, uint32_t& r2, uint32_t& r3, uint32_t addr) {
    asm volatile("ldmatrix.sync.aligned.m8n8.x4.trans.shared.b16 {%0,%1,%2,%3}, [%4];"
        : "=r"(r0), "=r"(r1), "=r"(r2), "=r"(r3) : "r"(addr));
}
__device__ __forceinline__ void mma16816(float* c, uint32_t a0, uint32_t a1, uint32_t a2, uint32_t a3,
                                         uint32_t b0, uint32_t b1) {
    asm volatile("mma.sync.aligned.m16n8k16.row.col.f32.bf16.bf16.f32 "
        "{%0,%1,%2,%3},{%4,%5,%6,%7},{%8,%9},{%0,%1,%2,%3};"
        : "+f"(c[0]), "+f"(c[1]), "+f"(c[2]), "+f"(c[3])
        : "r"(a0), "r"(a1), "r"(a2), "r"(a3), "r"(b0), "r"(b1));
}

// ---------------- weight conversion, ILP=4 ----------------
__global__ void convw_kernel(const float4* __restrict__ src,
                             uint2* __restrict__ h, uint2* __restrict__ l, int n4) {
    int base = blockIdx.x * 1024 + threadIdx.x;
    float4 v[4]; int idx[4]; bool ok[4];
#pragma unroll
    for (int j = 0; j < 4; j++) {
        idx[j] = base + j * 256;
        ok[j] = idx[j] < n4;
        if (ok[j]) v[j] = src[idx[j]];
    }
#pragma unroll
    for (int j = 0; j < 4; j++) {
        if (!ok[j]) continue;
        uint32_t h0, l0, h1, l1;
        split2(v[j].x, v[j].y, h0, l0);
        split2(v[j].z, v[j].w, h1, l1);
        h[idx[j]] = make_uint2(h0, h1);
        l[idx[j]] = make_uint2(l0, l1);
    }
}

// ================= wmma bf16 split GEMM core (unchanged from R6) ========
typedef wmma::fragment<wmma::accumulator, 16, 16, 16, float> FragC;
typedef wmma::fragment<wmma::matrix_a, 16, 16, 16, bf16, wmma::row_major> FragA;
typedef wmma::fragment<wmma::matrix_b, 16, 16, 16, bf16, wmma::row_major> FragB;

#define LDA 40
#define LDB 136
#define LDC 132
#define OFF_AH 0
#define OFF_AL 10240
#define OFF_BH 20480
#define OFF_BL 29184
#define STAGE  37888
#define DYN_SMEM (2*STAGE)

__device__ __forceinline__ void stage_fill(
    const bf16* __restrict__ Ahg, const bf16* __restrict__ Alg,
    const bf16* __restrict__ Bhg, const bf16* __restrict__ Blg,
    int nb, int k0, const int* rowmap, char* st, int tid)
{
#pragma unroll
    for (int i = 0; i < 2; i++) {
        int s = tid + i * 256;
        int row = s >> 2, q = s & 3;
        int r = rowmap[row];
        char* dh = st + OFF_AH + row * (LDA * 2) + q * 16;
        char* dl = st + OFF_AL + row * (LDA * 2) + q * 16;
        if (r >= 0) {
            __pipeline_memcpy_async(dh, Ahg + (size_t)r * 1024 + k0 + q * 8, 16);
            __pipeline_memcpy_async(dl, Alg + (size_t)r * 1024 + k0 + q * 8, 16);
        } else {
            *(uint4*)dh = make_uint4(0u, 0u, 0u, 0u);
            *(uint4*)dl = make_uint4(0u, 0u, 0u, 0u);
        }
    }
#pragma unroll
    for (int i = 0; i < 2; i++) {
        int s = tid + i * 256;
        int k = s >> 4, q = s & 15;
        char* dh = st + OFF_BH + k * (LDB * 2) + q * 16;
        char* dl = st + OFF_BL + k * (LDB * 2) + q * 16;
        __pipeline_memcpy_async(dh, Bhg + (size_t)(k0 + k) * 1024 + nb + q * 8, 16);
        __pipeline_memcpy_async(dl, Blg + (size_t)(k0 + k) * 1024 + nb + q * 8, 16);
    }
}

__device__ __forceinline__ void wm_mainloop(
    const bf16* __restrict__ Ahg, const bf16* __restrict__ Alg,
    const bf16* __restrict__ Bhg, const bf16* __restrict__ Blg,
    int nb, const int* rowmap, char* sm, FragC accs[4][2])
{
    int tid = threadIdx.x, wid = tid >> 5;
    int wm = wid & 1, wn = wid >> 1;
#pragma unroll
    for (int mt = 0; mt < 4; mt++)
#pragma unroll
        for (int nt = 0; nt < 2; nt++)
            wmma::fill_fragment(accs[mt][nt], 0.0f);

    stage_fill(Ahg, Alg, Bhg, Blg, nb, 0, rowmap, sm, tid);
    __pipeline_commit();

    for (int t = 0; t < 32; t++) {
        char* cur = sm + (t & 1) * STAGE;
        if (t < 31) {
            stage_fill(Ahg, Alg, Bhg, Blg, nb, (t + 1) * 32, rowmap,
                       sm + ((t + 1) & 1) * STAGE, tid);
            __pipeline_commit();
            __pipeline_wait_prior(1);
        } else {
            __pipeline_wait_prior(0);
        }
        __syncthreads();
        const bf16* Ah = (const bf16*)(cur + OFF_AH);
        const bf16* Al = (const bf16*)(cur + OFF_AL);
        const bf16* Bh = (const bf16*)(cur + OFF_BH);
        const bf16* Bl = (const bf16*)(cur + OFF_BL);
#pragma unroll
        for (int ks = 0; ks < 2; ks++) {
            FragB bh0, bh1, bl0, bl1;
            const bf16* bbase = Bh + (ks * 16) * LDB + wn * 32;
            const bf16* bbasl = Bl + (ks * 16) * LDB + wn * 32;
            wmma::load_matrix_sync(bh0, bbase,      LDB);
            wmma::load_matrix_sync(bh1, bbase + 16, LDB);
            wmma::load_matrix_sync(bl0, bbasl,      LDB);
            wmma::load_matrix_sync(bl1, bbasl + 16, LDB);
#pragma unroll
            for (int mt = 0; mt < 4; mt++) {
                FragA ah, al;
                wmma::load_matrix_sync(ah, Ah + (wm * 64 + mt * 16) * LDA + ks * 16, LDA);
                wmma::load_matrix_sync(al, Al + (wm * 64 + mt * 16) * LDA + ks * 16, LDA);
                wmma::mma_sync(accs[mt][0], ah, bh0, accs[mt][0]);
                wmma::mma_sync(accs[mt][0], ah, bl0, accs[mt][0]);
                wmma::mma_sync(accs[mt][0], al, bh0, accs[mt][0]);
                wmma::mma_sync(accs[mt][1], ah, bh1, accs[mt][1]);
                wmma::mma_sync(accs[mt][1], ah, bl1, accs[mt][1]);
                wmma::mma_sync(accs[mt][1], al, bh1, accs[mt][1]);
            }
        }
        __syncthreads();
    }
    float* Cs = (float*)sm;
#pragma unroll
    for (int mt = 0; mt < 4; mt++)
#pragma unroll
        for (int nt = 0; nt < 2; nt++)
            wmma::store_matrix_sync(Cs + (wm * 64 + mt * 16) * LDC + wn * 32 + nt * 16,
                                    accs[mt][nt], LDC, wmma::mem_row_major);
    __syncthreads();
}

#define WM_PROLOGUE(ROWEXPR)                                                   \
    extern __shared__ __align__(16) char dynsm[];                              \
    __shared__ int s_rowmap[128];                                              \
    int tid = threadIdx.x;                                                     \
    if (tid < 128) s_rowmap[tid] = (ROWEXPR);                                  \
    __syncthreads();                                                           \
    FragC accs[4][2];

#define EPI_VARS                                                               \
    float* Cs = (float*)dynsm;                                                 \
    int em = tid >> 1;                                                         \
    int en = (tid & 1) * 64;                                                   \
    const float* crow = Cs + em * LDC + en;

__global__ __launch_bounds__(256) void wm_gemm_kernel(
    const bf16* __restrict__ Ahg, const bf16* __restrict__ Alg,
    const bf16* __restrict__ Bhg, const bf16* __restrict__ Blg,
    const float* __restrict__ bias, int mode,
    const float* __restrict__ res1, const float* __restrict__ res2,
    float* __restrict__ Cf, bf16* __restrict__ Ch, bf16* __restrict__ Cl)
{
    int mb = blockIdx.y * 128, nb = blockIdx.x * 128;
    WM_PROLOGUE(mb + tid)
    wm_mainloop(Ahg, Alg, Bhg, Blg, nb, s_rowmap, dynsm, accs);
    EPI_VARS
    int m = mb + em;
    if (mode == 1) {
        uint32_t* oh = (uint32_t*)(Ch + (size_t)m * 1024 + nb + en);
        uint32_t* ol = (uint32_t*)(Cl + (size_t)m * 1024 + nb + en);
#pragma unroll
        for (int j = 0; j < 64; j += 2) {
            int n = nb + en + j;
            float v0 = gelu_f(crow[j]     + bias[n]);
            float v1 = gelu_f(crow[j + 1] + bias[n + 1]);
            uint32_t h, l; split2(v0, v1, h, l);
            oh[j >> 1] = h; ol[j >> 1] = l;
        }
    } else {
        float* orow = Cf + (size_t)m * 1024 + nb + en;
#pragma unroll
        for (int j = 0; j < 64; j += 4) {
            int n = nb + en + j;
            float4 v;
            v.x = crow[j+0] + bias[n+0];
            v.y = crow[j+1] + bias[n+1];
            v.z = crow[j+2] + bias[n+2];
            v.w = crow[j+3] + bias[n+3];
            if (mode == 2) {
                float4 r = *(const float4*)(res1 + (size_t)m * 1024 + n);
                v.x += r.x; v.y += r.y; v.z += r.z; v.w += r.w;
                if (res2) {
                    float4 r2 = *(const float4*)(res2 + (size_t)m * 1024 + n);
                    v.x += r2.x; v.y += r2.y; v.z += r2.z; v.w += r2.w;
                }
            }
            *(float4*)(orow + j) = v;
        }
    }
}

// ---------------- fused QKV GEMM; q,k fp32 scatter; v split scatter -------
__global__ __launch_bounds__(256) void wm_qkv_kernel(
    const float* __restrict__ qbias, const float* __restrict__ kbias,
    const float* __restrict__ vbias)
{
    const bf16 *Bh_, *Bl_; const float* bias;
    if (blockIdx.z == 0)      { Bh_ = g_qwh; Bl_ = g_qwl; bias = qbias; }
    else if (blockIdx.z == 1) { Bh_ = g_kwh; Bl_ = g_kwl; bias = kbias; }
    else                      { Bh_ = g_vwh; Bl_ = g_vwl; bias = vbias; }
    int mb = blockIdx.y * 128, nb = blockIdx.x * 128;
    WM_PROLOGUE(mb + tid)
    wm_mainloop(g_xnh, g_xnl, Bh_, Bl_, nb, s_rowmap, dynsm, accs);
    EPI_VARS
    int m = mb + em;
    int b = m >> 10, s = m & 1023;
    float* C = (blockIdx.z == 0) ? g_qb : g_kb;
#pragma unroll
    for (int j = 0; j < 64; j += 4) {
        int n = nb + en + j;
        int h = n >> 6, hd = n & 63;
        size_t addr = (size_t)(((b * Hh + h) * Ss + s)) * 64 + hd;
        float4 v;
        v.x = crow[j+0] + bias[n+0];
        v.y = crow[j+1] + bias[n+1];
        v.z = crow[j+2] + bias[n+2];
        v.w = crow[j+3] + bias[n+3];
        if (blockIdx.z == 2) {
            uint32_t h0, l0, h1, l1;
            split2(v.x, v.y, h0, l0);
            split2(v.z, v.w, h1, l1);
            *(uint2*)&g_vsh[addr] = make_uint2(h0, h1);
            *(uint2*)&g_vsl[addr] = make_uint2(l0, l1);
        } else {
            *(float4*)&C[addr] = v;
        }
    }
}

// ---------------- expert GEMM 1 ----------------
__global__ __launch_bounds__(256) void wm_egemm1_kernel(const float* __restrict__ re_b1)
{
    int e = blockIdx.z;
    int cnt = g_cnt[e];
    int mb = blockIdx.y * 128;
    if (mb >= cnt) return;
    int off = g_off[e];
    int nb = blockIdx.x * 128;
    WM_PROLOGUE((mb + tid < cnt) ? g_slot_tok[off + mb + tid] : -1)
    wm_mainloop(g_anh, g_anl,
                g_r1h + (size_t)e * (Dd * INTERi), g_r1l + (size_t)e * (Dd * INTERi),
                nb, s_rowmap, dynsm, accs);
    const float* bias = re_b1 + e * INTERi;
    EPI_VARS
    int row = mb + em;
    if (row < cnt) {
        uint32_t* oh = (uint32_t*)(g_hh + (size_t)(off + row) * INTERi + nb + en);
        uint32_t* ol = (uint32_t*)(g_hl + (size_t)(off + row) * INTERi + nb + en);
#pragma unroll
        for (int j = 0; j < 64; j += 2) {
            int n = nb + en + j;
            float v0 = gelu_f(crow[j]     + bias[n]);
            float v1 = gelu_f(crow[j + 1] + bias[n + 1]);
            uint32_t h, l; split2(v0, v1, h, l);
            oh[j >> 1] = h; ol[j >> 1] = l;
        }
    }
}

// ---------------- expert GEMM 2 ----------------
__global__ __launch_bounds__(256) void wm_egemm2_kernel(const float* __restrict__ re_b2)
{
    int e = blockIdx.z;
    int cnt = g_cnt[e];
    int mb = blockIdx.y * 128;
    if (mb >= cnt) return;
    int off = g_off[e];
    int nb = blockIdx.x * 128;
    WM_PROLOGUE((mb + tid < cnt) ? (off + mb + tid) : -1)
    wm_mainloop(g_hh, g_hl,
                g_r2h + (size_t)e * (INTERi * Dd), g_r2l + (size_t)e * (INTERi * Dd),
                nb, s_rowmap, dynsm, accs);
    const float* bias = re_b2 + e * Dd;
    EPI_VARS
    int row = mb + em;
    if (row < cnt) {
        int slot = off + row;
        int tok = g_slot_tok[slot];
        int rnk = g_slot_rank[slot];
        float gate = g_slot_gate[slot];
        float* outp = g_part + (size_t)(tok * 3 + rnk) * Dd + nb + en;
#pragma unroll
        for (int j = 0; j < 64; j += 4) {
            int n = nb + en + j;
            float4 v;
            v.x = gate * (crow[j+0] + bias[n+0]);
            v.y = gate * (crow[j+1] + bias[n+1]);
            v.z = gate * (crow[j+2] + bias[n+2]);
            v.w = gate * (crow[j+3] + bias[n+3]);
            *(float4*)(outp + j) = v;
        }
    }
}

// ================= tensor-core flash attention =================
// block: (q-tile 64) x (bh). 128 threads = 4 warps; warp w owns q rows w*16..w*16+15.
#define LDT 72            // bf16 tile leading dim (elems)
#define LDS_ 68           // S tile leading dim (floats)
#define AQ_H 0
#define AQ_L 9216
#define AK(s)  (18432 + (s)*18432)
#define AV(s)  (55296 + (s)*18432)
#define AS_OFF 92160
#define AP_H   109568
#define AP_L   118784
#define AM_OFF 128000
#define AL_OFF 128256
#define AC_OFF 128512
#define ATTN_SMEM 128768

__device__ __forceinline__ void attn_fill_kv(char* sm, int s, int grow, int tid) {
    const bf16* srcs[4] = {g_ksh, g_ksl, g_vsh, g_vsl};
    uint32_t dsts[4] = {(uint32_t)AK(s), (uint32_t)(AK(s) + 9216),
                        (uint32_t)AV(s), (uint32_t)(AV(s) + 9216)};
#pragma unroll
    for (int j = 0; j < 16; j++) {
        int id = tid + j * 128;
        int sel = id >> 9, rc = id & 511;
        int row = rc >> 3, cq = rc & 7;
        __pipeline_memcpy_async(sm + dsts[sel] + row * 144 + cq * 16,
                                srcs[sel] + (size_t)(grow + row) * 64 + cq * 8, 16);
    }
}

__global__ __launch_bounds__(128) void attn2_kernel() {
    extern __shared__ __align__(16) char sm[];
    int tid = threadIdx.x, wid = tid >> 5, lane = tid & 31;
    int bh = blockIdx.y;
    int qbase = (int)(gridDim.x - 1 - blockIdx.x) * 64;
    int qrow0 = bh * Ss + qbase;
    uint32_t smb = s2u(sm);

    // fill Q (split) + K/V tile 0
#pragma unroll
    for (int j = 0; j < 8; j++) {
        int id = tid + j * 128;
        int sel = id >> 9, rc = id & 511;
        int row = rc >> 3, cq = rc & 7;
        const bf16* src = sel ? g_qsl : g_qsh;
        __pipeline_memcpy_async(sm + (sel ? AQ_L : AQ_H) + row * 144 + cq * 16,
                                src + (size_t)(qrow0 + row) * 64 + cq * 8, 16);
    }
    attn_fill_kv(sm, 0, bh * Ss + 0, tid);
    __pipeline_commit();

    float* s_m = (float*)(sm + AM_OFF);
    float* s_l = (float*)(sm + AL_OFF);
    float* s_c = (float*)(sm + AC_OFF);
    if (tid < 64) { s_m[tid] = -1e30f; s_l[tid] = 0.f; }

    float O[8][4];
#pragma unroll
    for (int i = 0; i < 8; i++)
#pragma unroll
        for (int j = 0; j < 4; j++) O[i][j] = 0.f;

    int ntiles = qbase / 64 + 1;
    int row_lo = (lane >> 2), row_hi = row_lo + 8;

    for (int t = 0; t < ntiles; t++) {
        int stg = t & 1;
        if (t + 1 < ntiles) {
            attn_fill_kv(sm, (t + 1) & 1, bh * Ss + (t + 1) * 64, tid);
            __pipeline_commit();
            __pipeline_wait_prior(1);
        } else {
            __pipeline_wait_prior(0);
        }
        __syncthreads();

        // ---- S = Q K^T (3-term split), per warp: 16 rows x 64 cols ----
        float Sfr[8][4];
#pragma unroll
        for (int i = 0; i < 8; i++)
#pragma unroll
            for (int j = 0; j < 4; j++) Sfr[i][j] = 0.f;
        uint32_t arow = (uint32_t)(wid * 16 + (lane & 15)) * 144 + (uint32_t)(lane >> 4) * 16;
#pragma unroll
        for (int k = 0; k < 4; k++) {
            uint32_t ah0, ah1, ah2, ah3, al0, al1, al2, al3;
            ldsm4(ah0, ah1, ah2, ah3, smb + AQ_H + arow + k * 32);
            ldsm4(al0, al1, al2, al3, smb + AQ_L + arow + k * 32);
            uint32_t brow = (uint32_t)(lane & 15) * 144 + (uint32_t)(lane >> 4) * 16 + k * 32;
#pragma unroll
            for (int j = 0; j < 4; j++) {
                uint32_t kh0, kh1, kh2, kh3, kl0, kl1, kl2, kl3;
                ldsm4(kh0, kh1, kh2, kh3, smb + AK(stg) + brow + (uint32_t)j * 16 * 144);
                ldsm4(kl0, kl1, kl2, kl3, smb + AK(stg) + 9216 + brow + (uint32_t)j * 16 * 144);
                mma16816(Sfr[j*2],   ah0, ah1, ah2, ah3, kh0, kh2);
                mma16816(Sfr[j*2],   ah0, ah1, ah2, ah3, kl0, kl2);
                mma16816(Sfr[j*2],   al0, al1, al2, al3, kh0, kh2);
                mma16816(Sfr[j*2+1], ah0, ah1, ah2, ah3, kh1, kh3);
                mma16816(Sfr[j*2+1], ah0, ah1, ah2, ah3, kl1, kl3);
                mma16816(Sfr[j*2+1], al0, al1, al2, al3, kh1, kh3);
            }
        }
        // store S (scaled) to smem
        float* sS = (float*)(sm + AS_OFF);
        {
            int r0 = wid * 16 + row_lo, r1 = wid * 16 + row_hi;
            int c0 = (lane & 3) * 2;
#pragma unroll
            for (int nf = 0; nf < 8; nf++) {
                sS[r0 * LDS_ + nf * 8 + c0]     = Sfr[nf][0] * 0.125f;
                sS[r0 * LDS_ + nf * 8 + c0 + 1] = Sfr[nf][1] * 0.125f;
                sS[r1 * LDS_ + nf * 8 + c0]     = Sfr[nf][2] * 0.125f;
                sS[r1 * LDS_ + nf * 8 + c0 + 1] = Sfr[nf][3] * 0.125f;
            }
        }
        __syncthreads();

        // ---- online softmax: 2 threads per row ----
        {
            int row = tid >> 1, half = tid & 1;
            float* srow = (float*)(sm + AS_OFF) + row * LDS_ + half * 32;
            float sv[32];
            bool lastt = (t == ntiles - 1);
#pragma unroll
            for (int c = 0; c < 32; c++) {
                float s_ = srow[c];
                if (lastt && (half * 32 + c) > row) s_ = -1e30f;
                sv[c] = s_;
            }
            float tmax = -1e30f;
#pragma unroll
            for (int c = 0; c < 32; c++) tmax = fmaxf(tmax, sv[c]);
            tmax = fmaxf(tmax, __shfl_xor_sync(0xffffffffu, tmax, 1));
            float mo = s_m[row];
            float nm = fmaxf(mo, tmax);
            float corr = __expf(mo - nm);
            float sum = 0.f;
            uint32_t* ph = (uint32_t*)(sm + AP_H) + (row * LDT + half * 32) / 2;
            uint32_t* pl = (uint32_t*)(sm + AP_L) + (row * LDT + half * 32) / 2;
#pragma unroll
            for (int c = 0; c < 32; c += 2) {
                float p0 = __expf(sv[c] - nm);
                float p1 = __expf(sv[c + 1] - nm);
                sum += p0 + p1;
                uint32_t h, l; split2(p0, p1, h, l);
                ph[c >> 1] = h; pl[c >> 1] = l;
            }
            sum += __shfl_xor_sync(0xffffffffu, sum, 1);
            if (half == 0) {
                s_m[row] = nm;
                s_l[row] = s_l[row] * corr + sum;
                s_c[row] = corr;
            }
        }
        __syncthreads();

        // ---- rescale O, then O += P V (3-term split) ----
        {
            float c_lo = s_c[wid * 16 + row_lo];
            float c_hi = s_c[wid * 16 + row_hi];
#pragma unroll
            for (int nf = 0; nf < 8; nf++) {
                O[nf][0] *= c_lo; O[nf][1] *= c_lo;
                O[nf][2] *= c_hi; O[nf][3] *= c_hi;
            }
        }
#pragma unroll
        for (int k = 0; k < 4; k++) {
            uint32_t ph0, ph1, ph2, ph3, pl0, pl1, pl2, pl3;
            ldsm4(ph0, ph1, ph2, ph3, smb + AP_H + arow + k * 32);
            ldsm4(pl0, pl1, pl2, pl3, smb + AP_L + arow + k * 32);
            uint32_t vrow = (uint32_t)(k * 16 + (lane & 7) + ((lane >> 3) & 1) * 8) * 144
                          + (uint32_t)((lane >> 4) & 1) * 16;
#pragma unroll
            for (int j = 0; j < 4; j++) {
                uint32_t vh0, vh1, vh2, vh3, vl0, vl1, vl2, vl3;
                ldsm4t(vh0, vh1, vh2, vh3, smb + AV(stg) + vrow + (uint32_t)j * 32);
                ldsm4t(vl0, vl1, vl2, vl3, smb + AV(stg) + 9216 + vrow + (uint32_t)j * 32);
                mma16816(O[j*2],   ph0, ph1, ph2, ph3, vh0, vh1);
                mma16816(O[j*2],   ph0, ph1, ph2, ph3, vl0, vl1);
                mma16816(O[j*2],   pl0, pl1, pl2, pl3, vh0, vh1);
                mma16816(O[j*2+1], ph0, ph1, ph2, ph3, vh2, vh3);
                mma16816(O[j*2+1], ph0, ph1, ph2, ph3, vl2, vl3);
                mma16816(O[j*2+1], pl0, pl1, pl2, pl3, vh2, vh3);
            }
        }
        __syncthreads();
    }

    // ---- epilogue: O/l, split -> ctx ----
    {
        int b = bh >> 4, h = bh & 15;
        float linv0 = 1.f / s_l[wid * 16 + row_lo];
        float linv1 = 1.f / s_l[wid * 16 + row_hi];
        int q0 = qbase + wid * 16 + row_lo;
        int q1 = qbase + wid * 16 + row_hi;
        size_t base0 = (size_t)(b * Ss + q0) * 1024 + h * 64;
        size_t base1 = (size_t)(b * Ss + q1) * 1024 + h * 64;
        int c0 = (lane & 3) * 2;
#pragma unroll
        for (int nf = 0; nf < 8; nf++) {
            int col = nf * 8 + c0;
            uint32_t hh, ll;
            split2(O[nf][0] * linv0, O[nf][1] * linv0, hh, ll);
            *(uint32_t*)&g_ctxh[base0 + col] = hh;
            *(uint32_t*)&g_ctxl[base0 + col] = ll;
            split2(O[nf][2] * linv1, O[nf][3] * linv1, hh, ll);
            *(uint32_t*)&g_ctxh[base1 + col] = hh;
            *(uint32_t*)&g_ctxl[base1 + col] = ll;
        }
    }
}

// ---------------- small kernels ----------------
__global__ void reset_kernel() {
    int t = threadIdx.x;
    if (t < Ee) { g_cnt[t] = 0; g_cur[t] = 0; }
}

__global__ void rmsnorm_kernel(const float* __restrict__ in,
                               const float* __restrict__ gamma,
                               float* __restrict__ out,
                               bf16* __restrict__ oh, bf16* __restrict__ ol) {
    int row = blockIdx.x;
    const float* p = in + row * Dd;
    float ss = 0.f;
    for (int d = threadIdx.x; d < Dd; d += blockDim.x) { float v = p[d]; ss += v * v; }
    for (int o = 16; o; o >>= 1) ss += __shfl_xor_sync(0xffffffffu, ss, o);
    __shared__ float red[8];
    int w = threadIdx.x >> 5;
    if ((threadIdx.x & 31) == 0) red[w] = ss;
    __syncthreads();
    if (threadIdx.x < 8) {
        float v = red[threadIdx.x];
        for (int o = 4; o; o >>= 1) v += __shfl_xor_sync(0xffu, v, o);
        if (threadIdx.x == 0) red[0] = v;
    }
    __syncthreads();
    float rinv = rsqrtf(red[0] * (1.0f / Dd) + EPSf);
    for (int d = threadIdx.x * 2; d < Dd; d += blockDim.x * 2) {
        float v0 = p[d] * rinv * gamma[d];
        float v1 = p[d + 1] * rinv * gamma[d + 1];
        out[row * Dd + d]     = v0;
        out[row * Dd + d + 1] = v1;
        uint32_t h, l; split2(v0, v1, h, l);
        *(uint32_t*)&oh[row * Dd + d] = h;
        *(uint32_t*)&ol[row * Dd + d] = l;
    }
}

// rope: fp32 in -> bf16 hi/lo out
__global__ void rope_kernel(const float* __restrict__ p, const float* __restrict__ theta,
                            bf16* __restrict__ oh, bf16* __restrict__ ol) {
    __shared__ float buf[8][64];
    int w = threadIdx.x >> 5;
    int v = blockIdx.x * 8 + w;
    int s = v & (Ss - 1);
    const float* basep = p + (size_t)v * HDh;
    int i = threadIdx.x & 31;
    float x1 = basep[2 * i], x2 = basep[2 * i + 1];
    float ang = (float)s * theta[i];
    float c = cosf(ang), sn = sinf(ang);
    buf[w][i]      = x1 * c - x2 * sn;
    buf[w][32 + i] = x1 * sn + x2 * c;
    __syncwarp();
    float v0 = buf[w][2 * i], v1 = buf[w][2 * i + 1];
    uint32_t h, l; split2(v0, v1, h, l);
    *(uint32_t*)&oh[(size_t)v * HDh + 2 * i] = h;
    *(uint32_t*)&ol[(size_t)v * HDh + 2 * i] = l;
}

__global__ void router_kernel(const float* __restrict__ an, const float* __restrict__ W,
                              const float* __restrict__ bias) {
    int tkn = blockIdx.x;
    __shared__ float xs[Dd];
    for (int d = threadIdx.x; d < Dd; d += 32) xs[d] = an[tkn * Dd + d];
    __syncwarp();
    int e = threadIdx.x;
    float logit = -1e30f;
    if (e < Ee) {
        float acc = bias[e];
        for (int d = 0; d < Dd; d++) acc += xs[d] * W[d * Ee + e];
        logit = acc;
    }
    float mx = logit;
    for (int o = 16; o; o >>= 1) mx = fmaxf(mx, __shfl_xor_sync(0xffffffffu, mx, o));
    float ex = (e < Ee) ? __expf(logit - mx) : 0.f;
    float sm = ex;
    for (int o = 16; o; o >>= 1) sm += __shfl_xor_sync(0xffffffffu, sm, o);
    float pw = ex / sm;
    for (int it = 0; it < 3; it++) {
        float bv = pw; int bi = e;
        for (int o = 16; o; o >>= 1) {
            float ov = __shfl_xor_sync(0xffffffffu, bv, o);
            int   oi = __shfl_xor_sync(0xffffffffu, bi, o);
            if (ov > bv || (ov == bv && oi < bi)) { bv = ov; bi = oi; }
        }
        if (threadIdx.x == 0) {
            g_topi[tkn * 3 + it] = bi;
            g_topv[tkn * 3 + it] = bv;
            atomicAdd(&g_cnt[bi], 1);
        }
        if (e == bi) pw = -1.f;
    }
}

__global__ void scan_kernel() {
    if (threadIdx.x == 0) {
        int s = 0;
        for (int e = 0; e < Ee; e++) { g_off[e] = s; s += g_cnt[e]; }
    }
}

__global__ void fill_kernel() {
    int i = blockIdx.x * 256 + threadIdx.x;
    if (i >= SLOTS) return;
    int tkn = i / 3, r = i - tkn * 3;
    int e = g_topi[i];
    int pos = atomicAdd(&g_cur[e], 1);
    int slot = g_off[e] + pos;
    g_slot_tok[slot] = tkn;
    g_slot_rank[slot] = r;
    g_slot_gate[slot] = g_topv[i];
}

__global__ void final_kernel(float* __restrict__ out) {
    int i = blockIdx.x * 256 + threadIdx.x;
    int t = i >> 10, n = i & 1023;
    float v = out[i];
    v += g_part[(size_t)(t * 3 + 0) * Dd + n];
    v += g_part[(size_t)(t * 3 + 1) * Dd + n];
    v += g_part[(size_t)(t * 3 + 2) * Dd + n];
    out[i] = v;
}

// ---------------- launch ----------------
extern "C" void kernel_launch(void* const* d_in, const int* in_sizes, int n_in,
                              void* d_out, int out_size) {
    const float* x      = (const float*)d_in[0];
    const float* theta  = (const float*)d_in[2];
    const float* gamma1 = (const float*)d_in[3];
    const float* gamma2 = (const float*)d_in[4];
    const float* q_w  = (const float*)d_in[5];  const float* q_b  = (const float*)d_in[6];
    const float* k_w  = (const float*)d_in[7];  const float* k_b  = (const float*)d_in[8];
    const float* v_w  = (const float*)d_in[9];  const float* v_b  = (const float*)d_in[10];
    const float* o_w  = (const float*)d_in[11]; const float* o_b  = (const float*)d_in[12];
    const float* r_w  = (const float*)d_in[13]; const float* r_b  = (const float*)d_in[14];
    const float* sw1  = (const float*)d_in[15]; const float* sb1  = (const float*)d_in[16];
    const float* sw2  = (const float*)d_in[17]; const float* sb2  = (const float*)d_in[18];
    const float* rw1  = (const float*)d_in[19]; const float* rb1  = (const float*)d_in[20];
    const float* rw2  = (const float*)d_in[21]; const float* rb2  = (const float*)d_in[22];
    float* out = (float*)d_out;

    float *xn, *qb, *kb, *attn, *an;
    bf16 *xnh, *xnl, *ctxh, *ctxl, *anh, *anl, *t1h, *t1l;
    bf16 *qsh, *qsl, *ksh, *ksl;
    bf16 *qwh, *qwl, *kwh, *kwl, *vwh, *vwl, *owh, *owl, *s1h, *s1l, *s2h, *s2l;
    bf16 *r1h, *r1l, *r2h, *r2l;
    cudaGetSymbolAddress((void**)&xn,   g_xn);
    cudaGetSymbolAddress((void**)&qb,   g_qb);
    cudaGetSymbolAddress((void**)&kb,   g_kb);
    cudaGetSymbolAddress((void**)&attn, g_attn);
    cudaGetSymbolAddress((void**)&an,   g_an);
    cudaGetSymbolAddress((void**)&xnh,  g_xnh);  cudaGetSymbolAddress((void**)&xnl, g_xnl);
    cudaGetSymbolAddress((void**)&ctxh, g_ctxh); cudaGetSymbolAddress((void**)&ctxl, g_ctxl);
    cudaGetSymbolAddress((void**)&anh,  g_anh);  cudaGetSymbolAddress((void**)&anl, g_anl);
    cudaGetSymbolAddress((void**)&t1h,  g_t1h);  cudaGetSymbolAddress((void**)&t1l, g_t1l);
    cudaGetSymbolAddress((void**)&qsh,  g_qsh);  cudaGetSymbolAddress((void**)&qsl, g_qsl);
    cudaGetSymbolAddress((void**)&ksh,  g_ksh);  cudaGetSymbolAddress((void**)&ksl, g_ksl);
    cudaGetSymbolAddress((void**)&qwh,  g_qwh);  cudaGetSymbolAddress((void**)&qwl, g_qwl);
    cudaGetSymbolAddress((void**)&kwh,  g_kwh);  cudaGetSymbolAddress((void**)&kwl, g_kwl);
    cudaGetSymbolAddress((void**)&vwh,  g_vwh);  cudaGetSymbolAddress((void**)&vwl, g_vwl);
    cudaGetSymbolAddress((void**)&owh,  g_owh);  cudaGetSymbolAddress((void**)&owl, g_owl);
    cudaGetSymbolAddress((void**)&s1h,  g_s1h);  cudaGetSymbolAddress((void**)&s1l, g_s1l);
    cudaGetSymbolAddress((void**)&s2h,  g_s2h);  cudaGetSymbolAddress((void**)&s2l, g_s2l);
    cudaGetSymbolAddress((void**)&r1h,  g_r1h);  cudaGetSymbolAddress((void**)&r1l, g_r1l);
    cudaGetSymbolAddress((void**)&r2h,  g_r2h);  cudaGetSymbolAddress((void**)&r2l, g_r2l);

    cudaFuncSetAttribute(wm_gemm_kernel,   cudaFuncAttributeMaxDynamicSharedMemorySize, DYN_SMEM);
    cudaFuncSetAttribute(wm_qkv_kernel,    cudaFuncAttributeMaxDynamicSharedMemorySize, DYN_SMEM);
    cudaFuncSetAttribute(wm_egemm1_kernel, cudaFuncAttributeMaxDynamicSharedMemorySize, DYN_SMEM);
    cudaFuncSetAttribute(wm_egemm2_kernel, cudaFuncAttributeMaxDynamicSharedMemorySize, DYN_SMEM);
    cudaFuncSetAttribute(attn2_kernel,     cudaFuncAttributeMaxDynamicSharedMemorySize, ATTN_SMEM);

    const int D4 = Dd * Dd / 4;
    const int E4 = Ee * Dd * INTERi / 4;
    convw_kernel<<<(D4 + 1023) / 1024, 256>>>((const float4*)q_w, (uint2*)qwh, (uint2*)qwl, D4);
    convw_kernel<<<(D4 + 1023) / 1024, 256>>>((const float4*)k_w, (uint2*)kwh, (uint2*)kwl, D4);
    convw_kernel<<<(D4 + 1023) / 1024, 256>>>((const float4*)v_w, (uint2*)vwh, (uint2*)vwl, D4);
    convw_kernel<<<(D4 + 1023) / 1024, 256>>>((const float4*)o_w, (uint2*)owh, (uint2*)owl, D4);
    convw_kernel<<<(D4 + 1023) / 1024, 256>>>((const float4*)sw1, (uint2*)s1h, (uint2*)s1l, D4);
    convw_kernel<<<(D4 + 1023) / 1024, 256>>>((const float4*)sw2, (uint2*)s2h, (uint2*)s2l, D4);
    convw_kernel<<<(E4 + 1023) / 1024, 256>>>((const float4*)rw1, (uint2*)r1h, (uint2*)r1l, E4);
    convw_kernel<<<(E4 + 1023) / 1024, 256>>>((const float4*)rw2, (uint2*)r2h, (uint2*)r2l, E4);

    dim3 thr(256);
    dim3 grid8x16(8, 16);

    reset_kernel<<<1, 32>>>();
    rmsnorm_kernel<<<NT, 256>>>(x, gamma1, xn, xnh, xnl);

    wm_qkv_kernel<<<dim3(8, 16, 3), thr, DYN_SMEM>>>(q_b, k_b, v_b);

    rope_kernel<<<Bb * Hh * Ss / 8, 256>>>(qb, theta, qsh, qsl);
    rope_kernel<<<Bb * Hh * Ss / 8, 256>>>(kb, theta, ksh, ksl);

    attn2_kernel<<<dim3(16, Bb * Hh), 128, ATTN_SMEM>>>();

    wm_gemm_kernel<<<grid8x16, thr, DYN_SMEM>>>(ctxh, ctxl, owh, owl, o_b, 2, xn, nullptr,
                                                attn, nullptr, nullptr);
    rmsnorm_kernel<<<NT, 256>>>(attn, gamma2, an, anh, anl);

    wm_gemm_kernel<<<grid8x16, thr, DYN_SMEM>>>(anh, anl, s1h, s1l, sb1, 1, nullptr, nullptr,
                                                nullptr, t1h, t1l);
    wm_gemm_kernel<<<grid8x16, thr, DYN_SMEM>>>(t1h, t1l, s2h, s2l, sb2, 2, an, attn,
                                                out, nullptr, nullptr);

    router_kernel<<<NT, 32>>>(an, r_w, r_b);
    scan_kernel<<<1, 32>>>();
    fill_kernel<<<(SLOTS + 255) / 256, 256>>>();

    wm_egemm1_kernel<<<dim3(8, 16, Ee), thr, DYN_SMEM>>>(rb1);
    wm_egemm2_kernel<<<dim3(8, 16, Ee), thr, DYN_SMEM>>>(rb2);

    final_kernel<<<(NT * Dd) / 256, 256>>>(out);
}

// round 11
// speedup vs baseline: 2.3839x; 1.1323x over previous
#include <cuda_runtime.h>
#include <cuda_bf16.h>
#include <cuda_pipeline.h>
#include <mma.h>
#include <cstdint>

using namespace nvcuda;

#define Bb     2
#define Ss     1024
#define Dd     1024
#define Hh     16
#define HDh    64
#define NT     (Bb*Ss)
#define Ee     31
#define INTERi 1024
#define EPSf   1e-5f
#define SLOTS  (NT*3)

typedef __nv_bfloat16 bf16;

// ---------------- fp32 scratch ----------------
__device__ float g_xn  [NT*Dd];
__device__ float g_qb  [NT*Dd];
__device__ float g_kb  [NT*Dd];
__device__ float g_attn[NT*Dd];
__device__ float g_an  [NT*Dd];
__device__ float g_part[SLOTS*Dd];
__device__ int   g_topi[SLOTS];
__device__ float g_topv[SLOTS];
__device__ int   g_cnt[Ee];
__device__ int   g_off[Ee];
__device__ int   g_cur[Ee];
__device__ int   g_slot_tok [SLOTS];
__device__ int   g_slot_rank[SLOTS];
__device__ float g_slot_gate[SLOTS];

// ---------------- bf16 hi/lo activations ----------------
__device__ bf16 g_xnh[NT*Dd],  g_xnl[NT*Dd];
__device__ bf16 g_qsh[NT*Dd],  g_qsl[NT*Dd];
__device__ bf16 g_ksh[NT*Dd],  g_ksl[NT*Dd];
__device__ bf16 g_vsh[NT*Dd],  g_vsl[NT*Dd];
__device__ bf16 g_ctxh[NT*Dd], g_ctxl[NT*Dd];
__device__ bf16 g_anh[NT*Dd],  g_anl[NT*Dd];
__device__ bf16 g_t1h[NT*INTERi], g_t1l[NT*INTERi];
__device__ bf16 g_hh[SLOTS*INTERi], g_hl[SLOTS*INTERi];

// ---------------- bf16 hi/lo weights ----------------
__device__ bf16 g_qwh[Dd*Dd], g_qwl[Dd*Dd];
__device__ bf16 g_kwh[Dd*Dd], g_kwl[Dd*Dd];
__device__ bf16 g_vwh[Dd*Dd], g_vwl[Dd*Dd];
__device__ bf16 g_owh[Dd*Dd], g_owl[Dd*Dd];
__device__ bf16 g_s1h[Dd*INTERi], g_s1l[Dd*INTERi];
__device__ bf16 g_s2h[INTERi*Dd], g_s2l[INTERi*Dd];
__device__ bf16 g_r1h[Ee*Dd*INTERi], g_r1l[Ee*Dd*INTERi];
__device__ bf16 g_r2h[Ee*INTERi*Dd], g_r2l[Ee*INTERi*Dd];

__device__ __forceinline__ float gelu_f(float v) {
    return 0.5f * v * (1.0f + erff(v * 0.70710678118654752f));
}

__device__ __forceinline__ void split2(float x, float y, uint32_t& hi, uint32_t& lo) {
    bf16 hx = __float2bfloat16(x), hy = __float2bfloat16(y);
    bf16 lx = __float2bfloat16(x - __bfloat162float(hx));
    bf16 ly = __float2bfloat16(y - __bfloat162float(hy));
    __nv_bfloat162 H = __halves2bfloat162(hx, hy);
    __nv_bfloat162 L = __halves2bfloat162(lx, ly);
    hi = *(uint32_t*)&H; lo = *(uint32_t*)&L;
}

__device__ __forceinline__ uint32_t s2u(const void* p) {
    uint32_t a;
    asm("{ .reg .u64 t; cvta.to.shared.u64 t, %1; cvt.u32.u64 %0, t; }" : "=r"(a) : "l"(p));
    return a;
}

// ---------------- raw mma/ldmatrix helpers ----------------
__device__ __forceinline__ void ldsm4(uint32_t& r0, uint32_t& r1, uint32_t& r2, uint32_t& r3, uint32_t addr) {
    asm volatile("ldmatrix.sync.aligned.m8n8.x4.shared.b16 {%0,%1,%2,%3}, [%4];"
        : "=r"(r0), "=r"(r1), "=r"(r2), "=r"(r3) : "r"(addr));
}
__device__ __forceinline__ void ldsm4t(uint32_t& r0, uint32_t& r1, uint32_t& r2, uint32_t& r3, uint32_t addr) {
    asm volatile("ldmatrix.sync.aligned.m8n8.x4.trans.shared.b16 {%0,%1,%2,%3}, [%4];"
        : "=r"(r0), "=r"(r1), "=r"(r2), "=r"(r3) : "r"(addr));
}
__device__ __forceinline__ void mma16816(float* c, uint32_t a0, uint32_t a1, uint32_t a2, uint32_t a3,
                                         uint32_t b0, uint32_t b1) {
    asm volatile("mma.sync.aligned.m16n8k16.row.col.f32.bf16.bf16.f32 "
        "{%0,%1,%2,%3},{%4,%5,%6,%7},{%8,%9},{%0,%1,%2,%3};"
        : "+f"(c[0]), "+f"(c[1]), "+f"(c[2]), "+f"(c[3])
        : "r"(a0), "r"(a1), "r"(a2), "r"(a3), "r"(b0), "r"(b1));
}

// ---------------- weight conversion ----------------
#define D4 (Dd*Dd/4)
#define E4 (Ee*Dd*INTERi/4)

__global__ void convw_kernel(const float4* __restrict__ src,
                             uint2* __restrict__ h, uint2* __restrict__ l, int n4) {
    int base = blockIdx.x * 1024 + threadIdx.x;
    float4 v[4]; int idx[4]; bool ok[4];
#pragma unroll
    for (int j = 0; j < 4; j++) {
        idx[j] = base + j * 256;
        ok[j] = idx[j] < n4;
        if (ok[j]) v[j] = src[idx[j]];
    }
#pragma unroll
    for (int j = 0; j < 4; j++) {
        if (!ok[j]) continue;
        uint32_t h0, l0, h1, l1;
        split2(v[j].x, v[j].y, h0, l0);
        split2(v[j].z, v[j].w, h1, l1);
        h[idx[j]] = make_uint2(h0, h1);
        l[idx[j]] = make_uint2(l0, l1);
    }
}

// six DxD tensors in one launch (grid.y selects tensor)
__global__ void convw6_kernel(
    const float4* s0, const float4* s1, const float4* s2,
    const float4* s3, const float4* s4, const float4* s5,
    uint2* h0, uint2* h1, uint2* h2, uint2* h3, uint2* h4, uint2* h5,
    uint2* l0, uint2* l1, uint2* l2, uint2* l3, uint2* l4, uint2* l5)
{
    const float4* srcs[6] = {s0, s1, s2, s3, s4, s5};
    uint2* hs[6] = {h0, h1, h2, h3, h4, h5};
    uint2* ls[6] = {l0, l1, l2, l3, l4, l5};
    int w = blockIdx.y;
    const float4* src = srcs[w];
    uint2* h = hs[w];
    uint2* l = ls[w];
    int base = blockIdx.x * 1024 + threadIdx.x;
    float4 v[4];
#pragma unroll
    for (int j = 0; j < 4; j++) v[j] = src[base + j * 256];
#pragma unroll
    for (int j = 0; j < 4; j++) {
        uint32_t a0, b0, a1, b1;
        split2(v[j].x, v[j].y, a0, b0);
        split2(v[j].z, v[j].w, a1, b1);
        h[base + j * 256] = make_uint2(a0, a1);
        l[base + j * 256] = make_uint2(b0, b1);
    }
}

// ================= wmma bf16 split GEMM core =================
typedef wmma::fragment<wmma::accumulator, 16, 16, 16, float> FragC;
typedef wmma::fragment<wmma::matrix_a, 16, 16, 16, bf16, wmma::row_major> FragA;
typedef wmma::fragment<wmma::matrix_b, 16, 16, 16, bf16, wmma::row_major> FragB;

#define LDA 40
#define LDB 136
#define LDC 132
#define OFF_AH 0
#define OFF_AL 10240
#define OFF_BH 20480
#define OFF_BL 29184
#define STAGE  37888
#define DYN_SMEM (2*STAGE)

__device__ __forceinline__ void stage_fill(
    const bf16* __restrict__ Ahg, const bf16* __restrict__ Alg,
    const bf16* __restrict__ Bhg, const bf16* __restrict__ Blg,
    int nb, int k0, const int* rowmap, char* st, int tid)
{
#pragma unroll
    for (int i = 0; i < 2; i++) {
        int s = tid + i * 256;
        int row = s >> 2, q = s & 3;
        int r = rowmap[row];
        char* dh = st + OFF_AH + row * (LDA * 2) + q * 16;
        char* dl = st + OFF_AL + row * (LDA * 2) + q * 16;
        if (r >= 0) {
            __pipeline_memcpy_async(dh, Ahg + (size_t)r * 1024 + k0 + q * 8, 16);
            __pipeline_memcpy_async(dl, Alg + (size_t)r * 1024 + k0 + q * 8, 16);
        } else {
            *(uint4*)dh = make_uint4(0u, 0u, 0u, 0u);
            *(uint4*)dl = make_uint4(0u, 0u, 0u, 0u);
        }
    }
#pragma unroll
    for (int i = 0; i < 2; i++) {
        int s = tid + i * 256;
        int k = s >> 4, q = s & 15;
        char* dh = st + OFF_BH + k * (LDB * 2) + q * 16;
        char* dl = st + OFF_BL + k * (LDB * 2) + q * 16;
        __pipeline_memcpy_async(dh, Bhg + (size_t)(k0 + k) * 1024 + nb + q * 8, 16);
        __pipeline_memcpy_async(dl, Blg + (size_t)(k0 + k) * 1024 + nb + q * 8, 16);
    }
}

__device__ __forceinline__ void wm_mainloop(
    const bf16* __restrict__ Ahg, const bf16* __restrict__ Alg,
    const bf16* __restrict__ Bhg, const bf16* __restrict__ Blg,
    int nb, const int* rowmap, char* sm, FragC accs[4][2])
{
    int tid = threadIdx.x, wid = tid >> 5;
    int wm = wid & 1, wn = wid >> 1;
#pragma unroll
    for (int mt = 0; mt < 4; mt++)
#pragma unroll
        for (int nt = 0; nt < 2; nt++)
            wmma::fill_fragment(accs[mt][nt], 0.0f);

    stage_fill(Ahg, Alg, Bhg, Blg, nb, 0, rowmap, sm, tid);
    __pipeline_commit();

    for (int t = 0; t < 32; t++) {
        char* cur = sm + (t & 1) * STAGE;
        if (t < 31) {
            stage_fill(Ahg, Alg, Bhg, Blg, nb, (t + 1) * 32, rowmap,
                       sm + ((t + 1) & 1) * STAGE, tid);
            __pipeline_commit();
            __pipeline_wait_prior(1);
        } else {
            __pipeline_wait_prior(0);
        }
        __syncthreads();
        const bf16* Ah = (const bf16*)(cur + OFF_AH);
        const bf16* Al = (const bf16*)(cur + OFF_AL);
        const bf16* Bh = (const bf16*)(cur + OFF_BH);
        const bf16* Bl = (const bf16*)(cur + OFF_BL);
#pragma unroll
        for (int ks = 0; ks < 2; ks++) {
            FragB bh0, bh1, bl0, bl1;
            const bf16* bbase = Bh + (ks * 16) * LDB + wn * 32;
            const bf16* bbasl = Bl + (ks * 16) * LDB + wn * 32;
            wmma::load_matrix_sync(bh0, bbase,      LDB);
            wmma::load_matrix_sync(bh1, bbase + 16, LDB);
            wmma::load_matrix_sync(bl0, bbasl,      LDB);
            wmma::load_matrix_sync(bl1, bbasl + 16, LDB);
#pragma unroll
            for (int mt = 0; mt < 4; mt++) {
                FragA ah, al;
                wmma::load_matrix_sync(ah, Ah + (wm * 64 + mt * 16) * LDA + ks * 16, LDA);
                wmma::load_matrix_sync(al, Al + (wm * 64 + mt * 16) * LDA + ks * 16, LDA);
                wmma::mma_sync(accs[mt][0], ah, bh0, accs[mt][0]);
                wmma::mma_sync(accs[mt][0], ah, bl0, accs[mt][0]);
                wmma::mma_sync(accs[mt][0], al, bh0, accs[mt][0]);
                wmma::mma_sync(accs[mt][1], ah, bh1, accs[mt][1]);
                wmma::mma_sync(accs[mt][1], ah, bl1, accs[mt][1]);
                wmma::mma_sync(accs[mt][1], al, bh1, accs[mt][1]);
            }
        }
        __syncthreads();
    }
    float* Cs = (float*)sm;
#pragma unroll
    for (int mt = 0; mt < 4; mt++)
#pragma unroll
        for (int nt = 0; nt < 2; nt++)
            wmma::store_matrix_sync(Cs + (wm * 64 + mt * 16) * LDC + wn * 32 + nt * 16,
                                    accs[mt][nt], LDC, wmma::mem_row_major);
    __syncthreads();
}

#define WM_PROLOGUE(ROWEXPR)                                                   \
    extern __shared__ __align__(16) char dynsm[];                              \
    __shared__ int s_rowmap[128];                                              \
    int tid = threadIdx.x;                                                     \
    if (tid < 128) s_rowmap[tid] = (ROWEXPR);                                  \
    __syncthreads();                                                           \
    FragC accs[4][2];

#define EPI_VARS                                                               \
    float* Cs = (float*)dynsm;                                                 \
    int em = tid >> 1;                                                         \
    int en = (tid & 1) * 64;                                                   \
    const float* crow = Cs + em * LDC + en;

__global__ __launch_bounds__(256, 2) void wm_gemm_kernel(
    const bf16* __restrict__ Ahg, const bf16* __restrict__ Alg,
    const bf16* __restrict__ Bhg, const bf16* __restrict__ Blg,
    const float* __restrict__ bias, int mode,
    const float* __restrict__ res1, const float* __restrict__ res2,
    float* __restrict__ Cf, bf16* __restrict__ Ch, bf16* __restrict__ Cl)
{
    int mb = blockIdx.y * 128, nb = blockIdx.x * 128;
    WM_PROLOGUE(mb + tid)
    wm_mainloop(Ahg, Alg, Bhg, Blg, nb, s_rowmap, dynsm, accs);
    EPI_VARS
    int m = mb + em;
    if (mode == 1) {
        uint32_t* oh = (uint32_t*)(Ch + (size_t)m * 1024 + nb + en);
        uint32_t* ol = (uint32_t*)(Cl + (size_t)m * 1024 + nb + en);
#pragma unroll
        for (int j = 0; j < 64; j += 2) {
            int n = nb + en + j;
            float v0 = gelu_f(crow[j]     + bias[n]);
            float v1 = gelu_f(crow[j + 1] + bias[n + 1]);
            uint32_t h, l; split2(v0, v1, h, l);
            oh[j >> 1] = h; ol[j >> 1] = l;
        }
    } else {
        float* orow = Cf + (size_t)m * 1024 + nb + en;
#pragma unroll
        for (int j = 0; j < 64; j += 4) {
            int n = nb + en + j;
            float4 v;
            v.x = crow[j+0] + bias[n+0];
            v.y = crow[j+1] + bias[n+1];
            v.z = crow[j+2] + bias[n+2];
            v.w = crow[j+3] + bias[n+3];
            if (mode == 2) {
                float4 r = *(const float4*)(res1 + (size_t)m * 1024 + n);
                v.x += r.x; v.y += r.y; v.z += r.z; v.w += r.w;
                if (res2) {
                    float4 r2 = *(const float4*)(res2 + (size_t)m * 1024 + n);
                    v.x += r2.x; v.y += r2.y; v.z += r2.z; v.w += r2.w;
                }
            }
            *(float4*)(orow + j) = v;
        }
    }
}

__global__ __launch_bounds__(256, 2) void wm_qkv_kernel(
    const float* __restrict__ qbias, const float* __restrict__ kbias,
    const float* __restrict__ vbias)
{
    const bf16 *Bh_, *Bl_; const float* bias;
    if (blockIdx.z == 0)      { Bh_ = g_qwh; Bl_ = g_qwl; bias = qbias; }
    else if (blockIdx.z == 1) { Bh_ = g_kwh; Bl_ = g_kwl; bias = kbias; }
    else                      { Bh_ = g_vwh; Bl_ = g_vwl; bias = vbias; }
    int mb = blockIdx.y * 128, nb = blockIdx.x * 128;
    WM_PROLOGUE(mb + tid)
    wm_mainloop(g_xnh, g_xnl, Bh_, Bl_, nb, s_rowmap, dynsm, accs);
    EPI_VARS
    int m = mb + em;
    int b = m >> 10, s = m & 1023;
    float* C = (blockIdx.z == 0) ? g_qb : g_kb;
#pragma unroll
    for (int j = 0; j < 64; j += 4) {
        int n = nb + en + j;
        int h = n >> 6, hd = n & 63;
        size_t addr = (size_t)(((b * Hh + h) * Ss + s)) * 64 + hd;
        float4 v;
        v.x = crow[j+0] + bias[n+0];
        v.y = crow[j+1] + bias[n+1];
        v.z = crow[j+2] + bias[n+2];
        v.w = crow[j+3] + bias[n+3];
        if (blockIdx.z == 2) {
            uint32_t h0, l0, h1, l1;
            split2(v.x, v.y, h0, l0);
            split2(v.z, v.w, h1, l1);
            *(uint2*)&g_vsh[addr] = make_uint2(h0, h1);
            *(uint2*)&g_vsl[addr] = make_uint2(l0, l1);
        } else {
            *(float4*)&C[addr] = v;
        }
    }
}

__global__ __launch_bounds__(256, 2) void wm_egemm1_kernel(const float* __restrict__ re_b1)
{
    int e = blockIdx.z;
    int cnt = g_cnt[e];
    int mb = blockIdx.y * 128;
    if (mb >= cnt) return;
    int off = g_off[e];
    int nb = blockIdx.x * 128;
    WM_PROLOGUE((mb + tid < cnt) ? g_slot_tok[off + mb + tid] : -1)
    wm_mainloop(g_anh, g_anl,
                g_r1h + (size_t)e * (Dd * INTERi), g_r1l + (size_t)e * (Dd * INTERi),
                nb, s_rowmap, dynsm, accs);
    const float* bias = re_b1 + e * INTERi;
    EPI_VARS
    int row = mb + em;
    if (row < cnt) {
        uint32_t* oh = (uint32_t*)(g_hh + (size_t)(off + row) * INTERi + nb + en);
        uint32_t* ol = (uint32_t*)(g_hl + (size_t)(off + row) * INTERi + nb + en);
#pragma unroll
        for (int j = 0; j < 64; j += 2) {
            int n = nb + en + j;
            float v0 = gelu_f(crow[j]     + bias[n]);
            float v1 = gelu_f(crow[j + 1] + bias[n + 1]);
            uint32_t h, l; split2(v0, v1, h, l);
            oh[j >> 1] = h; ol[j >> 1] = l;
        }
    }
}

__global__ __launch_bounds__(256, 2) void wm_egemm2_kernel(const float* __restrict__ re_b2)
{
    int e = blockIdx.z;
    int cnt = g_cnt[e];
    int mb = blockIdx.y * 128;
    if (mb >= cnt) return;
    int off = g_off[e];
    int nb = blockIdx.x * 128;
    WM_PROLOGUE((mb + tid < cnt) ? (off + mb + tid) : -1)
    wm_mainloop(g_hh, g_hl,
                g_r2h + (size_t)e * (INTERi * Dd), g_r2l + (size_t)e * (INTERi * Dd),
                nb, s_rowmap, dynsm, accs);
    const float* bias = re_b2 + e * Dd;
    EPI_VARS
    int row = mb + em;
    if (row < cnt) {
        int slot = off + row;
        int tok = g_slot_tok[slot];
        int rnk = g_slot_rank[slot];
        float gate = g_slot_gate[slot];
        float* outp = g_part + (size_t)(tok * 3 + rnk) * Dd + nb + en;
#pragma unroll
        for (int j = 0; j < 64; j += 4) {
            int n = nb + en + j;
            float4 v;
            v.x = gate * (crow[j+0] + bias[n+0]);
            v.y = gate * (crow[j+1] + bias[n+1]);
            v.z = gate * (crow[j+2] + bias[n+2]);
            v.w = gate * (crow[j+3] + bias[n+3]);
            *(float4*)(outp + j) = v;
        }
    }
}

// ================= tensor-core flash attention =================
// 128-query tile, 256 threads (8 warps); warp w owns q rows w*16..w*16+15.
#define LDT 72
#define LDS_ 68
#define AQ_H 0
#define AQ_L 18432
#define AKOF(s)  (36864 + (s)*36864)
#define AVOF(s)  (AKOF(s) + 18432)
#define AS_OFF 110592
#define AP_H   145408
#define AP_L   163840
#define AM_OFF 182272
#define AL_OFF 182784
#define AC_OFF 183296
#define ATTN_SMEM 183808

__device__ __forceinline__ void attn_fill_kv(char* sm, int s, int grow, int tid) {
    const bf16* srcs[4] = {g_ksh, g_ksl, g_vsh, g_vsl};
    uint32_t dsts[4] = {(uint32_t)AKOF(s), (uint32_t)(AKOF(s) + 9216),
                        (uint32_t)AVOF(s), (uint32_t)(AVOF(s) + 9216)};
#pragma unroll
    for (int j = 0; j < 8; j++) {
        int id = tid + j * 256;
        int sel = id >> 9, rc = id & 511;
        int row = rc >> 3, cq = rc & 7;
        __pipeline_memcpy_async(sm + dsts[sel] + row * 144 + cq * 16,
                                srcs[sel] + (size_t)(grow + row) * 64 + cq * 8, 16);
    }
}

__global__ __launch_bounds__(256) void attn2_kernel() {
    extern __shared__ __align__(16) char sm[];
    int tid = threadIdx.x, wid = tid >> 5, lane = tid & 31;
    int bh = blockIdx.y;
    int qbase = (int)(gridDim.x - 1 - blockIdx.x) * 128;
    int qrow0 = bh * Ss + qbase;
    uint32_t smb = s2u(sm);

    // fill Q hi/lo: 2 regions x 128 rows x 8 16B-chunks
#pragma unroll
    for (int j = 0; j < 8; j++) {
        int id = tid + j * 256;
        int sel = id >> 10, rc = id & 1023;
        int row = rc >> 3, cq = rc & 7;
        const bf16* src = sel ? g_qsl : g_qsh;
        __pipeline_memcpy_async(sm + (sel ? AQ_L : AQ_H) + row * 144 + cq * 16,
                                src + (size_t)(qrow0 + row) * 64 + cq * 8, 16);
    }
    attn_fill_kv(sm, 0, bh * Ss, tid);
    __pipeline_commit();

    float* s_m = (float*)(sm + AM_OFF);
    float* s_l = (float*)(sm + AL_OFF);
    float* s_c = (float*)(sm + AC_OFF);
    if (tid < 128) { s_m[tid] = -1e30f; s_l[tid] = 0.f; }

    float O[8][4];
#pragma unroll
    for (int i = 0; i < 8; i++)
#pragma unroll
        for (int j = 0; j < 4; j++) O[i][j] = 0.f;

    int ntiles = qbase / 64 + 2;
    int row_lo = lane >> 2, row_hi = row_lo + 8;

    for (int t = 0; t < ntiles; t++) {
        int stg = t & 1;
        if (t + 1 < ntiles) {
            attn_fill_kv(sm, (t + 1) & 1, bh * Ss + (t + 1) * 64, tid);
            __pipeline_commit();
            __pipeline_wait_prior(1);
        } else {
            __pipeline_wait_prior(0);
        }
        __syncthreads();

        // ---- S = Q K^T (3-term split), per warp: 16 rows x 64 cols ----
        float Sfr[8][4];
#pragma unroll
        for (int i = 0; i < 8; i++)
#pragma unroll
            for (int j = 0; j < 4; j++) Sfr[i][j] = 0.f;
        uint32_t arow = (uint32_t)(wid * 16 + (lane & 15)) * 144 + (uint32_t)(lane >> 4) * 16;
#pragma unroll
        for (int k = 0; k < 4; k++) {
            uint32_t ah0, ah1, ah2, ah3, al0, al1, al2, al3;
            ldsm4(ah0, ah1, ah2, ah3, smb + AQ_H + arow + k * 32);
            ldsm4(al0, al1, al2, al3, smb + AQ_L + arow + k * 32);
            uint32_t brow = (uint32_t)(lane & 15) * 144 + (uint32_t)(lane >> 4) * 16 + k * 32;
#pragma unroll
            for (int j = 0; j < 4; j++) {
                uint32_t kh0, kh1, kh2, kh3, kl0, kl1, kl2, kl3;
                ldsm4(kh0, kh1, kh2, kh3, smb + AKOF(stg) + brow + (uint32_t)j * 16 * 144);
                ldsm4(kl0, kl1, kl2, kl3, smb + AKOF(stg) + 9216 + brow + (uint32_t)j * 16 * 144);
                mma16816(Sfr[j*2],   ah0, ah1, ah2, ah3, kh0, kh2);
                mma16816(Sfr[j*2],   ah0, ah1, ah2, ah3, kl0, kl2);
                mma16816(Sfr[j*2],   al0, al1, al2, al3, kh0, kh2);
                mma16816(Sfr[j*2+1], ah0, ah1, ah2, ah3, kh1, kh3);
                mma16816(Sfr[j*2+1], ah0, ah1, ah2, ah3, kl1, kl3);
                mma16816(Sfr[j*2+1], al0, al1, al2, al3, kh1, kh3);
            }
        }
        float* sS = (float*)(sm + AS_OFF);
        {
            int r0 = wid * 16 + row_lo, r1 = wid * 16 + row_hi;
            int c0 = (lane & 3) * 2;
#pragma unroll
            for (int nf = 0; nf < 8; nf++) {
                sS[r0 * LDS_ + nf * 8 + c0]     = Sfr[nf][0] * 0.125f;
                sS[r0 * LDS_ + nf * 8 + c0 + 1] = Sfr[nf][1] * 0.125f;
                sS[r1 * LDS_ + nf * 8 + c0]     = Sfr[nf][2] * 0.125f;
                sS[r1 * LDS_ + nf * 8 + c0 + 1] = Sfr[nf][3] * 0.125f;
            }
        }
        __syncthreads();

        // ---- online softmax: 2 threads per row, causal mask by column compare ----
        {
            int row = tid >> 1, half = tid & 1;
            float* srow = (float*)(sm + AS_OFF) + row * LDS_ + half * 32;
            int qglob = qbase + row;
            int kbase = t * 64 + half * 32;
            float sv[32];
#pragma unroll
            for (int c = 0; c < 32; c++) {
                float s_ = srow[c];
                if (kbase + c > qglob) s_ = -1e30f;
                sv[c] = s_;
            }
            float tmax = -1e30f;
#pragma unroll
            for (int c = 0; c < 32; c++) tmax = fmaxf(tmax, sv[c]);
            tmax = fmaxf(tmax, __shfl_xor_sync(0xffffffffu, tmax, 1));
            float mo = s_m[row];
            float nm = fmaxf(mo, tmax);
            float corr = __expf(mo - nm);
            float sum = 0.f;
            uint32_t* ph = (uint32_t*)(sm + AP_H) + (row * LDT + half * 32) / 2;
            uint32_t* pl = (uint32_t*)(sm + AP_L) + (row * LDT + half * 32) / 2;
#pragma unroll
            for (int c = 0; c < 32; c += 2) {
                float p0 = __expf(sv[c] - nm);
                float p1 = __expf(sv[c + 1] - nm);
                sum += p0 + p1;
                uint32_t h, l; split2(p0, p1, h, l);
                ph[c >> 1] = h; pl[c >> 1] = l;
            }
            sum += __shfl_xor_sync(0xffffffffu, sum, 1);
            if (half == 0) {
                s_m[row] = nm;
                s_l[row] = s_l[row] * corr + sum;
                s_c[row] = corr;
            }
        }
        __syncthreads();

        // ---- rescale O, then O += P V (3-term split) ----
        {
            float c_lo = s_c[wid * 16 + row_lo];
            float c_hi = s_c[wid * 16 + row_hi];
#pragma unroll
            for (int nf = 0; nf < 8; nf++) {
                O[nf][0] *= c_lo; O[nf][1] *= c_lo;
                O[nf][2] *= c_hi; O[nf][3] *= c_hi;
            }
        }
#pragma unroll
        for (int k = 0; k < 4; k++) {
            uint32_t ph0, ph1, ph2, ph3, pl0, pl1, pl2, pl3;
            ldsm4(ph0, ph1, ph2, ph3, smb + AP_H + arow + k * 32);
            ldsm4(pl0, pl1, pl2, pl3, smb + AP_L + arow + k * 32);
            uint32_t vrow = (uint32_t)(k * 16 + (lane & 7) + ((lane >> 3) & 1) * 8) * 144
                          + (uint32_t)((lane >> 4) & 1) * 16;
#pragma unroll
            for (int j = 0; j < 4; j++) {
                uint32_t vh0, vh1, vh2, vh3, vl0, vl1, vl2, vl3;
                ldsm4t(vh0, vh1, vh2, vh3, smb + AVOF(stg) + vrow + (uint32_t)j * 32);
                ldsm4t(vl0, vl1, vl2, vl3, smb + AVOF(stg) + 9216 + vrow + (uint32_t)j * 32);
                mma16816(O[j*2],   ph0, ph1, ph2, ph3, vh0, vh1);
                mma16816(O[j*2],   ph0, ph1, ph2, ph3, vl0, vl1);
                mma16816(O[j*2],   pl0, pl1, pl2, pl3, vh0, vh1);
                mma16816(O[j*2+1], ph0, ph1, ph2, ph3, vh2, vh3);
                mma16816(O[j*2+1], ph0, ph1, ph2, ph3, vl2, vl3);
                mma16816(O[j*2+1], pl0, pl1, pl2, pl3, vh2, vh3);
            }
        }
        __syncthreads();
    }

    // ---- epilogue ----
    {
        int b = bh >> 4, h = bh & 15;
        float linv0 = 1.f / s_l[wid * 16 + row_lo];
        float linv1 = 1.f / s_l[wid * 16 + row_hi];
        int q0 = qbase + wid * 16 + row_lo;
        int q1 = qbase + wid * 16 + row_hi;
        size_t base0 = (size_t)(b * Ss + q0) * 1024 + h * 64;
        size_t base1 = (size_t)(b * Ss + q1) * 1024 + h * 64;
        int c0 = (lane & 3) * 2;
#pragma unroll
        for (int nf = 0; nf < 8; nf++) {
            int col = nf * 8 + c0;
            uint32_t hh, ll;
            split2(O[nf][0] * linv0, O[nf][1] * linv0, hh, ll);
            *(uint32_t*)&g_ctxh[base0 + col] = hh;
            *(uint32_t*)&g_ctxl[base0 + col] = ll;
            split2(O[nf][2] * linv1, O[nf][3] * linv1, hh, ll);
            *(uint32_t*)&g_ctxh[base1 + col] = hh;
            *(uint32_t*)&g_ctxl[base1 + col] = ll;
        }
    }
}

// ---------------- small kernels ----------------
__global__ void reset_kernel() {
    int t = threadIdx.x;
    if (t < Ee) { g_cnt[t] = 0; g_cur[t] = 0; }
}

__global__ void rmsnorm_kernel(const float* __restrict__ in,
                               const float* __restrict__ gamma,
                               float* __restrict__ out,
                               bf16* __restrict__ oh, bf16* __restrict__ ol) {
    int row = blockIdx.x;
    const float* p = in + row * Dd;
    float ss = 0.f;
    for (int d = threadIdx.x; d < Dd; d += blockDim.x) { float v = p[d]; ss += v * v; }
    for (int o = 16; o; o >>= 1) ss += __shfl_xor_sync(0xffffffffu, ss, o);
    __shared__ float red[8];
    int w = threadIdx.x >> 5;
    if ((threadIdx.x & 31) == 0) red[w] = ss;
    __syncthreads();
    if (threadIdx.x < 8) {
        float v = red[threadIdx.x];
        for (int o = 4; o; o >>= 1) v += __shfl_xor_sync(0xffu, v, o);
        if (threadIdx.x == 0) red[0] = v;
    }
    __syncthreads();
    float rinv = rsqrtf(red[0] * (1.0f / Dd) + EPSf);
    for (int d = threadIdx.x * 2; d < Dd; d += blockDim.x * 2) {
        float v0 = p[d] * rinv * gamma[d];
        float v1 = p[d + 1] * rinv * gamma[d + 1];
        out[row * Dd + d]     = v0;
        out[row * Dd + d + 1] = v1;
        uint32_t h, l; split2(v0, v1, h, l);
        *(uint32_t*)&oh[row * Dd + d] = h;
        *(uint32_t*)&ol[row * Dd + d] = l;
    }
}

__global__ void rope_kernel(const float* __restrict__ p, const float* __restrict__ theta,
                            bf16* __restrict__ oh, bf16* __restrict__ ol) {
    __shared__ float buf[8][64];
    int w = threadIdx.x >> 5;
    int v = blockIdx.x * 8 + w;
    int s = v & (Ss - 1);
    const float* basep = p + (size_t)v * HDh;
    int i = threadIdx.x & 31;
    float x1 = basep[2 * i], x2 = basep[2 * i + 1];
    float ang = (float)s * theta[i];
    float c = cosf(ang), sn = sinf(ang);
    buf[w][i]      = x1 * c - x2 * sn;
    buf[w][32 + i] = x1 * sn + x2 * c;
    __syncwarp();
    float v0 = buf[w][2 * i], v1 = buf[w][2 * i + 1];
    uint32_t h, l; split2(v0, v1, h, l);
    *(uint32_t*)&oh[(size_t)v * HDh + 2 * i] = h;
    *(uint32_t*)&ol[(size_t)v * HDh + 2 * i] = l;
}

__global__ void router_kernel(const float* __restrict__ an, const float* __restrict__ W,
                              const float* __restrict__ bias) {
    int tkn = blockIdx.x;
    __shared__ float xs[Dd];
    for (int d = threadIdx.x; d < Dd; d += 32) xs[d] = an[tkn * Dd + d];
    __syncwarp();
    int e = threadIdx.x;
    float logit = -1e30f;
    if (e < Ee) {
        float acc = bias[e];
        for (int d = 0; d < Dd; d++) acc += xs[d] * W[d * Ee + e];
        logit = acc;
    }
    float mx = logit;
    for (int o = 16; o; o >>= 1) mx = fmaxf(mx, __shfl_xor_sync(0xffffffffu, mx, o));
    float ex = (e < Ee) ? __expf(logit - mx) : 0.f;
    float sm = ex;
    for (int o = 16; o; o >>= 1) sm += __shfl_xor_sync(0xffffffffu, sm, o);
    float pw = ex / sm;
    for (int it = 0; it < 3; it++) {
        float bv = pw; int bi = e;
        for (int o = 16; o; o >>= 1) {
            float ov = __shfl_xor_sync(0xffffffffu, bv, o);
            int   oi = __shfl_xor_sync(0xffffffffu, bi, o);
            if (ov > bv || (ov == bv && oi < bi)) { bv = ov; bi = oi; }
        }
        if (threadIdx.x == 0) {
            g_topi[tkn * 3 + it] = bi;
            g_topv[tkn * 3 + it] = bv;
            atomicAdd(&g_cnt[bi], 1);
        }
        if (e == bi) pw = -1.f;
    }
}

__global__ void scan_kernel() {
    if (threadIdx.x == 0) {
        int s = 0;
        for (int e = 0; e < Ee; e++) { g_off[e] = s; s += g_cnt[e]; }
    }
}

__global__ void fill_kernel() {
    int i = blockIdx.x * 256 + threadIdx.x;
    if (i >= SLOTS) return;
    int tkn = i / 3, r = i - tkn * 3;
    int e = g_topi[i];
    int pos = atomicAdd(&g_cur[e], 1);
    int slot = g_off[e] + pos;
    g_slot_tok[slot] = tkn;
    g_slot_rank[slot] = r;
    g_slot_gate[slot] = g_topv[i];
}

__global__ void final_kernel(float* __restrict__ out) {
    int i = blockIdx.x * 256 + threadIdx.x;
    int t = i >> 10, n = i & 1023;
    float v = out[i];
    v += g_part[(size_t)(t * 3 + 0) * Dd + n];
    v += g_part[(size_t)(t * 3 + 1) * Dd + n];
    v += g_part[(size_t)(t * 3 + 2) * Dd + n];
    out[i] = v;
}

// ---------------- launch ----------------
extern "C" void kernel_launch(void* const* d_in, const int* in_sizes, int n_in,
                              void* d_out, int out_size) {
    const float* x      = (const float*)d_in[0];
    const float* theta  = (const float*)d_in[2];
    const float* gamma1 = (const float*)d_in[3];
    const float* gamma2 = (const float*)d_in[4];
    const float* q_w  = (const float*)d_in[5];  const float* q_b  = (const float*)d_in[6];
    const float* k_w  = (const float*)d_in[7];  const float* k_b  = (const float*)d_in[8];
    const float* v_w  = (const float*)d_in[9];  const float* v_b  = (const float*)d_in[10];
    const float* o_w  = (const float*)d_in[11]; const float* o_b  = (const float*)d_in[12];
    const float* r_w  = (const float*)d_in[13]; const float* r_b  = (const float*)d_in[14];
    const float* sw1  = (const float*)d_in[15]; const float* sb1  = (const float*)d_in[16];
    const float* sw2  = (const float*)d_in[17]; const float* sb2  = (const float*)d_in[18];
    const float* rw1  = (const float*)d_in[19]; const float* rb1  = (const float*)d_in[20];
    const float* rw2  = (const float*)d_in[21]; const float* rb2  = (const float*)d_in[22];
    float* out = (float*)d_out;

    float *xn, *qb, *kb, *attn, *an;
    bf16 *xnh, *xnl, *anh, *anl, *t1h, *t1l, *ctxh, *ctxl, *qsh, *qsl, *ksh, *ksl;
    bf16 *qwh, *qwl, *kwh, *kwl, *vwh, *vwl, *owh, *owl, *s1h, *s1l, *s2h, *s2l;
    bf16 *r1h, *r1l, *r2h, *r2l;
    cudaGetSymbolAddress((void**)&xn,   g_xn);
    cudaGetSymbolAddress((void**)&qb,   g_qb);
    cudaGetSymbolAddress((void**)&kb,   g_kb);
    cudaGetSymbolAddress((void**)&attn, g_attn);
    cudaGetSymbolAddress((void**)&an,   g_an);
    cudaGetSymbolAddress((void**)&xnh,  g_xnh);  cudaGetSymbolAddress((void**)&xnl, g_xnl);
    cudaGetSymbolAddress((void**)&ctxh, g_ctxh); cudaGetSymbolAddress((void**)&ctxl, g_ctxl);
    cudaGetSymbolAddress((void**)&anh,  g_anh);  cudaGetSymbolAddress((void**)&anl, g_anl);
    cudaGetSymbolAddress((void**)&t1h,  g_t1h);  cudaGetSymbolAddress((void**)&t1l, g_t1l);
    cudaGetSymbolAddress((void**)&qsh,  g_qsh);  cudaGetSymbolAddress((void**)&qsl, g_qsl);
    cudaGetSymbolAddress((void**)&ksh,  g_ksh);  cudaGetSymbolAddress((void**)&ksl, g_ksl);
    cudaGetSymbolAddress((void**)&qwh,  g_qwh);  cudaGetSymbolAddress((void**)&qwl, g_qwl);
    cudaGetSymbolAddress((void**)&kwh,  g_kwh);  cudaGetSymbolAddress((void**)&kwl, g_kwl);
    cudaGetSymbolAddress((void**)&vwh,  g_vwh);  cudaGetSymbolAddress((void**)&vwl, g_vwl);
    cudaGetSymbolAddress((void**)&owh,  g_owh);  cudaGetSymbolAddress((void**)&owl, g_owl);
    cudaGetSymbolAddress((void**)&s1h,  g_s1h);  cudaGetSymbolAddress((void**)&s1l, g_s1l);
    cudaGetSymbolAddress((void**)&s2h,  g_s2h);  cudaGetSymbolAddress((void**)&s2l, g_s2l);
    cudaGetSymbolAddress((void**)&r1h,  g_r1h);  cudaGetSymbolAddress((void**)&r1l, g_r1l);
    cudaGetSymbolAddress((void**)&r2h,  g_r2h);  cudaGetSymbolAddress((void**)&r2l, g_r2l);

    cudaFuncSetAttribute(wm_gemm_kernel,   cudaFuncAttributeMaxDynamicSharedMemorySize, DYN_SMEM);
    cudaFuncSetAttribute(wm_qkv_kernel,    cudaFuncAttributeMaxDynamicSharedMemorySize, DYN_SMEM);
    cudaFuncSetAttribute(wm_egemm1_kernel, cudaFuncAttributeMaxDynamicSharedMemorySize, DYN_SMEM);
    cudaFuncSetAttribute(wm_egemm2_kernel, cudaFuncAttributeMaxDynamicSharedMemorySize, DYN_SMEM);
    cudaFuncSetAttribute(attn2_kernel,     cudaFuncAttributeMaxDynamicSharedMemorySize, ATTN_SMEM);

    dim3 thr(256);
    dim3 grid8x16(8, 16);

    // launches 0-4, so that launch #5 (ncu -s 5 -c 1) is wm_qkv_kernel
    convw6_kernel<<<dim3(D4 / 1024, 6), 256>>>(
        (const float4*)q_w, (const float4*)k_w, (const float4*)v_w,
        (const float4*)o_w, (const float4*)sw1, (const float4*)sw2,
        (uint2*)qwh, (uint2*)kwh, (uint2*)vwh, (uint2*)owh, (uint2*)s1h, (uint2*)s2h,
        (uint2*)qwl, (uint2*)kwl, (uint2*)vwl, (uint2*)owl, (uint2*)s1l, (uint2*)s2l);
    convw_kernel<<<(E4 + 1023) / 1024, 256>>>((const float4*)rw1, (uint2*)r1h, (uint2*)r1l, E4);
    convw_kernel<<<(E4 + 1023) / 1024, 256>>>((const float4*)rw2, (uint2*)r2h, (uint2*)r2l, E4);
    reset_kernel<<<1, 32>>>();
    rmsnorm_kernel<<<NT, 256>>>(x, gamma1, xn, xnh, xnl);

    wm_qkv_kernel<<<dim3(8, 16, 3), thr, DYN_SMEM>>>(q_b, k_b, v_b);   // launch #5

    rope_kernel<<<Bb * Hh * Ss / 8, 256>>>(qb, theta, qsh, qsl);
    rope_kernel<<<Bb * Hh * Ss / 8, 256>>>(kb, theta, ksh, ksl);

    attn2_kernel<<<dim3(8, Bb * Hh), 256, ATTN_SMEM>>>();

    wm_gemm_kernel<<<grid8x16, thr, DYN_SMEM>>>(ctxh, ctxl, owh, owl, o_b, 2, xn, nullptr,
                                                attn, nullptr, nullptr);
    rmsnorm_kernel<<<NT, 256>>>(attn, gamma2, an, anh, anl);

    wm_gemm_kernel<<<grid8x16, thr, DYN_SMEM>>>(anh, anl, s1h, s1l, sb1, 1, nullptr, nullptr,
                                                nullptr, t1h, t1l);
    wm_gemm_kernel<<<grid8x16, thr, DYN_SMEM>>>(t1h, t1l, s2h, s2l, sb2, 2, an, attn,
                                                out, nullptr, nullptr);

    router_kernel<<<NT, 32>>>(an, r_w, r_b);
    scan_kernel<<<1, 32>>>();
    fill_kernel<<<(SLOTS + 255) / 256, 256>>>();

    wm_egemm1_kernel<<<dim3(8, 16, Ee), thr, DYN_SMEM>>>(rb1);
    wm_egemm2_kernel<<<dim3(8, 16, Ee), thr, DYN_SMEM>>>(rb2);

    final_kernel<<<(NT * Dd) / 256, 256>>>(out);
}

// round 12
// speedup vs baseline: 2.6810x; 1.1246x over previous
#include <cuda_runtime.h>
#include <cuda_bf16.h>
#include <cuda_pipeline.h>
#include <mma.h>
#include <cstdint>

using namespace nvcuda;

#define Bb     2
#define Ss     1024
#define Dd     1024
#define Hh     16
#define HDh    64
#define NT     (Bb*Ss)
#define Ee     31
#define INTERi 1024
#define EPSf   1e-5f
#define SLOTS  (NT*3)

typedef __nv_bfloat16 bf16;

// ---------------- fp32 scratch ----------------
__device__ float g_xn  [NT*Dd];
__device__ float g_qb  [NT*Dd];
__device__ float g_kb  [NT*Dd];
__device__ float g_attn[NT*Dd];
__device__ float g_an  [NT*Dd];
__device__ float g_part[SLOTS*Dd];
__device__ int   g_topi[SLOTS];
__device__ float g_topv[SLOTS];
__device__ int   g_cnt[Ee];
__device__ int   g_off[Ee];
__device__ int   g_cur[Ee];
__device__ int   g_slot_tok [SLOTS];
__device__ int   g_slot_rank[SLOTS];
__device__ float g_slot_gate[SLOTS];

// ---------------- bf16 hi/lo activations ----------------
__device__ bf16 g_xnh[NT*Dd],  g_xnl[NT*Dd];
__device__ bf16 g_qsh[NT*Dd],  g_qsl[NT*Dd];
__device__ bf16 g_ksh[NT*Dd],  g_ksl[NT*Dd];
__device__ bf16 g_vsh[NT*Dd],  g_vsl[NT*Dd];
__device__ bf16 g_ctxh[NT*Dd], g_ctxl[NT*Dd];
__device__ bf16 g_anh[NT*Dd],  g_anl[NT*Dd];
__device__ bf16 g_t1h[NT*INTERi], g_t1l[NT*INTERi];
__device__ bf16 g_hh[SLOTS*INTERi], g_hl[SLOTS*INTERi];

// ---------------- bf16 hi/lo weights ----------------
__device__ bf16 g_qwh[Dd*Dd], g_qwl[Dd*Dd];
__device__ bf16 g_kwh[Dd*Dd], g_kwl[Dd*Dd];
__device__ bf16 g_vwh[Dd*Dd], g_vwl[Dd*Dd];
__device__ bf16 g_owh[Dd*Dd], g_owl[Dd*Dd];
__device__ bf16 g_s1h[Dd*INTERi], g_s1l[Dd*INTERi];
__device__ bf16 g_s2h[INTERi*Dd], g_s2l[INTERi*Dd];
__device__ bf16 g_r1h[Ee*Dd*INTERi], g_r1l[Ee*Dd*INTERi];
__device__ bf16 g_r2h[Ee*INTERi*Dd], g_r2l[Ee*INTERi*Dd];

__device__ __forceinline__ float gelu_f(float v) {
    return 0.5f * v * (1.0f + erff(v * 0.70710678118654752f));
}

__device__ __forceinline__ void split2(float x, float y, uint32_t& hi, uint32_t& lo) {
    bf16 hx = __float2bfloat16(x), hy = __float2bfloat16(y);
    bf16 lx = __float2bfloat16(x - __bfloat162float(hx));
    bf16 ly = __float2bfloat16(y - __bfloat162float(hy));
    __nv_bfloat162 H = __halves2bfloat162(hx, hy);
    __nv_bfloat162 L = __halves2bfloat162(lx, ly);
    hi = *(uint32_t*)&H; lo = *(uint32_t*)&L;
}

__device__ __forceinline__ uint32_t s2u(const void* p) {
    uint32_t a;
    asm("{ .reg .u64 t; cvta.to.shared.u64 t, %1; cvt.u32.u64 %0, t; }" : "=r"(a) : "l"(p));
    return a;
}

// ---------------- raw mma/ldmatrix helpers ----------------
__device__ __forceinline__ void ldsm4(uint32_t& r0, uint32_t& r1, uint32_t& r2, uint32_t& r3, uint32_t addr) {
    asm volatile("ldmatrix.sync.aligned.m8n8.x4.shared.b16 {%0,%1,%2,%3}, [%4];"
        : "=r"(r0), "=r"(r1), "=r"(r2), "=r"(r3) : "r"(addr));
}
__device__ __forceinline__ void ldsm4t(uint32_t& r0, uint32_t& r1, uint32_t& r2, uint32_t& r3, uint32_t addr) {
    asm volatile("ldmatrix.sync.aligned.m8n8.x4.trans.shared.b16 {%0,%1,%2,%3}, [%4];"
        : "=r"(r0), "=r"(r1), "=r"(r2), "=r"(r3) : "r"(addr));
}
__device__ __forceinline__ void mma16816(float* c, uint32_t a0, uint32_t a1, uint32_t a2, uint32_t a3,
                                         uint32_t b0, uint32_t b1) {
    asm volatile("mma.sync.aligned.m16n8k16.row.col.f32.bf16.bf16.f32 "
        "{%0,%1,%2,%3},{%4,%5,%6,%7},{%8,%9},{%0,%1,%2,%3};"
        : "+f"(c[0]), "+f"(c[1]), "+f"(c[2]), "+f"(c[3])
        : "r"(a0), "r"(a1), "r"(a2), "r"(a3), "r"(b0), "r"(b1));
}

// ---------------- weight conversion ----------------
#define D4 (Dd*Dd/4)
#define E4 (Ee*Dd*INTERi/4)

__global__ void convw_kernel(const float4* __restrict__ src,
                             uint2* __restrict__ h, uint2* __restrict__ l, int n4) {
    int base = blockIdx.x * 1024 + threadIdx.x;
    float4 v[4]; int idx[4]; bool ok[4];
#pragma unroll
    for (int j = 0; j < 4; j++) {
        idx[j] = base + j * 256;
        ok[j] = idx[j] < n4;
        if (ok[j]) v[j] = src[idx[j]];
    }
#pragma unroll
    for (int j = 0; j < 4; j++) {
        if (!ok[j]) continue;
        uint32_t h0, l0, h1, l1;
        split2(v[j].x, v[j].y, h0, l0);
        split2(v[j].z, v[j].w, h1, l1);
        h[idx[j]] = make_uint2(h0, h1);
        l[idx[j]] = make_uint2(l0, l1);
    }
}

__global__ void convw6_kernel(
    const float4* s0, const float4* s1, const float4* s2,
    const float4* s3, const float4* s4, const float4* s5,
    uint2* h0, uint2* h1, uint2* h2, uint2* h3, uint2* h4, uint2* h5,
    uint2* l0, uint2* l1, uint2* l2, uint2* l3, uint2* l4, uint2* l5)
{
    const float4* srcs[6] = {s0, s1, s2, s3, s4, s5};
    uint2* hs[6] = {h0, h1, h2, h3, h4, h5};
    uint2* ls[6] = {l0, l1, l2, l3, l4, l5};
    int w = blockIdx.y;
    const float4* src = srcs[w];
    uint2* h = hs[w];
    uint2* l = ls[w];
    int base = blockIdx.x * 1024 + threadIdx.x;
    float4 v[4];
#pragma unroll
    for (int j = 0; j < 4; j++) v[j] = src[base + j * 256];
#pragma unroll
    for (int j = 0; j < 4; j++) {
        uint32_t a0, b0, a1, b1;
        split2(v[j].x, v[j].y, a0, b0);
        split2(v[j].z, v[j].w, a1, b1);
        h[base + j * 256] = make_uint2(a0, a1);
        l[base + j * 256] = make_uint2(b0, b1);
    }
}

// ================= wmma bf16 split GEMM core =================
typedef wmma::fragment<wmma::accumulator, 16, 16, 16, float> FragC;
typedef wmma::fragment<wmma::matrix_a, 16, 16, 16, bf16, wmma::row_major> FragA;
typedef wmma::fragment<wmma::matrix_b, 16, 16, 16, bf16, wmma::row_major> FragB;

#define LDA 40
#define LDB 136
#define LDC 132
#define OFF_AH 0
#define OFF_AL 10240
#define OFF_BH 20480
#define OFF_BL 29184
#define STAGE  37888
#define DYN_SMEM (2*STAGE)

__device__ __forceinline__ void stage_fill(
    const bf16* __restrict__ Ahg, const bf16* __restrict__ Alg,
    const bf16* __restrict__ Bhg, const bf16* __restrict__ Blg,
    int nb, int k0, const int* rowmap, char* st, int tid)
{
#pragma unroll
    for (int i = 0; i < 2; i++) {
        int s = tid + i * 256;
        int row = s >> 2, q = s & 3;
        int r = rowmap[row];
        char* dh = st + OFF_AH + row * (LDA * 2) + q * 16;
        char* dl = st + OFF_AL + row * (LDA * 2) + q * 16;
        if (r >= 0) {
            __pipeline_memcpy_async(dh, Ahg + (size_t)r * 1024 + k0 + q * 8, 16);
            __pipeline_memcpy_async(dl, Alg + (size_t)r * 1024 + k0 + q * 8, 16);
        } else {
            *(uint4*)dh = make_uint4(0u, 0u, 0u, 0u);
            *(uint4*)dl = make_uint4(0u, 0u, 0u, 0u);
        }
    }
#pragma unroll
    for (int i = 0; i < 2; i++) {
        int s = tid + i * 256;
        int k = s >> 4, q = s & 15;
        char* dh = st + OFF_BH + k * (LDB * 2) + q * 16;
        char* dl = st + OFF_BL + k * (LDB * 2) + q * 16;
        __pipeline_memcpy_async(dh, Bhg + (size_t)(k0 + k) * 1024 + nb + q * 8, 16);
        __pipeline_memcpy_async(dl, Blg + (size_t)(k0 + k) * 1024 + nb + q * 8, 16);
    }
}

__device__ __forceinline__ void wm_mainloop(
    const bf16* __restrict__ Ahg, const bf16* __restrict__ Alg,
    const bf16* __restrict__ Bhg, const bf16* __restrict__ Blg,
    int nb, const int* rowmap, char* sm, FragC accs[4][2])
{
    int tid = threadIdx.x, wid = tid >> 5;
    int wm = wid & 1, wn = wid >> 1;
#pragma unroll
    for (int mt = 0; mt < 4; mt++)
#pragma unroll
        for (int nt = 0; nt < 2; nt++)
            wmma::fill_fragment(accs[mt][nt], 0.0f);

    stage_fill(Ahg, Alg, Bhg, Blg, nb, 0, rowmap, sm, tid);
    __pipeline_commit();

    for (int t = 0; t < 32; t++) {
        char* cur = sm + (t & 1) * STAGE;
        if (t < 31) {
            stage_fill(Ahg, Alg, Bhg, Blg, nb, (t + 1) * 32, rowmap,
                       sm + ((t + 1) & 1) * STAGE, tid);
            __pipeline_commit();
            __pipeline_wait_prior(1);
        } else {
            __pipeline_wait_prior(0);
        }
        __syncthreads();
        const bf16* Ah = (const bf16*)(cur + OFF_AH);
        const bf16* Al = (const bf16*)(cur + OFF_AL);
        const bf16* Bh = (const bf16*)(cur + OFF_BH);
        const bf16* Bl = (const bf16*)(cur + OFF_BL);
#pragma unroll
        for (int ks = 0; ks < 2; ks++) {
            FragB bh0, bh1, bl0, bl1;
            const bf16* bbase = Bh + (ks * 16) * LDB + wn * 32;
            const bf16* bbasl = Bl + (ks * 16) * LDB + wn * 32;
            wmma::load_matrix_sync(bh0, bbase,      LDB);
            wmma::load_matrix_sync(bh1, bbase + 16, LDB);
            wmma::load_matrix_sync(bl0, bbasl,      LDB);
            wmma::load_matrix_sync(bl1, bbasl + 16, LDB);
#pragma unroll
            for (int mt = 0; mt < 4; mt++) {
                FragA ah, al;
                wmma::load_matrix_sync(ah, Ah + (wm * 64 + mt * 16) * LDA + ks * 16, LDA);
                wmma::load_matrix_sync(al, Al + (wm * 64 + mt * 16) * LDA + ks * 16, LDA);
                wmma::mma_sync(accs[mt][0], ah, bh0, accs[mt][0]);
                wmma::mma_sync(accs[mt][0], ah, bl0, accs[mt][0]);
                wmma::mma_sync(accs[mt][0], al, bh0, accs[mt][0]);
                wmma::mma_sync(accs[mt][1], ah, bh1, accs[mt][1]);
                wmma::mma_sync(accs[mt][1], ah, bl1, accs[mt][1]);
                wmma::mma_sync(accs[mt][1], al, bh1, accs[mt][1]);
            }
        }
        __syncthreads();
    }
    float* Cs = (float*)sm;
#pragma unroll
    for (int mt = 0; mt < 4; mt++)
#pragma unroll
        for (int nt = 0; nt < 2; nt++)
            wmma::store_matrix_sync(Cs + (wm * 64 + mt * 16) * LDC + wn * 32 + nt * 16,
                                    accs[mt][nt], LDC, wmma::mem_row_major);
    __syncthreads();
}

#define WM_PROLOGUE(ROWEXPR)                                                   \
    extern __shared__ __align__(16) char dynsm[];                              \
    __shared__ int s_rowmap[128];                                              \
    int tid = threadIdx.x;                                                     \
    if (tid < 128) s_rowmap[tid] = (ROWEXPR);                                  \
    __syncthreads();                                                           \
    FragC accs[4][2];

#define EPI_VARS                                                               \
    float* Cs = (float*)dynsm;                                                 \
    int em = tid >> 1;                                                         \
    int en = (tid & 1) * 64;                                                   \
    const float* crow = Cs + em * LDC + en;

__global__ __launch_bounds__(256, 2) void wm_gemm_kernel(
    const bf16* __restrict__ Ahg, const bf16* __restrict__ Alg,
    const bf16* __restrict__ Bhg, const bf16* __restrict__ Blg,
    const float* __restrict__ bias, int mode,
    const float* __restrict__ res1, const float* __restrict__ res2,
    float* __restrict__ Cf, bf16* __restrict__ Ch, bf16* __restrict__ Cl)
{
    int mb = blockIdx.y * 128, nb = blockIdx.x * 128;
    WM_PROLOGUE(mb + tid)
    wm_mainloop(Ahg, Alg, Bhg, Blg, nb, s_rowmap, dynsm, accs);
    EPI_VARS
    int m = mb + em;
    if (mode == 1) {
        uint32_t* oh = (uint32_t*)(Ch + (size_t)m * 1024 + nb + en);
        uint32_t* ol = (uint32_t*)(Cl + (size_t)m * 1024 + nb + en);
#pragma unroll
        for (int j = 0; j < 64; j += 2) {
            int n = nb + en + j;
            float v0 = gelu_f(crow[j]     + bias[n]);
            float v1 = gelu_f(crow[j + 1] + bias[n + 1]);
            uint32_t h, l; split2(v0, v1, h, l);
            oh[j >> 1] = h; ol[j >> 1] = l;
        }
    } else {
        float* orow = Cf + (size_t)m * 1024 + nb + en;
#pragma unroll
        for (int j = 0; j < 64; j += 4) {
            int n = nb + en + j;
            float4 v;
            v.x = crow[j+0] + bias[n+0];
            v.y = crow[j+1] + bias[n+1];
            v.z = crow[j+2] + bias[n+2];
            v.w = crow[j+3] + bias[n+3];
            if (mode == 2) {
                float4 r = *(const float4*)(res1 + (size_t)m * 1024 + n);
                v.x += r.x; v.y += r.y; v.z += r.z; v.w += r.w;
                if (res2) {
                    float4 r2 = *(const float4*)(res2 + (size_t)m * 1024 + n);
                    v.x += r2.x; v.y += r2.y; v.z += r2.z; v.w += r2.w;
                }
            }
            *(float4*)(orow + j) = v;
        }
    }
}

__global__ __launch_bounds__(256, 2) void wm_qkv_kernel(
    const float* __restrict__ qbias, const float* __restrict__ kbias,
    const float* __restrict__ vbias)
{
    const bf16 *Bh_, *Bl_; const float* bias;
    if (blockIdx.z == 0)      { Bh_ = g_qwh; Bl_ = g_qwl; bias = qbias; }
    else if (blockIdx.z == 1) { Bh_ = g_kwh; Bl_ = g_kwl; bias = kbias; }
    else                      { Bh_ = g_vwh; Bl_ = g_vwl; bias = vbias; }
    int mb = blockIdx.y * 128, nb = blockIdx.x * 128;
    WM_PROLOGUE(mb + tid)
    wm_mainloop(g_xnh, g_xnl, Bh_, Bl_, nb, s_rowmap, dynsm, accs);
    EPI_VARS
    int m = mb + em;
    int b = m >> 10, s = m & 1023;
    float* C = (blockIdx.z == 0) ? g_qb : g_kb;
#pragma unroll
    for (int j = 0; j < 64; j += 4) {
        int n = nb + en + j;
        int h = n >> 6, hd = n & 63;
        size_t addr = (size_t)(((b * Hh + h) * Ss + s)) * 64 + hd;
        float4 v;
        v.x = crow[j+0] + bias[n+0];
        v.y = crow[j+1] + bias[n+1];
        v.z = crow[j+2] + bias[n+2];
        v.w = crow[j+3] + bias[n+3];
        if (blockIdx.z == 2) {
            uint32_t h0, l0, h1, l1;
            split2(v.x, v.y, h0, l0);
            split2(v.z, v.w, h1, l1);
            *(uint2*)&g_vsh[addr] = make_uint2(h0, h1);
            *(uint2*)&g_vsl[addr] = make_uint2(l0, l1);
        } else {
            *(float4*)&C[addr] = v;
        }
    }
}

__global__ __launch_bounds__(256, 2) void wm_egemm1_kernel(const float* __restrict__ re_b1)
{
    int e = blockIdx.z;
    int cnt = g_cnt[e];
    int mb = blockIdx.y * 128;
    if (mb >= cnt) return;
    int off = g_off[e];
    int nb = blockIdx.x * 128;
    WM_PROLOGUE((mb + tid < cnt) ? g_slot_tok[off + mb + tid] : -1)
    wm_mainloop(g_anh, g_anl,
                g_r1h + (size_t)e * (Dd * INTERi), g_r1l + (size_t)e * (Dd * INTERi),
                nb, s_rowmap, dynsm, accs);
    const float* bias = re_b1 + e * INTERi;
    EPI_VARS
    int row = mb + em;
    if (row < cnt) {
        uint32_t* oh = (uint32_t*)(g_hh + (size_t)(off + row) * INTERi + nb + en);
        uint32_t* ol = (uint32_t*)(g_hl + (size_t)(off + row) * INTERi + nb + en);
#pragma unroll
        for (int j = 0; j < 64; j += 2) {
            int n = nb + en + j;
            float v0 = gelu_f(crow[j]     + bias[n]);
            float v1 = gelu_f(crow[j + 1] + bias[n + 1]);
            uint32_t h, l; split2(v0, v1, h, l);
            oh[j >> 1] = h; ol[j >> 1] = l;
        }
    }
}

__global__ __launch_bounds__(256, 2) void wm_egemm2_kernel(const float* __restrict__ re_b2)
{
    int e = blockIdx.z;
    int cnt = g_cnt[e];
    int mb = blockIdx.y * 128;
    if (mb >= cnt) return;
    int off = g_off[e];
    int nb = blockIdx.x * 128;
    WM_PROLOGUE((mb + tid < cnt) ? (off + mb + tid) : -1)
    wm_mainloop(g_hh, g_hl,
                g_r2h + (size_t)e * (INTERi * Dd), g_r2l + (size_t)e * (INTERi * Dd),
                nb, s_rowmap, dynsm, accs);
    const float* bias = re_b2 + e * Dd;
    EPI_VARS
    int row = mb + em;
    if (row < cnt) {
        int slot = off + row;
        int tok = g_slot_tok[slot];
        int rnk = g_slot_rank[slot];
        float gate = g_slot_gate[slot];
        float* outp = g_part + (size_t)(tok * 3 + rnk) * Dd + nb + en;
#pragma unroll
        for (int j = 0; j < 64; j += 4) {
            int n = nb + en + j;
            float4 v;
            v.x = gate * (crow[j+0] + bias[n+0]);
            v.y = gate * (crow[j+1] + bias[n+1]);
            v.z = gate * (crow[j+2] + bias[n+2]);
            v.w = gate * (crow[j+3] + bias[n+3]);
            *(float4*)(outp + j) = v;
        }
    }
}

// ================= tensor-core flash attention =================
#define LDT 72
#define LDS_ 68
#define AQ_H 0
#define AQ_L 18432
#define AKOF(s)  (36864 + (s)*36864)
#define AVOF(s)  (AKOF(s) + 18432)
#define AS_OFF 110592
#define AP_H   145408
#define AP_L   163840
#define AM_OFF 182272
#define AL_OFF 182784
#define AC_OFF 183296
#define ATTN_SMEM 183808

__device__ __forceinline__ void attn_fill_kv(char* sm, int s, int grow, int tid) {
    const bf16* srcs[4] = {g_ksh, g_ksl, g_vsh, g_vsl};
    uint32_t dsts[4] = {(uint32_t)AKOF(s), (uint32_t)(AKOF(s) + 9216),
                        (uint32_t)AVOF(s), (uint32_t)(AVOF(s) + 9216)};
#pragma unroll
    for (int j = 0; j < 8; j++) {
        int id = tid + j * 256;
        int sel = id >> 9, rc = id & 511;
        int row = rc >> 3, cq = rc & 7;
        __pipeline_memcpy_async(sm + dsts[sel] + row * 144 + cq * 16,
                                srcs[sel] + (size_t)(grow + row) * 64 + cq * 8, 16);
    }
}

__global__ __launch_bounds__(256) void attn2_kernel() {
    extern __shared__ __align__(16) char sm[];
    int tid = threadIdx.x, wid = tid >> 5, lane = tid & 31;
    int bh = blockIdx.y;
    int qbase = (int)(gridDim.x - 1 - blockIdx.x) * 128;
    int qrow0 = bh * Ss + qbase;
    uint32_t smb = s2u(sm);

#pragma unroll
    for (int j = 0; j < 8; j++) {
        int id = tid + j * 256;
        int sel = id >> 10, rc = id & 1023;
        int row = rc >> 3, cq = rc & 7;
        const bf16* src = sel ? g_qsl : g_qsh;
        __pipeline_memcpy_async(sm + (sel ? AQ_L : AQ_H) + row * 144 + cq * 16,
                                src + (size_t)(qrow0 + row) * 64 + cq * 8, 16);
    }
    attn_fill_kv(sm, 0, bh * Ss, tid);
    __pipeline_commit();

    float* s_m = (float*)(sm + AM_OFF);
    float* s_l = (float*)(sm + AL_OFF);
    float* s_c = (float*)(sm + AC_OFF);
    if (tid < 128) { s_m[tid] = -1e30f; s_l[tid] = 0.f; }

    float O[8][4];
#pragma unroll
    for (int i = 0; i < 8; i++)
#pragma unroll
        for (int j = 0; j < 4; j++) O[i][j] = 0.f;

    int ntiles = qbase / 64 + 2;
    int row_lo = lane >> 2, row_hi = row_lo + 8;

    for (int t = 0; t < ntiles; t++) {
        int stg = t & 1;
        if (t + 1 < ntiles) {
            attn_fill_kv(sm, (t + 1) & 1, bh * Ss + (t + 1) * 64, tid);
            __pipeline_commit();
            __pipeline_wait_prior(1);
        } else {
            __pipeline_wait_prior(0);
        }
        __syncthreads();

        float Sfr[8][4];
#pragma unroll
        for (int i = 0; i < 8; i++)
#pragma unroll
            for (int j = 0; j < 4; j++) Sfr[i][j] = 0.f;
        uint32_t arow = (uint32_t)(wid * 16 + (lane & 15)) * 144 + (uint32_t)(lane >> 4) * 16;
#pragma unroll
        for (int k = 0; k < 4; k++) {
            uint32_t ah0, ah1, ah2, ah3, al0, al1, al2, al3;
            ldsm4(ah0, ah1, ah2, ah3, smb + AQ_H + arow + k * 32);
            ldsm4(al0, al1, al2, al3, smb + AQ_L + arow + k * 32);
            uint32_t brow = (uint32_t)(lane & 15) * 144 + (uint32_t)(lane >> 4) * 16 + k * 32;
#pragma unroll
            for (int j = 0; j < 4; j++) {
                uint32_t kh0, kh1, kh2, kh3, kl0, kl1, kl2, kl3;
                ldsm4(kh0, kh1, kh2, kh3, smb + AKOF(stg) + brow + (uint32_t)j * 16 * 144);
                ldsm4(kl0, kl1, kl2, kl3, smb + AKOF(stg) + 9216 + brow + (uint32_t)j * 16 * 144);
                mma16816(Sfr[j*2],   ah0, ah1, ah2, ah3, kh0, kh2);
                mma16816(Sfr[j*2],   ah0, ah1, ah2, ah3, kl0, kl2);
                mma16816(Sfr[j*2],   al0, al1, al2, al3, kh0, kh2);
                mma16816(Sfr[j*2+1], ah0, ah1, ah2, ah3, kh1, kh3);
                mma16816(Sfr[j*2+1], ah0, ah1, ah2, ah3, kl1, kl3);
                mma16816(Sfr[j*2+1], al0, al1, al2, al3, kh1, kh3);
            }
        }
        float* sS = (float*)(sm + AS_OFF);
        {
            int r0 = wid * 16 + row_lo, r1 = wid * 16 + row_hi;
            int c0 = (lane & 3) * 2;
#pragma unroll
            for (int nf = 0; nf < 8; nf++) {
                sS[r0 * LDS_ + nf * 8 + c0]     = Sfr[nf][0] * 0.125f;
                sS[r0 * LDS_ + nf * 8 + c0 + 1] = Sfr[nf][1] * 0.125f;
                sS[r1 * LDS_ + nf * 8 + c0]     = Sfr[nf][2] * 0.125f;
                sS[r1 * LDS_ + nf * 8 + c0 + 1] = Sfr[nf][3] * 0.125f;
            }
        }
        __syncthreads();

        {
            int row = tid >> 1, half = tid & 1;
            float* srow = (float*)(sm + AS_OFF) + row * LDS_ + half * 32;
            int qglob = qbase + row;
            int kbase = t * 64 + half * 32;
            float sv[32];
#pragma unroll
            for (int c = 0; c < 32; c++) {
                float s_ = srow[c];
                if (kbase + c > qglob) s_ = -1e30f;
                sv[c] = s_;
            }
            float tmax = -1e30f;
#pragma unroll
            for (int c = 0; c < 32; c++) tmax = fmaxf(tmax, sv[c]);
            tmax = fmaxf(tmax, __shfl_xor_sync(0xffffffffu, tmax, 1));
            float mo = s_m[row];
            float nm = fmaxf(mo, tmax);
            float corr = __expf(mo - nm);
            float sum = 0.f;
            uint32_t* ph = (uint32_t*)(sm + AP_H) + (row * LDT + half * 32) / 2;
            uint32_t* pl = (uint32_t*)(sm + AP_L) + (row * LDT + half * 32) / 2;
#pragma unroll
            for (int c = 0; c < 32; c += 2) {
                float p0 = __expf(sv[c] - nm);
                float p1 = __expf(sv[c + 1] - nm);
                sum += p0 + p1;
                uint32_t h, l; split2(p0, p1, h, l);
                ph[c >> 1] = h; pl[c >> 1] = l;
            }
            sum += __shfl_xor_sync(0xffffffffu, sum, 1);
            if (half == 0) {
                s_m[row] = nm;
                s_l[row] = s_l[row] * corr + sum;
                s_c[row] = corr;
            }
        }
        __syncthreads();

        {
            float c_lo = s_c[wid * 16 + row_lo];
            float c_hi = s_c[wid * 16 + row_hi];
#pragma unroll
            for (int nf = 0; nf < 8; nf++) {
                O[nf][0] *= c_lo; O[nf][1] *= c_lo;
                O[nf][2] *= c_hi; O[nf][3] *= c_hi;
            }
        }
#pragma unroll
        for (int k = 0; k < 4; k++) {
            uint32_t ph0, ph1, ph2, ph3, pl0, pl1, pl2, pl3;
            ldsm4(ph0, ph1, ph2, ph3, smb + AP_H + arow + k * 32);
            ldsm4(pl0, pl1, pl2, pl3, smb + AP_L + arow + k * 32);
            uint32_t vrow = (uint32_t)(k * 16 + (lane & 7) + ((lane >> 3) & 1) * 8) * 144
                          + (uint32_t)((lane >> 4) & 1) * 16;
#pragma unroll
            for (int j = 0; j < 4; j++) {
                uint32_t vh0, vh1, vh2, vh3, vl0, vl1, vl2, vl3;
                ldsm4t(vh0, vh1, vh2, vh3, smb + AVOF(stg) + vrow + (uint32_t)j * 32);
                ldsm4t(vl0, vl1, vl2, vl3, smb + AVOF(stg) + 9216 + vrow + (uint32_t)j * 32);
                mma16816(O[j*2],   ph0, ph1, ph2, ph3, vh0, vh1);
                mma16816(O[j*2],   ph0, ph1, ph2, ph3, vl0, vl1);
                mma16816(O[j*2],   pl0, pl1, pl2, pl3, vh0, vh1);
                mma16816(O[j*2+1], ph0, ph1, ph2, ph3, vh2, vh3);
                mma16816(O[j*2+1], ph0, ph1, ph2, ph3, vl2, vl3);
                mma16816(O[j*2+1], pl0, pl1, pl2, pl3, vh2, vh3);
            }
        }
        __syncthreads();
    }

    {
        int b = bh >> 4, h = bh & 15;
        float linv0 = 1.f / s_l[wid * 16 + row_lo];
        float linv1 = 1.f / s_l[wid * 16 + row_hi];
        int q0 = qbase + wid * 16 + row_lo;
        int q1 = qbase + wid * 16 + row_hi;
        size_t base0 = (size_t)(b * Ss + q0) * 1024 + h * 64;
        size_t base1 = (size_t)(b * Ss + q1) * 1024 + h * 64;
        int c0 = (lane & 3) * 2;
#pragma unroll
        for (int nf = 0; nf < 8; nf++) {
            int col = nf * 8 + c0;
            uint32_t hh, ll;
            split2(O[nf][0] * linv0, O[nf][1] * linv0, hh, ll);
            *(uint32_t*)&g_ctxh[base0 + col] = hh;
            *(uint32_t*)&g_ctxl[base0 + col] = ll;
            split2(O[nf][2] * linv1, O[nf][3] * linv1, hh, ll);
            *(uint32_t*)&g_ctxh[base1 + col] = hh;
            *(uint32_t*)&g_ctxl[base1 + col] = ll;
        }
    }
}

// ---------------- small kernels ----------------
__global__ void reset_kernel() {
    int t = threadIdx.x;
    if (t < Ee) { g_cnt[t] = 0; g_cur[t] = 0; }
}

__global__ void rmsnorm_kernel(const float* __restrict__ in,
                               const float* __restrict__ gamma,
                               float* __restrict__ out,
                               bf16* __restrict__ oh, bf16* __restrict__ ol) {
    int row = blockIdx.x;
    const float* p = in + row * Dd;
    float ss = 0.f;
    for (int d = threadIdx.x; d < Dd; d += blockDim.x) { float v = p[d]; ss += v * v; }
    for (int o = 16; o; o >>= 1) ss += __shfl_xor_sync(0xffffffffu, ss, o);
    __shared__ float red[8];
    int w = threadIdx.x >> 5;
    if ((threadIdx.x & 31) == 0) red[w] = ss;
    __syncthreads();
    if (threadIdx.x < 8) {
        float v = red[threadIdx.x];
        for (int o = 4; o; o >>= 1) v += __shfl_xor_sync(0xffu, v, o);
        if (threadIdx.x == 0) red[0] = v;
    }
    __syncthreads();
    float rinv = rsqrtf(red[0] * (1.0f / Dd) + EPSf);
    for (int d = threadIdx.x * 2; d < Dd; d += blockDim.x * 2) {
        float v0 = p[d] * rinv * gamma[d];
        float v1 = p[d + 1] * rinv * gamma[d + 1];
        out[row * Dd + d]     = v0;
        out[row * Dd + d + 1] = v1;
        uint32_t h, l; split2(v0, v1, h, l);
        *(uint32_t*)&oh[row * Dd + d] = h;
        *(uint32_t*)&ol[row * Dd + d] = l;
    }
}

__global__ void rope_kernel(const float* __restrict__ p, const float* __restrict__ theta,
                            bf16* __restrict__ oh, bf16* __restrict__ ol) {
    __shared__ float buf[8][64];
    int w = threadIdx.x >> 5;
    int v = blockIdx.x * 8 + w;
    int s = v & (Ss - 1);
    const float* basep = p + (size_t)v * HDh;
    int i = threadIdx.x & 31;
    float x1 = basep[2 * i], x2 = basep[2 * i + 1];
    float ang = (float)s * theta[i];
    float c = cosf(ang), sn = sinf(ang);
    buf[w][i]      = x1 * c - x2 * sn;
    buf[w][32 + i] = x1 * sn + x2 * c;
    __syncwarp();
    float v0 = buf[w][2 * i], v1 = buf[w][2 * i + 1];
    uint32_t h, l; split2(v0, v1, h, l);
    *(uint32_t*)&oh[(size_t)v * HDh + 2 * i] = h;
    *(uint32_t*)&ol[(size_t)v * HDh + 2 * i] = l;
}

__global__ void router_kernel(const float* __restrict__ an, const float* __restrict__ W,
                              const float* __restrict__ bias) {
    int tkn = blockIdx.x;
    __shared__ float xs[Dd];
    for (int d = threadIdx.x; d < Dd; d += 32) xs[d] = an[tkn * Dd + d];
    __syncwarp();
    int e = threadIdx.x;
    float logit = -1e30f;
    if (e < Ee) {
        float acc = bias[e];
        for (int d = 0; d < Dd; d++) acc += xs[d] * W[d * Ee + e];
        logit = acc;
    }
    float mx = logit;
    for (int o = 16; o; o >>= 1) mx = fmaxf(mx, __shfl_xor_sync(0xffffffffu, mx, o));
    float ex = (e < Ee) ? __expf(logit - mx) : 0.f;
    float sm = ex;
    for (int o = 16; o; o >>= 1) sm += __shfl_xor_sync(0xffffffffu, sm, o);
    float pw = ex / sm;
    for (int it = 0; it < 3; it++) {
        float bv = pw; int bi = e;
        for (int o = 16; o; o >>= 1) {
            float ov = __shfl_xor_sync(0xffffffffu, bv, o);
            int   oi = __shfl_xor_sync(0xffffffffu, bi, o);
            if (ov > bv || (ov == bv && oi < bi)) { bv = ov; bi = oi; }
        }
        if (threadIdx.x == 0) {
            g_topi[tkn * 3 + it] = bi;
            g_topv[tkn * 3 + it] = bv;
            atomicAdd(&g_cnt[bi], 1);
        }
        if (e == bi) pw = -1.f;
    }
}

__global__ void scan_kernel() {
    if (threadIdx.x == 0) {
        int s = 0;
        for (int e = 0; e < Ee; e++) { g_off[e] = s; s += g_cnt[e]; }
    }
}

__global__ void fill_kernel() {
    int i = blockIdx.x * 256 + threadIdx.x;
    if (i >= SLOTS) return;
    int tkn = i / 3, r = i - tkn * 3;
    int e = g_topi[i];
    int pos = atomicAdd(&g_cur[e], 1);
    int slot = g_off[e] + pos;
    g_slot_tok[slot] = tkn;
    g_slot_rank[slot] = r;
    g_slot_gate[slot] = g_topv[i];
}

__global__ void final_kernel(float* __restrict__ out) {
    int i = blockIdx.x * 256 + threadIdx.x;
    int t = i >> 10, n = i & 1023;
    float v = out[i];
    v += g_part[(size_t)(t * 3 + 0) * Dd + n];
    v += g_part[(size_t)(t * 3 + 1) * Dd + n];
    v += g_part[(size_t)(t * 3 + 2) * Dd + n];
    out[i] = v;
}

// ---------------- launch ----------------
extern "C" void kernel_launch(void* const* d_in, const int* in_sizes, int n_in,
                              void* d_out, int out_size) {
    const float* x      = (const float*)d_in[0];
    const float* theta  = (const float*)d_in[2];
    const float* gamma1 = (const float*)d_in[3];
    const float* gamma2 = (const float*)d_in[4];
    const float* q_w  = (const float*)d_in[5];  const float* q_b  = (const float*)d_in[6];
    const float* k_w  = (const float*)d_in[7];  const float* k_b  = (const float*)d_in[8];
    const float* v_w  = (const float*)d_in[9];  const float* v_b  = (const float*)d_in[10];
    const float* o_w  = (const float*)d_in[11]; const float* o_b  = (const float*)d_in[12];
    const float* r_w  = (const float*)d_in[13]; const float* r_b  = (const float*)d_in[14];
    const float* sw1  = (const float*)d_in[15]; const float* sb1  = (const float*)d_in[16];
    const float* sw2  = (const float*)d_in[17]; const float* sb2  = (const float*)d_in[18];
    const float* rw1  = (const float*)d_in[19]; const float* rb1  = (const float*)d_in[20];
    const float* rw2  = (const float*)d_in[21]; const float* rb2  = (const float*)d_in[22];
    float* out = (float*)d_out;

    float *xn, *qb, *kb, *attn, *an;
    bf16 *xnh, *xnl, *anh, *anl, *t1h, *t1l, *ctxh, *ctxl, *qsh, *qsl, *ksh, *ksl;
    bf16 *qwh, *qwl, *kwh, *kwl, *vwh, *vwl, *owh, *owl, *s1h, *s1l, *s2h, *s2l;
    bf16 *r1h, *r1l, *r2h, *r2l;
    cudaGetSymbolAddress((void**)&xn,   g_xn);
    cudaGetSymbolAddress((void**)&qb,   g_qb);
    cudaGetSymbolAddress((void**)&kb,   g_kb);
    cudaGetSymbolAddress((void**)&attn, g_attn);
    cudaGetSymbolAddress((void**)&an,   g_an);
    cudaGetSymbolAddress((void**)&xnh,  g_xnh);  cudaGetSymbolAddress((void**)&xnl, g_xnl);
    cudaGetSymbolAddress((void**)&ctxh, g_ctxh); cudaGetSymbolAddress((void**)&ctxl, g_ctxl);
    cudaGetSymbolAddress((void**)&anh,  g_anh);  cudaGetSymbolAddress((void**)&anl, g_anl);
    cudaGetSymbolAddress((void**)&t1h,  g_t1h);  cudaGetSymbolAddress((void**)&t1l, g_t1l);
    cudaGetSymbolAddress((void**)&qsh,  g_qsh);  cudaGetSymbolAddress((void**)&qsl, g_qsl);
    cudaGetSymbolAddress((void**)&ksh,  g_ksh);  cudaGetSymbolAddress((void**)&ksl, g_ksl);
    cudaGetSymbolAddress((void**)&qwh,  g_qwh);  cudaGetSymbolAddress((void**)&qwl, g_qwl);
    cudaGetSymbolAddress((void**)&kwh,  g_kwh);  cudaGetSymbolAddress((void**)&kwl, g_kwl);
    cudaGetSymbolAddress((void**)&vwh,  g_vwh);  cudaGetSymbolAddress((void**)&vwl, g_vwl);
    cudaGetSymbolAddress((void**)&owh,  g_owh);  cudaGetSymbolAddress((void**)&owl, g_owl);
    cudaGetSymbolAddress((void**)&s1h,  g_s1h);  cudaGetSymbolAddress((void**)&s1l, g_s1l);
    cudaGetSymbolAddress((void**)&s2h,  g_s2h);  cudaGetSymbolAddress((void**)&s2l, g_s2l);
    cudaGetSymbolAddress((void**)&r1h,  g_r1h);  cudaGetSymbolAddress((void**)&r1l, g_r1l);
    cudaGetSymbolAddress((void**)&r2h,  g_r2h);  cudaGetSymbolAddress((void**)&r2l, g_r2l);

    cudaFuncSetAttribute(wm_gemm_kernel,   cudaFuncAttributeMaxDynamicSharedMemorySize, DYN_SMEM);
    cudaFuncSetAttribute(wm_qkv_kernel,    cudaFuncAttributeMaxDynamicSharedMemorySize, DYN_SMEM);
    cudaFuncSetAttribute(wm_egemm1_kernel, cudaFuncAttributeMaxDynamicSharedMemorySize, DYN_SMEM);
    cudaFuncSetAttribute(wm_egemm2_kernel, cudaFuncAttributeMaxDynamicSharedMemorySize, DYN_SMEM);
    cudaFuncSetAttribute(attn2_kernel,     cudaFuncAttributeMaxDynamicSharedMemorySize, ATTN_SMEM);

    // one-time side stream + fork/join events (host resources only; no device mem)
    static cudaStream_t s1 = nullptr;
    static cudaEvent_t evFork = nullptr, evAN = nullptr, evPART = nullptr;
    if (!s1) {
        cudaStreamCreateWithFlags(&s1, cudaStreamNonBlocking);
        cudaEventCreateWithFlags(&evFork, cudaEventDisableTiming);
        cudaEventCreateWithFlags(&evAN,   cudaEventDisableTiming);
        cudaEventCreateWithFlags(&evPART, cudaEventDisableTiming);
    }

    dim3 thr(256);
    dim3 grid8x16(8, 16);

    // ---- fork: expert weight conversion on s1 ----
    cudaEventRecord(evFork, 0);
    cudaStreamWaitEvent(s1, evFork, 0);
    convw_kernel<<<(E4 + 1023) / 1024, 256, 0, s1>>>((const float4*)rw1, (uint2*)r1h, (uint2*)r1l, E4);
    convw_kernel<<<(E4 + 1023) / 1024, 256, 0, s1>>>((const float4*)rw2, (uint2*)r2h, (uint2*)r2l, E4);

    // ---- main path ----
    convw6_kernel<<<dim3(D4 / 1024, 6), 256>>>(
        (const float4*)q_w, (const float4*)k_w, (const float4*)v_w,
        (const float4*)o_w, (const float4*)sw1, (const float4*)sw2,
        (uint2*)qwh, (uint2*)kwh, (uint2*)vwh, (uint2*)owh, (uint2*)s1h, (uint2*)s2h,
        (uint2*)qwl, (uint2*)kwl, (uint2*)vwl, (uint2*)owl, (uint2*)s1l, (uint2*)s2l);
    reset_kernel<<<1, 32>>>();
    rmsnorm_kernel<<<NT, 256>>>(x, gamma1, xn, xnh, xnl);

    wm_qkv_kernel<<<dim3(8, 16, 3), thr, DYN_SMEM>>>(q_b, k_b, v_b);

    rope_kernel<<<Bb * Hh * Ss / 8, 256>>>(qb, theta, qsh, qsl);
    rope_kernel<<<Bb * Hh * Ss / 8, 256>>>(kb, theta, ksh, ksl);

    attn2_kernel<<<dim3(8, Bb * Hh), 256, ATTN_SMEM>>>();

    wm_gemm_kernel<<<grid8x16, thr, DYN_SMEM>>>(ctxh, ctxl, owh, owl, o_b, 2, xn, nullptr,
                                                attn, nullptr, nullptr);
    rmsnorm_kernel<<<NT, 256>>>(attn, gamma2, an, anh, anl);
    cudaEventRecord(evAN, 0);

    // ---- expert path on s1 (needs an + expert weights) ----
    cudaStreamWaitEvent(s1, evAN, 0);
    router_kernel<<<NT, 32, 0, s1>>>(an, r_w, r_b);
    scan_kernel<<<1, 32, 0, s1>>>();
    fill_kernel<<<(SLOTS + 255) / 256, 256, 0, s1>>>();
    wm_egemm1_kernel<<<dim3(8, 16, Ee), thr, DYN_SMEM, s1>>>(rb1);
    wm_egemm2_kernel<<<dim3(8, 16, Ee), thr, DYN_SMEM, s1>>>(rb2);
    cudaEventRecord(evPART, s1);

    // ---- shared MLP on main stream (concurrent with expert path) ----
    wm_gemm_kernel<<<grid8x16, thr, DYN_SMEM>>>(anh, anl, s1h, s1l, sb1, 1, nullptr, nullptr,
                                                nullptr, t1h, t1l);
    wm_gemm_kernel<<<grid8x16, thr, DYN_SMEM>>>(t1h, t1l, s2h, s2l, sb2, 2, an, attn,
                                                out, nullptr, nullptr);

    // ---- join + final sum ----
    cudaStreamWaitEvent(0, evPART, 0);
    final_kernel<<<(NT * Dd) / 256, 256>>>(out);
}

// round 13
// speedup vs baseline: 3.1925x; 1.1908x over previous
#include <cuda_runtime.h>
#include <cuda_bf16.h>
#include <cuda_fp16.h>
#include <cuda_pipeline.h>
#include <mma.h>
#include <cstdint>

using namespace nvcuda;

#define Bb     2
#define Ss     1024
#define Dd     1024
#define Hh     16
#define HDh    64
#define NT     (Bb*Ss)
#define Ee     31
#define INTERi 1024
#define EPSf   1e-5f
#define SLOTS  (NT*3)

typedef __nv_bfloat16 bf16;

// ---------------- fp32 scratch ----------------
__device__ float g_xn  [NT*Dd];
__device__ float g_attn[NT*Dd];
__device__ float g_an  [NT*Dd];
__device__ float g_part[SLOTS*Dd];
__device__ int   g_topi[SLOTS];
__device__ float g_topv[SLOTS];
__device__ int   g_cnt[Ee];
__device__ int   g_off[Ee];
__device__ int   g_cur[Ee];
__device__ int   g_slot_tok [SLOTS];
__device__ int   g_slot_rank[SLOTS];
__device__ float g_slot_gate[SLOTS];

// ---------------- bf16 hi/lo activations ----------------
__device__ bf16 g_xnh[NT*Dd],  g_xnl[NT*Dd];
__device__ bf16 g_qsh[NT*Dd],  g_qsl[NT*Dd];
__device__ bf16 g_ksh[NT*Dd],  g_ksl[NT*Dd];
__device__ bf16 g_vsh[NT*Dd],  g_vsl[NT*Dd];
__device__ bf16 g_ctxh[NT*Dd], g_ctxl[NT*Dd];
__device__ bf16 g_anh[NT*Dd],  g_anl[NT*Dd];
__device__ bf16 g_t1h[NT*INTERi], g_t1l[NT*INTERi];

// ---------------- fp16 expert-path activations ----------------
__device__ __half g_anf[NT*Dd];
__device__ __half g_hf [SLOTS*INTERi];

// ---------------- bf16 hi/lo dense weights ----------------
__device__ bf16 g_qwh[Dd*Dd], g_qwl[Dd*Dd];
__device__ bf16 g_kwh[Dd*Dd], g_kwl[Dd*Dd];
__device__ bf16 g_vwh[Dd*Dd], g_vwl[Dd*Dd];
__device__ bf16 g_owh[Dd*Dd], g_owl[Dd*Dd];
__device__ bf16 g_s1h[Dd*INTERi], g_s1l[Dd*INTERi];
__device__ bf16 g_s2h[INTERi*Dd], g_s2l[INTERi*Dd];

// ---------------- fp16 hi/lo expert weights ----------------
__device__ __half g_r1hh[Ee*Dd*INTERi], g_r1hl[Ee*Dd*INTERi];
__device__ __half g_r2hh[Ee*INTERi*Dd], g_r2hl[Ee*INTERi*Dd];

__device__ __forceinline__ float gelu_f(float v) {
    return 0.5f * v * (1.0f + erff(v * 0.70710678118654752f));
}

__device__ __forceinline__ void split2(float x, float y, uint32_t& hi, uint32_t& lo) {
    bf16 hx = __float2bfloat16(x), hy = __float2bfloat16(y);
    bf16 lx = __float2bfloat16(x - __bfloat162float(hx));
    bf16 ly = __float2bfloat16(y - __bfloat162float(hy));
    __nv_bfloat162 H = __halves2bfloat162(hx, hy);
    __nv_bfloat162 L = __halves2bfloat162(lx, ly);
    hi = *(uint32_t*)&H; lo = *(uint32_t*)&L;
}

__device__ __forceinline__ void split2h(float x, float y, uint32_t& hi, uint32_t& lo) {
    __half hx = __float2half_rn(x), hy = __float2half_rn(y);
    __half lx = __float2half_rn(x - __half2float(hx));
    __half ly = __float2half_rn(y - __half2float(hy));
    __half2 H = __halves2half2(hx, hy);
    __half2 L = __halves2half2(lx, ly);
    hi = *(uint32_t*)&H; lo = *(uint32_t*)&L;
}

__device__ __forceinline__ uint32_t s2u(const void* p) {
    uint32_t a;
    asm("{ .reg .u64 t; cvta.to.shared.u64 t, %1; cvt.u32.u64 %0, t; }" : "=r"(a) : "l"(p));
    return a;
}

// ---------------- raw mma/ldmatrix helpers (attention) ----------------
__device__ __forceinline__ void ldsm4(uint32_t& r0, uint32_t& r1, uint32_t& r2, uint32_t& r3, uint32_t addr) {
    asm volatile("ldmatrix.sync.aligned.m8n8.x4.shared.b16 {%0,%1,%2,%3}, [%4];"
        : "=r"(r0), "=r"(r1), "=r"(r2), "=r"(r3) : "r"(addr));
}
__device__ __forceinline__ void ldsm4t(uint32_t& r0, uint32_t& r1, uint32_t& r2, uint32_t& r3, uint32_t addr) {
    asm volatile("ldmatrix.sync.aligned.m8n8.x4.trans.shared.b16 {%0,%1,%2,%3}, [%4];"
        : "=r"(r0), "=r"(r1), "=r"(r2), "=r"(r3) : "r"(addr));
}
__device__ __forceinline__ void mma16816(float* c, uint32_t a0, uint32_t a1, uint32_t a2, uint32_t a3,
                                         uint32_t b0, uint32_t b1) {
    asm volatile("mma.sync.aligned.m16n8k16.row.col.f32.bf16.bf16.f32 "
        "{%0,%1,%2,%3},{%4,%5,%6,%7},{%8,%9},{%0,%1,%2,%3};"
        : "+f"(c[0]), "+f"(c[1]), "+f"(c[2]), "+f"(c[3])
        : "r"(a0), "r"(a1), "r"(a2), "r"(a3), "r"(b0), "r"(b1));
}

// ---------------- weight conversion ----------------
#define D4 (Dd*Dd/4)
#define E4 (Ee*Dd*INTERi/4)

// three DxD tensors -> bf16 hi/lo (grid.y selects tensor)
__global__ void convw3_kernel(
    const float4* s0, const float4* s1, const float4* s2,
    uint2* h0, uint2* h1, uint2* h2,
    uint2* l0, uint2* l1, uint2* l2)
{
    const float4* srcs[3] = {s0, s1, s2};
    uint2* hs[3] = {h0, h1, h2};
    uint2* ls[3] = {l0, l1, l2};
    int w = blockIdx.y;
    const float4* src = srcs[w];
    uint2* h = hs[w];
    uint2* l = ls[w];
    int base = blockIdx.x * 1024 + threadIdx.x;
    float4 v[4];
#pragma unroll
    for (int j = 0; j < 4; j++) v[j] = src[base + j * 256];
#pragma unroll
    for (int j = 0; j < 4; j++) {
        uint32_t a0, b0, a1, b1;
        split2(v[j].x, v[j].y, a0, b0);
        split2(v[j].z, v[j].w, a1, b1);
        h[base + j * 256] = make_uint2(a0, a1);
        l[base + j * 256] = make_uint2(b0, b1);
    }
}

// fp16 hi/lo split (expert weights)
__global__ void convh_kernel(const float4* __restrict__ src,
                             uint2* __restrict__ h, uint2* __restrict__ l, int n4) {
    int base = blockIdx.x * 1024 + threadIdx.x;
    float4 v[4]; int idx[4]; bool ok[4];
#pragma unroll
    for (int j = 0; j < 4; j++) {
        idx[j] = base + j * 256;
        ok[j] = idx[j] < n4;
        if (ok[j]) v[j] = src[idx[j]];
    }
#pragma unroll
    for (int j = 0; j < 4; j++) {
        if (!ok[j]) continue;
        uint32_t h0, l0, h1, l1;
        split2h(v[j].x, v[j].y, h0, l0);
        split2h(v[j].z, v[j].w, h1, l1);
        h[idx[j]] = make_uint2(h0, h1);
        l[idx[j]] = make_uint2(l0, l1);
    }
}

// ================= wmma bf16 split GEMM core (3-chain) =================
typedef wmma::fragment<wmma::accumulator, 16, 16, 16, float> FragC;
typedef wmma::fragment<wmma::matrix_a, 16, 16, 16, bf16, wmma::row_major> FragA;
typedef wmma::fragment<wmma::matrix_b, 16, 16, 16, bf16, wmma::row_major> FragB;
typedef wmma::fragment<wmma::matrix_a, 16, 16, 16, __half, wmma::row_major> FragAH;
typedef wmma::fragment<wmma::matrix_b, 16, 16, 16, __half, wmma::row_major> FragBH;

#define LDA 40
#define LDB 136
#define LDC 132
#define OFF_AH 0
#define OFF_AL 10240
#define OFF_BH 20480
#define OFF_BL 29184
#define STAGE  37888
#define DYN_SMEM (2*STAGE)

__device__ __forceinline__ void stage_fill(
    const bf16* __restrict__ Ahg, const bf16* __restrict__ Alg,
    const bf16* __restrict__ Bhg, const bf16* __restrict__ Blg,
    int nb, int k0, const int* rowmap, char* st, int tid)
{
#pragma unroll
    for (int i = 0; i < 2; i++) {
        int s = tid + i * 256;
        int row = s >> 2, q = s & 3;
        int r = rowmap[row];
        char* dh = st + OFF_AH + row * (LDA * 2) + q * 16;
        char* dl = st + OFF_AL + row * (LDA * 2) + q * 16;
        if (r >= 0) {
            __pipeline_memcpy_async(dh, Ahg + (size_t)r * 1024 + k0 + q * 8, 16);
            __pipeline_memcpy_async(dl, Alg + (size_t)r * 1024 + k0 + q * 8, 16);
        } else {
            *(uint4*)dh = make_uint4(0u, 0u, 0u, 0u);
            *(uint4*)dl = make_uint4(0u, 0u, 0u, 0u);
        }
    }
#pragma unroll
    for (int i = 0; i < 2; i++) {
        int s = tid + i * 256;
        int k = s >> 4, q = s & 15;
        char* dh = st + OFF_BH + k * (LDB * 2) + q * 16;
        char* dl = st + OFF_BL + k * (LDB * 2) + q * 16;
        __pipeline_memcpy_async(dh, Bhg + (size_t)(k0 + k) * 1024 + nb + q * 8, 16);
        __pipeline_memcpy_async(dl, Blg + (size_t)(k0 + k) * 1024 + nb + q * 8, 16);
    }
}

__device__ __forceinline__ void wm_mainloop(
    const bf16* __restrict__ Ahg, const bf16* __restrict__ Alg,
    const bf16* __restrict__ Bhg, const bf16* __restrict__ Blg,
    int nb, const int* rowmap, char* sm, FragC accs[4][2])
{
    int tid = threadIdx.x, wid = tid >> 5;
    int wm = wid & 1, wn = wid >> 1;
#pragma unroll
    for (int mt = 0; mt < 4; mt++)
#pragma unroll
        for (int nt = 0; nt < 2; nt++)
            wmma::fill_fragment(accs[mt][nt], 0.0f);

    stage_fill(Ahg, Alg, Bhg, Blg, nb, 0, rowmap, sm, tid);
    __pipeline_commit();

    for (int t = 0; t < 32; t++) {
        char* cur = sm + (t & 1) * STAGE;
        if (t < 31) {
            stage_fill(Ahg, Alg, Bhg, Blg, nb, (t + 1) * 32, rowmap,
                       sm + ((t + 1) & 1) * STAGE, tid);
            __pipeline_commit();
            __pipeline_wait_prior(1);
        } else {
            __pipeline_wait_prior(0);
        }
        __syncthreads();
        const bf16* Ah = (const bf16*)(cur + OFF_AH);
        const bf16* Al = (const bf16*)(cur + OFF_AL);
        const bf16* Bh = (const bf16*)(cur + OFF_BH);
        const bf16* Bl = (const bf16*)(cur + OFF_BL);
#pragma unroll
        for (int ks = 0; ks < 2; ks++) {
            FragB bh0, bh1, bl0, bl1;
            const bf16* bbase = Bh + (ks * 16) * LDB + wn * 32;
            const bf16* bbasl = Bl + (ks * 16) * LDB + wn * 32;
            wmma::load_matrix_sync(bh0, bbase,      LDB);
            wmma::load_matrix_sync(bh1, bbase + 16, LDB);
            wmma::load_matrix_sync(bl0, bbasl,      LDB);
            wmma::load_matrix_sync(bl1, bbasl + 16, LDB);
#pragma unroll
            for (int mt = 0; mt < 4; mt++) {
                FragA ah, al;
                wmma::load_matrix_sync(ah, Ah + (wm * 64 + mt * 16) * LDA + ks * 16, LDA);
                wmma::load_matrix_sync(al, Al + (wm * 64 + mt * 16) * LDA + ks * 16, LDA);
                wmma::mma_sync(accs[mt][0], ah, bh0, accs[mt][0]);
                wmma::mma_sync(accs[mt][0], ah, bl0, accs[mt][0]);
                wmma::mma_sync(accs[mt][0], al, bh0, accs[mt][0]);
                wmma::mma_sync(accs[mt][1], ah, bh1, accs[mt][1]);
                wmma::mma_sync(accs[mt][1], ah, bl1, accs[mt][1]);
                wmma::mma_sync(accs[mt][1], al, bh1, accs[mt][1]);
            }
        }
        __syncthreads();
    }
    float* Cs = (float*)sm;
#pragma unroll
    for (int mt = 0; mt < 4; mt++)
#pragma unroll
        for (int nt = 0; nt < 2; nt++)
            wmma::store_matrix_sync(Cs + (wm * 64 + mt * 16) * LDC + wn * 32 + nt * 16,
                                    accs[mt][nt], LDC, wmma::mem_row_major);
    __syncthreads();
}

// ================= fp16 2-chain GEMM core (A plain fp16, B hi/lo) ========
#define H_OFF_A  0
#define H_OFF_BH 10240
#define H_OFF_BL 18944
#define H_STAGE  27648

__device__ __forceinline__ void stage_fill_h(
    const __half* __restrict__ Ag,
    const __half* __restrict__ Bhg, const __half* __restrict__ Blg,
    int nb, int k0, const int* rowmap, char* st, int tid)
{
    {
        int s = tid;                      // 512 chunks, 2 per thread
#pragma unroll
        for (int i = 0; i < 2; i++) {
            int id = s + i * 256;
            int row = id >> 2, q = id & 3;
            int r = rowmap[row];
            char* da = st + H_OFF_A + row * (LDA * 2) + q * 16;
            if (r >= 0)
                __pipeline_memcpy_async(da, Ag + (size_t)r * 1024 + k0 + q * 8, 16);
            else
                *(uint4*)da = make_uint4(0u, 0u, 0u, 0u);
        }
    }
#pragma unroll
    for (int i = 0; i < 2; i++) {
        int id = tid + i * 256;
        int k = id >> 4, q = id & 15;
        __pipeline_memcpy_async(st + H_OFF_BH + k * (LDB * 2) + q * 16,
                                Bhg + (size_t)(k0 + k) * 1024 + nb + q * 8, 16);
        __pipeline_memcpy_async(st + H_OFF_BL + k * (LDB * 2) + q * 16,
                                Blg + (size_t)(k0 + k) * 1024 + nb + q * 8, 16);
    }
}

__device__ __forceinline__ void wm_mainloop_h(
    const __half* __restrict__ Ag,
    const __half* __restrict__ Bhg, const __half* __restrict__ Blg,
    int nb, const int* rowmap, char* sm, FragC accs[4][2])
{
    int tid = threadIdx.x, wid = tid >> 5;
    int wm = wid & 1, wn = wid >> 1;
#pragma unroll
    for (int mt = 0; mt < 4; mt++)
#pragma unroll
        for (int nt = 0; nt < 2; nt++)
            wmma::fill_fragment(accs[mt][nt], 0.0f);

    stage_fill_h(Ag, Bhg, Blg, nb, 0, rowmap, sm, tid);
    __pipeline_commit();

    for (int t = 0; t < 32; t++) {
        char* cur = sm + (t & 1) * H_STAGE;
        if (t < 31) {
            stage_fill_h(Ag, Bhg, Blg, nb, (t + 1) * 32, rowmap,
                         sm + ((t + 1) & 1) * H_STAGE, tid);
            __pipeline_commit();
            __pipeline_wait_prior(1);
        } else {
            __pipeline_wait_prior(0);
        }
        __syncthreads();
        const __half* Ah = (const __half*)(cur + H_OFF_A);
        const __half* Bh = (const __half*)(cur + H_OFF_BH);
        const __half* Bl = (const __half*)(cur + H_OFF_BL);
#pragma unroll
        for (int ks = 0; ks < 2; ks++) {
            FragBH bh0, bh1, bl0, bl1;
            const __half* bbase = Bh + (ks * 16) * LDB + wn * 32;
            const __half* bbasl = Bl + (ks * 16) * LDB + wn * 32;
            wmma::load_matrix_sync(bh0, bbase,      LDB);
            wmma::load_matrix_sync(bh1, bbase + 16, LDB);
            wmma::load_matrix_sync(bl0, bbasl,      LDB);
            wmma::load_matrix_sync(bl1, bbasl + 16, LDB);
#pragma unroll
            for (int mt = 0; mt < 4; mt++) {
                FragAH ah;
                wmma::load_matrix_sync(ah, Ah + (wm * 64 + mt * 16) * LDA + ks * 16, LDA);
                wmma::mma_sync(accs[mt][0], ah, bh0, accs[mt][0]);
                wmma::mma_sync(accs[mt][0], ah, bl0, accs[mt][0]);
                wmma::mma_sync(accs[mt][1], ah, bh1, accs[mt][1]);
                wmma::mma_sync(accs[mt][1], ah, bl1, accs[mt][1]);
            }
        }
        __syncthreads();
    }
    float* Cs = (float*)sm;
#pragma unroll
    for (int mt = 0; mt < 4; mt++)
#pragma unroll
        for (int nt = 0; nt < 2; nt++)
            wmma::store_matrix_sync(Cs + (wm * 64 + mt * 16) * LDC + wn * 32 + nt * 16,
                                    accs[mt][nt], LDC, wmma::mem_row_major);
    __syncthreads();
}

#define WM_PROLOGUE(ROWEXPR)                                                   \
    extern __shared__ __align__(16) char dynsm[];                              \
    __shared__ int s_rowmap[128];                                              \
    int tid = threadIdx.x;                                                     \
    if (tid < 128) s_rowmap[tid] = (ROWEXPR);                                  \
    __syncthreads();                                                           \
    FragC accs[4][2];

#define EPI_VARS                                                               \
    float* Cs = (float*)dynsm;                                                 \
    int em = tid >> 1;                                                         \
    int en = (tid & 1) * 64;                                                   \
    const float* crow = Cs + em * LDC + en;

// ---------------- dense GEMM: mode 0 plain->Cf, 1 gelu->Ch/Cl, 2 +res ----
__global__ __launch_bounds__(256, 2) void wm_gemm_kernel(
    const bf16* __restrict__ Ahg, const bf16* __restrict__ Alg,
    const bf16* __restrict__ Bhg, const bf16* __restrict__ Blg,
    const float* __restrict__ bias, int mode,
    const float* __restrict__ res1, const float* __restrict__ res2,
    float* __restrict__ Cf, bf16* __restrict__ Ch, bf16* __restrict__ Cl)
{
    int mb = blockIdx.y * 128, nb = blockIdx.x * 128;
    WM_PROLOGUE(mb + tid)
    wm_mainloop(Ahg, Alg, Bhg, Blg, nb, s_rowmap, dynsm, accs);
    EPI_VARS
    int m = mb + em;
    if (mode == 1) {
        uint32_t* oh = (uint32_t*)(Ch + (size_t)m * 1024 + nb + en);
        uint32_t* ol = (uint32_t*)(Cl + (size_t)m * 1024 + nb + en);
#pragma unroll
        for (int j = 0; j < 64; j += 2) {
            int n = nb + en + j;
            float v0 = gelu_f(crow[j]     + bias[n]);
            float v1 = gelu_f(crow[j + 1] + bias[n + 1]);
            uint32_t h, l; split2(v0, v1, h, l);
            oh[j >> 1] = h; ol[j >> 1] = l;
        }
    } else {
        float* orow = Cf + (size_t)m * 1024 + nb + en;
#pragma unroll
        for (int j = 0; j < 64; j += 4) {
            int n = nb + en + j;
            float4 v;
            v.x = crow[j+0] + bias[n+0];
            v.y = crow[j+1] + bias[n+1];
            v.z = crow[j+2] + bias[n+2];
            v.w = crow[j+3] + bias[n+3];
            if (mode == 2) {
                float4 r = *(const float4*)(res1 + (size_t)m * 1024 + n);
                v.x += r.x; v.y += r.y; v.z += r.z; v.w += r.w;
                if (res2) {
                    float4 r2 = *(const float4*)(res2 + (size_t)m * 1024 + n);
                    v.x += r2.x; v.y += r2.y; v.z += r2.z; v.w += r2.w;
                }
            }
            *(float4*)(orow + j) = v;
        }
    }
}

// ---------------- fused QKV GEMM + RoPE; q,k -> split bf16; v -> split bf16
__global__ __launch_bounds__(256, 2) void wm_qkv_kernel(
    const float* __restrict__ qbias, const float* __restrict__ kbias,
    const float* __restrict__ vbias, const float* __restrict__ theta)
{
    const bf16 *Bh_, *Bl_; const float* bias;
    if (blockIdx.z == 0)      { Bh_ = g_qwh; Bl_ = g_qwl; bias = qbias; }
    else if (blockIdx.z == 1) { Bh_ = g_kwh; Bl_ = g_kwl; bias = kbias; }
    else                      { Bh_ = g_vwh; Bl_ = g_vwl; bias = vbias; }
    int mb = blockIdx.y * 128, nb = blockIdx.x * 128;
    WM_PROLOGUE(mb + tid)
    wm_mainloop(g_xnh, g_xnl, Bh_, Bl_, nb, s_rowmap, dynsm, accs);
    EPI_VARS
    int m = mb + em;
    int b = m >> 10, s = m & 1023;
    int n0 = nb + en;
    int hh = n0 >> 6;
    size_t base = ((size_t)(b * Hh + hh) * Ss + s) * 64;
    if (blockIdx.z == 2) {
#pragma unroll
        for (int j = 0; j < 64; j += 2) {
            int n = n0 + j;
            float v0 = crow[j]     + bias[n];
            float v1 = crow[j + 1] + bias[n + 1];
            uint32_t h, l; split2(v0, v1, h, l);
            *(uint32_t*)&g_vsh[base + j] = h;
            *(uint32_t*)&g_vsl[base + j] = l;
        }
    } else {
        bf16* oh = (blockIdx.z == 0) ? g_qsh : g_ksh;
        bf16* ol = (blockIdx.z == 0) ? g_qsl : g_ksl;
        float outv[64];
#pragma unroll
        for (int i = 0; i < 32; i++) {
            float x1 = crow[2 * i]     + bias[n0 + 2 * i];
            float x2 = crow[2 * i + 1] + bias[n0 + 2 * i + 1];
            float sn, c;
            sincosf((float)s * theta[i], &sn, &c);
            outv[i]      = x1 * c - x2 * sn;
            outv[32 + i] = x1 * sn + x2 * c;
        }
#pragma unroll
        for (int j = 0; j < 64; j += 2) {
            uint32_t h, l; split2(outv[j], outv[j + 1], h, l);
            *(uint32_t*)&oh[base + j] = h;
            *(uint32_t*)&ol[base + j] = l;
        }
    }
}

// ---------------- expert GEMM 1 (fp16 2-chain): h = gelu(an @ W1[e]) ------
__global__ __launch_bounds__(256, 2) void wm_egemm1h_kernel(const float* __restrict__ re_b1)
{
    int e = blockIdx.z;
    int cnt = g_cnt[e];
    int mb = blockIdx.y * 128;
    if (mb >= cnt) return;
    int off = g_off[e];
    int nb = blockIdx.x * 128;
    WM_PROLOGUE((mb + tid < cnt) ? g_slot_tok[off + mb + tid] : -1)
    wm_mainloop_h(g_anf,
                  g_r1hh + (size_t)e * (Dd * INTERi), g_r1hl + (size_t)e * (Dd * INTERi),
                  nb, s_rowmap, dynsm, accs);
    const float* bias = re_b1 + e * INTERi;
    EPI_VARS
    int row = mb + em;
    if (row < cnt) {
        __half2* hrow = (__half2*)(g_hf + (size_t)(off + row) * INTERi + nb + en);
#pragma unroll
        for (int j = 0; j < 64; j += 2) {
            int n = nb + en + j;
            float v0 = gelu_f(crow[j]     + bias[n]);
            float v1 = gelu_f(crow[j + 1] + bias[n + 1]);
            hrow[j >> 1] = __floats2half2_rn(v0, v1);
        }
    }
}

// ---------------- expert GEMM 2 (fp16 2-chain) ----------------
__global__ __launch_bounds__(256, 2) void wm_egemm2h_kernel(const float* __restrict__ re_b2)
{
    int e = blockIdx.z;
    int cnt = g_cnt[e];
    int mb = blockIdx.y * 128;
    if (mb >= cnt) return;
    int off = g_off[e];
    int nb = blockIdx.x * 128;
    WM_PROLOGUE((mb + tid < cnt) ? (off + mb + tid) : -1)
    wm_mainloop_h(g_hf,
                  g_r2hh + (size_t)e * (INTERi * Dd), g_r2hl + (size_t)e * (INTERi * Dd),
                  nb, s_rowmap, dynsm, accs);
    const float* bias = re_b2 + e * Dd;
    EPI_VARS
    int row = mb + em;
    if (row < cnt) {
        int slot = off + row;
        int tok = g_slot_tok[slot];
        int rnk = g_slot_rank[slot];
        float gate = g_slot_gate[slot];
        float* outp = g_part + (size_t)(tok * 3 + rnk) * Dd + nb + en;
#pragma unroll
        for (int j = 0; j < 64; j += 4) {
            int n = nb + en + j;
            float4 v;
            v.x = gate * (crow[j+0] + bias[n+0]);
            v.y = gate * (crow[j+1] + bias[n+1]);
            v.z = gate * (crow[j+2] + bias[n+2]);
            v.w = gate * (crow[j+3] + bias[n+3]);
            *(float4*)(outp + j) = v;
        }
    }
}

// ================= tensor-core flash attention =================
#define LDT 72
#define LDS_ 68
#define AQ_H 0
#define AQ_L 18432
#define AKOF(s)  (36864 + (s)*36864)
#define AVOF(s)  (AKOF(s) + 18432)
#define AS_OFF 110592
#define AP_H   145408
#define AP_L   163840
#define AM_OFF 182272
#define AL_OFF 182784
#define AC_OFF 183296
#define ATTN_SMEM 183808

__device__ __forceinline__ void attn_fill_kv(char* sm, int s, int grow, int tid) {
    const bf16* srcs[4] = {g_ksh, g_ksl, g_vsh, g_vsl};
    uint32_t dsts[4] = {(uint32_t)AKOF(s), (uint32_t)(AKOF(s) + 9216),
                        (uint32_t)AVOF(s), (uint32_t)(AVOF(s) + 9216)};
#pragma unroll
    for (int j = 0; j < 8; j++) {
        int id = tid + j * 256;
        int sel = id >> 9, rc = id & 511;
        int row = rc >> 3, cq = rc & 7;
        __pipeline_memcpy_async(sm + dsts[sel] + row * 144 + cq * 16,
                                srcs[sel] + (size_t)(grow + row) * 64 + cq * 8, 16);
    }
}

__global__ __launch_bounds__(256) void attn2_kernel() {
    extern __shared__ __align__(16) char sm[];
    int tid = threadIdx.x, wid = tid >> 5, lane = tid & 31;
    int bh = blockIdx.y;
    int qbase = (int)(gridDim.x - 1 - blockIdx.x) * 128;
    int qrow0 = bh * Ss + qbase;
    uint32_t smb = s2u(sm);

#pragma unroll
    for (int j = 0; j < 8; j++) {
        int id = tid + j * 256;
        int sel = id >> 10, rc = id & 1023;
        int row = rc >> 3, cq = rc & 7;
        const bf16* src = sel ? g_qsl : g_qsh;
        __pipeline_memcpy_async(sm + (sel ? AQ_L : AQ_H) + row * 144 + cq * 16,
                                src + (size_t)(qrow0 + row) * 64 + cq * 8, 16);
    }
    attn_fill_kv(sm, 0, bh * Ss, tid);
    __pipeline_commit();

    float* s_m = (float*)(sm + AM_OFF);
    float* s_l = (float*)(sm + AL_OFF);
    float* s_c = (float*)(sm + AC_OFF);
    if (tid < 128) { s_m[tid] = -1e30f; s_l[tid] = 0.f; }

    float O[8][4];
#pragma unroll
    for (int i = 0; i < 8; i++)
#pragma unroll
        for (int j = 0; j < 4; j++) O[i][j] = 0.f;

    int ntiles = qbase / 64 + 2;
    int row_lo = lane >> 2, row_hi = row_lo + 8;

    for (int t = 0; t < ntiles; t++) {
        int stg = t & 1;
        if (t + 1 < ntiles) {
            attn_fill_kv(sm, (t + 1) & 1, bh * Ss + (t + 1) * 64, tid);
            __pipeline_commit();
            __pipeline_wait_prior(1);
        } else {
            __pipeline_wait_prior(0);
        }
        __syncthreads();

        float Sfr[8][4];
#pragma unroll
        for (int i = 0; i < 8; i++)
#pragma unroll
            for (int j = 0; j < 4; j++) Sfr[i][j] = 0.f;
        uint32_t arow = (uint32_t)(wid * 16 + (lane & 15)) * 144 + (uint32_t)(lane >> 4) * 16;
#pragma unroll
        for (int k = 0; k < 4; k++) {
            uint32_t ah0, ah1, ah2, ah3, al0, al1, al2, al3;
            ldsm4(ah0, ah1, ah2, ah3, smb + AQ_H + arow + k * 32);
            ldsm4(al0, al1, al2, al3, smb + AQ_L + arow + k * 32);
            uint32_t brow = (uint32_t)(lane & 15) * 144 + (uint32_t)(lane >> 4) * 16 + k * 32;
#pragma unroll
            for (int j = 0; j < 4; j++) {
                uint32_t kh0, kh1, kh2, kh3, kl0, kl1, kl2, kl3;
                ldsm4(kh0, kh1, kh2, kh3, smb + AKOF(stg) + brow + (uint32_t)j * 16 * 144);
                ldsm4(kl0, kl1, kl2, kl3, smb + AKOF(stg) + 9216 + brow + (uint32_t)j * 16 * 144);
                mma16816(Sfr[j*2],   ah0, ah1, ah2, ah3, kh0, kh2);
                mma16816(Sfr[j*2],   ah0, ah1, ah2, ah3, kl0, kl2);
                mma16816(Sfr[j*2],   al0, al1, al2, al3, kh0, kh2);
                mma16816(Sfr[j*2+1], ah0, ah1, ah2, ah3, kh1, kh3);
                mma16816(Sfr[j*2+1], ah0, ah1, ah2, ah3, kl1, kl3);
                mma16816(Sfr[j*2+1], al0, al1, al2, al3, kh1, kh3);
            }
        }
        float* sS = (float*)(sm + AS_OFF);
        {
            int r0 = wid * 16 + row_lo, r1 = wid * 16 + row_hi;
            int c0 = (lane & 3) * 2;
#pragma unroll
            for (int nf = 0; nf < 8; nf++) {
                sS[r0 * LDS_ + nf * 8 + c0]     = Sfr[nf][0] * 0.125f;
                sS[r0 * LDS_ + nf * 8 + c0 + 1] = Sfr[nf][1] * 0.125f;
                sS[r1 * LDS_ + nf * 8 + c0]     = Sfr[nf][2] * 0.125f;
                sS[r1 * LDS_ + nf * 8 + c0 + 1] = Sfr[nf][3] * 0.125f;
            }
        }
        __syncthreads();

        {
            int row = tid >> 1, half = tid & 1;
            float* srow = (float*)(sm + AS_OFF) + row * LDS_ + half * 32;
            int qglob = qbase + row;
            int kbase = t * 64 + half * 32;
            float sv[32];
#pragma unroll
            for (int c = 0; c < 32; c++) {
                float s_ = srow[c];
                if (kbase + c > qglob) s_ = -1e30f;
                sv[c] = s_;
            }
            float tmax = -1e30f;
#pragma unroll
            for (int c = 0; c < 32; c++) tmax = fmaxf(tmax, sv[c]);
            tmax = fmaxf(tmax, __shfl_xor_sync(0xffffffffu, tmax, 1));
            float mo = s_m[row];
            float nm = fmaxf(mo, tmax);
            float corr = __expf(mo - nm);
            float sum = 0.f;
            uint32_t* ph = (uint32_t*)(sm + AP_H) + (row * LDT + half * 32) / 2;
            uint32_t* pl = (uint32_t*)(sm + AP_L) + (row * LDT + half * 32) / 2;
#pragma unroll
            for (int c = 0; c < 32; c += 2) {
                float p0 = __expf(sv[c] - nm);
                float p1 = __expf(sv[c + 1] - nm);
                sum += p0 + p1;
                uint32_t h, l; split2(p0, p1, h, l);
                ph[c >> 1] = h; pl[c >> 1] = l;
            }
            sum += __shfl_xor_sync(0xffffffffu, sum, 1);
            if (half == 0) {
                s_m[row] = nm;
                s_l[row] = s_l[row] * corr + sum;
                s_c[row] = corr;
            }
        }
        __syncthreads();

        {
            float c_lo = s_c[wid * 16 + row_lo];
            float c_hi = s_c[wid * 16 + row_hi];
#pragma unroll
            for (int nf = 0; nf < 8; nf++) {
                O[nf][0] *= c_lo; O[nf][1] *= c_lo;
                O[nf][2] *= c_hi; O[nf][3] *= c_hi;
            }
        }
#pragma unroll
        for (int k = 0; k < 4; k++) {
            uint32_t ph0, ph1, ph2, ph3, pl0, pl1, pl2, pl3;
            ldsm4(ph0, ph1, ph2, ph3, smb + AP_H + arow + k * 32);
            ldsm4(pl0, pl1, pl2, pl3, smb + AP_L + arow + k * 32);
            uint32_t vrow = (uint32_t)(k * 16 + (lane & 7) + ((lane >> 3) & 1) * 8) * 144
                          + (uint32_t)((lane >> 4) & 1) * 16;
#pragma unroll
            for (int j = 0; j < 4; j++) {
                uint32_t vh0, vh1, vh2, vh3, vl0, vl1, vl2, vl3;
                ldsm4t(vh0, vh1, vh2, vh3, smb + AVOF(stg) + vrow + (uint32_t)j * 32);
                ldsm4t(vl0, vl1, vl2, vl3, smb + AVOF(stg) + 9216 + vrow + (uint32_t)j * 32);
                mma16816(O[j*2],   ph0, ph1, ph2, ph3, vh0, vh1);
                mma16816(O[j*2],   ph0, ph1, ph2, ph3, vl0, vl1);
                mma16816(O[j*2],   pl0, pl1, pl2, pl3, vh0, vh1);
                mma16816(O[j*2+1], ph0, ph1, ph2, ph3, vh2, vh3);
                mma16816(O[j*2+1], ph0, ph1, ph2, ph3, vl2, vl3);
                mma16816(O[j*2+1], pl0, pl1, pl2, pl3, vh2, vh3);
            }
        }
        __syncthreads();
    }

    {
        int b = bh >> 4, h = bh & 15;
        float linv0 = 1.f / s_l[wid * 16 + row_lo];
        float linv1 = 1.f / s_l[wid * 16 + row_hi];
        int q0 = qbase + wid * 16 + row_lo;
        int q1 = qbase + wid * 16 + row_hi;
        size_t base0 = (size_t)(b * Ss + q0) * 1024 + h * 64;
        size_t base1 = (size_t)(b * Ss + q1) * 1024 + h * 64;
        int c0 = (lane & 3) * 2;
#pragma unroll
        for (int nf = 0; nf < 8; nf++) {
            int col = nf * 8 + c0;
            uint32_t hh, ll;
            split2(O[nf][0] * linv0, O[nf][1] * linv0, hh, ll);
            *(uint32_t*)&g_ctxh[base0 + col] = hh;
            *(uint32_t*)&g_ctxl[base0 + col] = ll;
            split2(O[nf][2] * linv1, O[nf][3] * linv1, hh, ll);
            *(uint32_t*)&g_ctxh[base1 + col] = hh;
            *(uint32_t*)&g_ctxl[base1 + col] = ll;
        }
    }
}

// ---------------- small kernels ----------------
__global__ void reset_kernel() {
    int t = threadIdx.x;
    if (t < Ee) { g_cnt[t] = 0; g_cur[t] = 0; }
}

__global__ void rmsnorm_kernel(const float* __restrict__ in,
                               const float* __restrict__ gamma,
                               float* __restrict__ out,
                               bf16* __restrict__ oh, bf16* __restrict__ ol,
                               __half* __restrict__ ofh) {
    int row = blockIdx.x;
    const float* p = in + row * Dd;
    float ss = 0.f;
    for (int d = threadIdx.x; d < Dd; d += blockDim.x) { float v = p[d]; ss += v * v; }
    for (int o = 16; o; o >>= 1) ss += __shfl_xor_sync(0xffffffffu, ss, o);
    __shared__ float red[8];
    int w = threadIdx.x >> 5;
    if ((threadIdx.x & 31) == 0) red[w] = ss;
    __syncthreads();
    if (threadIdx.x < 8) {
        float v = red[threadIdx.x];
        for (int o = 4; o; o >>= 1) v += __shfl_xor_sync(0xffu, v, o);
        if (threadIdx.x == 0) red[0] = v;
    }
    __syncthreads();
    float rinv = rsqrtf(red[0] * (1.0f / Dd) + EPSf);
    for (int d = threadIdx.x * 2; d < Dd; d += blockDim.x * 2) {
        float v0 = p[d] * rinv * gamma[d];
        float v1 = p[d + 1] * rinv * gamma[d + 1];
        out[row * Dd + d]     = v0;
        out[row * Dd + d + 1] = v1;
        uint32_t h, l; split2(v0, v1, h, l);
        *(uint32_t*)&oh[row * Dd + d] = h;
        *(uint32_t*)&ol[row * Dd + d] = l;
        if (ofh) *(__half2*)&ofh[row * Dd + d] = __floats2half2_rn(v0, v1);
    }
}

__global__ void router_kernel(const float* __restrict__ an, const float* __restrict__ W,
                              const float* __restrict__ bias) {
    int tkn = blockIdx.x;
    __shared__ float xs[Dd];
    for (int d = threadIdx.x; d < Dd; d += 32) xs[d] = an[tkn * Dd + d];
    __syncwarp();
    int e = threadIdx.x;
    float logit = -1e30f;
    if (e < Ee) {
        float acc = bias[e];
        for (int d = 0; d < Dd; d++) acc += xs[d] * W[d * Ee + e];
        logit = acc;
    }
    float mx = logit;
    for (int o = 16; o; o >>= 1) mx = fmaxf(mx, __shfl_xor_sync(0xffffffffu, mx, o));
    float ex = (e < Ee) ? __expf(logit - mx) : 0.f;
    float sm = ex;
    for (int o = 16; o; o >>= 1) sm += __shfl_xor_sync(0xffffffffu, sm, o);
    float pw = ex / sm;
    for (int it = 0; it < 3; it++) {
        float bv = pw; int bi = e;
        for (int o = 16; o; o >>= 1) {
            float ov = __shfl_xor_sync(0xffffffffu, bv, o);
            int   oi = __shfl_xor_sync(0xffffffffu, bi, o);
            if (ov > bv || (ov == bv && oi < bi)) { bv = ov; bi = oi; }
        }
        if (threadIdx.x == 0) {
            g_topi[tkn * 3 + it] = bi;
            g_topv[tkn * 3 + it] = bv;
            atomicAdd(&g_cnt[bi], 1);
        }
        if (e == bi) pw = -1.f;
    }
}

__global__ void scan_kernel() {
    if (threadIdx.x == 0) {
        int s = 0;
        for (int e = 0; e < Ee; e++) { g_off[e] = s; s += g_cnt[e]; }
    }
}

__global__ void fill_kernel() {
    int i = blockIdx.x * 256 + threadIdx.x;
    if (i >= SLOTS) return;
    int tkn = i / 3, r = i - tkn * 3;
    int e = g_topi[i];
    int pos = atomicAdd(&g_cur[e], 1);
    int slot = g_off[e] + pos;
    g_slot_tok[slot] = tkn;
    g_slot_rank[slot] = r;
    g_slot_gate[slot] = g_topv[i];
}

__global__ void final_kernel(float* __restrict__ out) {
    int i = blockIdx.x * 256 + threadIdx.x;
    int t = i >> 10, n = i & 1023;
    float v = out[i];
    v += g_part[(size_t)(t * 3 + 0) * Dd + n];
    v += g_part[(size_t)(t * 3 + 1) * Dd + n];
    v += g_part[(size_t)(t * 3 + 2) * Dd + n];
    out[i] = v;
}

// ---------------- launch ----------------
extern "C" void kernel_launch(void* const* d_in, const int* in_sizes, int n_in,
                              void* d_out, int out_size) {
    const float* x      = (const float*)d_in[0];
    const float* theta  = (const float*)d_in[2];
    const float* gamma1 = (const float*)d_in[3];
    const float* gamma2 = (const float*)d_in[4];
    const float* q_w  = (const float*)d_in[5];  const float* q_b  = (const float*)d_in[6];
    const float* k_w  = (const float*)d_in[7];  const float* k_b  = (const float*)d_in[8];
    const float* v_w  = (const float*)d_in[9];  const float* v_b  = (const float*)d_in[10];
    const float* o_w  = (const float*)d_in[11]; const float* o_b  = (const float*)d_in[12];
    const float* r_w  = (const float*)d_in[13]; const float* r_b  = (const float*)d_in[14];
    const float* sw1  = (const float*)d_in[15]; const float* sb1  = (const float*)d_in[16];
    const float* sw2  = (const float*)d_in[17]; const float* sb2  = (const float*)d_in[18];
    const float* rw1  = (const float*)d_in[19]; const float* rb1  = (const float*)d_in[20];
    const float* rw2  = (const float*)d_in[21]; const float* rb2  = (const float*)d_in[22];
    float* out = (float*)d_out;

    float *xn, *attn, *an;
    bf16 *xnh, *xnl, *anh, *anl, *t1h, *t1l, *ctxh, *ctxl;
    bf16 *qwh, *qwl, *kwh, *kwl, *vwh, *vwl, *owh, *owl, *s1h, *s1l, *s2h, *s2l;
    __half *anf, *r1hh, *r1hl, *r2hh, *r2hl;
    cudaGetSymbolAddress((void**)&xn,   g_xn);
    cudaGetSymbolAddress((void**)&attn, g_attn);
    cudaGetSymbolAddress((void**)&an,   g_an);
    cudaGetSymbolAddress((void**)&xnh,  g_xnh);  cudaGetSymbolAddress((void**)&xnl, g_xnl);
    cudaGetSymbolAddress((void**)&ctxh, g_ctxh); cudaGetSymbolAddress((void**)&ctxl, g_ctxl);
    cudaGetSymbolAddress((void**)&anh,  g_anh);  cudaGetSymbolAddress((void**)&anl, g_anl);
    cudaGetSymbolAddress((void**)&t1h,  g_t1h);  cudaGetSymbolAddress((void**)&t1l, g_t1l);
    cudaGetSymbolAddress((void**)&anf,  g_anf);
    cudaGetSymbolAddress((void**)&qwh,  g_qwh);  cudaGetSymbolAddress((void**)&qwl, g_qwl);
    cudaGetSymbolAddress((void**)&kwh,  g_kwh);  cudaGetSymbolAddress((void**)&kwl, g_kwl);
    cudaGetSymbolAddress((void**)&vwh,  g_vwh);  cudaGetSymbolAddress((void**)&vwl, g_vwl);
    cudaGetSymbolAddress((void**)&owh,  g_owh);  cudaGetSymbolAddress((void**)&owl, g_owl);
    cudaGetSymbolAddress((void**)&s1h,  g_s1h);  cudaGetSymbolAddress((void**)&s1l, g_s1l);
    cudaGetSymbolAddress((void**)&s2h,  g_s2h);  cudaGetSymbolAddress((void**)&s2l, g_s2l);
    cudaGetSymbolAddress((void**)&r1hh, g_r1hh); cudaGetSymbolAddress((void**)&r1hl, g_r1hl);
    cudaGetSymbolAddress((void**)&r2hh, g_r2hh); cudaGetSymbolAddress((void**)&r2hl, g_r2hl);

    cudaFuncSetAttribute(wm_gemm_kernel,     cudaFuncAttributeMaxDynamicSharedMemorySize, DYN_SMEM);
    cudaFuncSetAttribute(wm_qkv_kernel,      cudaFuncAttributeMaxDynamicSharedMemorySize, DYN_SMEM);
    cudaFuncSetAttribute(wm_egemm1h_kernel,  cudaFuncAttributeMaxDynamicSharedMemorySize, DYN_SMEM);
    cudaFuncSetAttribute(wm_egemm2h_kernel,  cudaFuncAttributeMaxDynamicSharedMemorySize, DYN_SMEM);
    cudaFuncSetAttribute(attn2_kernel,       cudaFuncAttributeMaxDynamicSharedMemorySize, ATTN_SMEM);

    static cudaStream_t s1 = nullptr;
    static cudaEvent_t evFork = nullptr, evOW = nullptr, evAN = nullptr, evPART = nullptr;
    if (!s1) {
        cudaStreamCreateWithFlags(&s1, cudaStreamNonBlocking);
        cudaEventCreateWithFlags(&evFork, cudaEventDisableTiming);
        cudaEventCreateWithFlags(&evOW,   cudaEventDisableTiming);
        cudaEventCreateWithFlags(&evAN,   cudaEventDisableTiming);
        cudaEventCreateWithFlags(&evPART, cudaEventDisableTiming);
    }

    dim3 thr(256);
    dim3 grid8x16(8, 16);

    // ---- fork: o/sh1/sh2 bf16 conv + expert fp16 conv on s1 ----
    cudaEventRecord(evFork, 0);
    cudaStreamWaitEvent(s1, evFork, 0);
    convw3_kernel<<<dim3(D4 / 1024, 3), 256, 0, s1>>>(
        (const float4*)o_w, (const float4*)sw1, (const float4*)sw2,
        (uint2*)owh, (uint2*)s1h, (uint2*)s2h,
        (uint2*)owl, (uint2*)s1l, (uint2*)s2l);
    cudaEventRecord(evOW, s1);
    convh_kernel<<<(E4 + 1023) / 1024, 256, 0, s1>>>((const float4*)rw1, (uint2*)r1hh, (uint2*)r1hl, E4);
    convh_kernel<<<(E4 + 1023) / 1024, 256, 0, s1>>>((const float4*)rw2, (uint2*)r2hh, (uint2*)r2hl, E4);

    // ---- main path ----
    convw3_kernel<<<dim3(D4 / 1024, 3), 256>>>(
        (const float4*)q_w, (const float4*)k_w, (const float4*)v_w,
        (uint2*)qwh, (uint2*)kwh, (uint2*)vwh,
        (uint2*)qwl, (uint2*)kwl, (uint2*)vwl);
    reset_kernel<<<1, 32>>>();
    rmsnorm_kernel<<<NT, 256>>>(x, gamma1, xn, xnh, xnl, nullptr);

    wm_qkv_kernel<<<dim3(8, 16, 3), thr, DYN_SMEM>>>(q_b, k_b, v_b, theta);

    attn2_kernel<<<dim3(8, Bb * Hh), 256, ATTN_SMEM>>>();

    cudaStreamWaitEvent(0, evOW, 0);
    wm_gemm_kernel<<<grid8x16, thr, DYN_SMEM>>>(ctxh, ctxl, owh, owl, o_b, 2, xn, nullptr,
                                                attn, nullptr, nullptr);
    rmsnorm_kernel<<<NT, 256>>>(attn, gamma2, an, anh, anl, anf);
    cudaEventRecord(evAN, 0);

    // ---- expert path on s1 ----
    cudaStreamWaitEvent(s1, evAN, 0);
    router_kernel<<<NT, 32, 0, s1>>>(an, r_w, r_b);
    scan_kernel<<<1, 32, 0, s1>>>();
    fill_kernel<<<(SLOTS + 255) / 256, 256, 0, s1>>>();
    wm_egemm1h_kernel<<<dim3(8, 16, Ee), thr, DYN_SMEM, s1>>>(rb1);
    wm_egemm2h_kernel<<<dim3(8, 16, Ee), thr, DYN_SMEM, s1>>>(rb2);
    cudaEventRecord(evPART, s1);

    // ---- shared MLP concurrent on s0 ----
    wm_gemm_kernel<<<grid8x16, thr, DYN_SMEM>>>(anh, anl, s1h, s1l, sb1, 1, nullptr, nullptr,
                                                nullptr, t1h, t1l);
    wm_gemm_kernel<<<grid8x16, thr, DYN_SMEM>>>(t1h, t1l, s2h, s2l, sb2, 2, an, attn,
                                                out, nullptr, nullptr);

    // ---- join + final ----
    cudaStreamWaitEvent(0, evPART, 0);
    final_kernel<<<(NT * Dd) / 256, 256>>>(out);
}

// round 15
// speedup vs baseline: 3.5431x; 1.1098x over previous
#include <cuda_runtime.h>
#include <cuda_bf16.h>
#include <cuda_fp16.h>
#include <cuda_pipeline.h>
#include <mma.h>
#include <cstdint>

using namespace nvcuda;

#define Bb     2
#define Ss     1024
#define Dd     1024
#define Hh     16
#define HDh    64
#define NT     (Bb*Ss)
#define Ee     31
#define INTERi 1024
#define EPSf   1e-5f
#define SLOTS  (NT*3)

typedef __nv_bfloat16 bf16;

// ---------------- fp32 scratch ----------------
__device__ float g_xn  [NT*Dd];
__device__ float g_attn[NT*Dd];
__device__ float g_an  [NT*Dd];
__device__ float g_part[SLOTS*Dd];
__device__ int   g_topi[SLOTS];
__device__ float g_topv[SLOTS];
__device__ int   g_cnt[Ee];
__device__ int   g_off[Ee];
__device__ int   g_cur[Ee];
__device__ int   g_slot_tok [SLOTS];
__device__ int   g_slot_rank[SLOTS];
__device__ float g_slot_gate[SLOTS];

// ---------------- bf16 hi/lo attention activations ----------------
__device__ bf16 g_qsh[NT*Dd],  g_qsl[NT*Dd];
__device__ bf16 g_ksh[NT*Dd],  g_ksl[NT*Dd];
__device__ bf16 g_vsh[NT*Dd],  g_vsl[NT*Dd];

// ---------------- fp16 activations ----------------
__device__ __half g_xnf[NT*Dd];
__device__ __half g_ctxf[NT*Dd];
__device__ __half g_anf[NT*Dd];
__device__ __half g_t1f[NT*INTERi];
__device__ __half g_hf [SLOTS*INTERi];

// ---------------- fp16 hi/lo weights ----------------
__device__ __half g_qwh[Dd*Dd], g_qwl[Dd*Dd];
__device__ __half g_kwh[Dd*Dd], g_kwl[Dd*Dd];
__device__ __half g_vwh[Dd*Dd], g_vwl[Dd*Dd];
__device__ __half g_owh[Dd*Dd], g_owl[Dd*Dd];
__device__ __half g_s1h[Dd*INTERi], g_s1l[Dd*INTERi];
__device__ __half g_s2h[INTERi*Dd], g_s2l[INTERi*Dd];
__device__ __half g_r1hh[Ee*Dd*INTERi], g_r1hl[Ee*Dd*INTERi];
__device__ __half g_r2hh[Ee*INTERi*Dd], g_r2hl[Ee*INTERi*Dd];

__device__ __forceinline__ float gelu_f(float v) {
    return 0.5f * v * (1.0f + erff(v * 0.70710678118654752f));
}

__device__ __forceinline__ void split2(float x, float y, uint32_t& hi, uint32_t& lo) {
    bf16 hx = __float2bfloat16(x), hy = __float2bfloat16(y);
    bf16 lx = __float2bfloat16(x - __bfloat162float(hx));
    bf16 ly = __float2bfloat16(y - __bfloat162float(hy));
    __nv_bfloat162 H = __halves2bfloat162(hx, hy);
    __nv_bfloat162 L = __halves2bfloat162(lx, ly);
    hi = *(uint32_t*)&H; lo = *(uint32_t*)&L;
}

__device__ __forceinline__ void split2h(float x, float y, uint32_t& hi, uint32_t& lo) {
    __half hx = __float2half_rn(x), hy = __float2half_rn(y);
    __half lx = __float2half_rn(x - __half2float(hx));
    __half ly = __float2half_rn(y - __half2float(hy));
    __half2 H = __halves2half2(hx, hy);
    __half2 L = __halves2half2(lx, ly);
    hi = *(uint32_t*)&H; lo = *(uint32_t*)&L;
}

__device__ __forceinline__ uint32_t s2u(const void* p) {
    uint32_t a;
    asm("{ .reg .u64 t; cvta.to.shared.u64 t, %1; cvt.u32.u64 %0, t; }" : "=r"(a) : "l"(p));
    return a;
}

// ---------------- raw mma/ldmatrix helpers (attention) ----------------
__device__ __forceinline__ void ldsm4(uint32_t& r0, uint32_t& r1, uint32_t& r2, uint32_t& r3, uint32_t addr) {
    asm volatile("ldmatrix.sync.aligned.m8n8.x4.shared.b16 {%0,%1,%2,%3}, [%4];"
        : "=r"(r0), "=r"(r1), "=r"(r2), "=r"(r3) : "r"(addr));
}
__device__ __forceinline__ void ldsm4t(uint32_t& r0, uint32_t& r1, uint32_t& r2, uint32_t& r3, uint32_t addr) {
    asm volatile("ldmatrix.sync.aligned.m8n8.x4.trans.shared.b16 {%0,%1,%2,%3}, [%4];"
        : "=r"(r0), "=r"(r1), "=r"(r2), "=r"(r3) : "r"(addr));
}
__device__ __forceinline__ void mma16816(float* c, uint32_t a0, uint32_t a1, uint32_t a2, uint32_t a3,
                                         uint32_t b0, uint32_t b1) {
    asm volatile("mma.sync.aligned.m16n8k16.row.col.f32.bf16.bf16.f32 "
        "{%0,%1,%2,%3},{%4,%5,%6,%7},{%8,%9},{%0,%1,%2,%3};"
        : "+f"(c[0]), "+f"(c[1]), "+f"(c[2]), "+f"(c[3])
        : "r"(a0), "r"(a1), "r"(a2), "r"(a3), "r"(b0), "r"(b1));
}

// ---------------- weight conversion (fp16 hi/lo) ----------------
#define D4 (Dd*Dd/4)
#define E4 (Ee*Dd*INTERi/4)

__global__ void convh_kernel(const float4* __restrict__ src,
                             uint2* __restrict__ h, uint2* __restrict__ l, int n4) {
    int base = blockIdx.x * 1024 + threadIdx.x;
    float4 v[4]; int idx[4]; bool ok[4];
#pragma unroll
    for (int j = 0; j < 4; j++) {
        idx[j] = base + j * 256;
        ok[j] = idx[j] < n4;
        if (ok[j]) v[j] = src[idx[j]];
    }
#pragma unroll
    for (int j = 0; j < 4; j++) {
        if (!ok[j]) continue;
        uint32_t h0, l0, h1, l1;
        split2h(v[j].x, v[j].y, h0, l0);
        split2h(v[j].z, v[j].w, h1, l1);
        h[idx[j]] = make_uint2(h0, h1);
        l[idx[j]] = make_uint2(l0, l1);
    }
}

__global__ void convh3_kernel(
    const float4* s0, const float4* s1, const float4* s2,
    uint2* h0, uint2* h1, uint2* h2,
    uint2* l0, uint2* l1, uint2* l2)
{
    const float4* srcs[3] = {s0, s1, s2};
    uint2* hs[3] = {h0, h1, h2};
    uint2* ls[3] = {l0, l1, l2};
    int w = blockIdx.y;
    const float4* src = srcs[w];
    uint2* h = hs[w];
    uint2* l = ls[w];
    int base = blockIdx.x * 1024 + threadIdx.x;
    float4 v[4];
#pragma unroll
    for (int j = 0; j < 4; j++) v[j] = src[base + j * 256];
#pragma unroll
    for (int j = 0; j < 4; j++) {
        uint32_t a0, b0, a1, b1;
        split2h(v[j].x, v[j].y, a0, b0);
        split2h(v[j].z, v[j].w, a1, b1);
        h[base + j * 256] = make_uint2(a0, a1);
        l[base + j * 256] = make_uint2(b0, b1);
    }
}

// ================= fp16 2-chain GEMM core (A plain, B hi/lo) =============
typedef wmma::fragment<wmma::accumulator, 16, 16, 16, float> FragC;
typedef wmma::fragment<wmma::matrix_a, 16, 16, 16, __half, wmma::row_major> FragAH;
typedef wmma::fragment<wmma::matrix_b, 16, 16, 16, __half, wmma::row_major> FragBH;

#define LDA 40
#define LDB 136
#define LDC 132
#define H_OFF_A  0
#define H_OFF_BH 10240
#define H_OFF_BL 18944
#define H_STAGE  27648
#define DYN_SMEM (2*H_STAGE)
#define EPI_SMEM (128*LDC*4)      // 67584 used by epilogue staging (fits in 2*H_STAGE? 55296 < 67584 -> no)
// epilogue needs 67584; allocate max(2*H_STAGE, EPI_SMEM)
#undef DYN_SMEM
#define DYN_SMEM 67584

__device__ __forceinline__ void stage_fill_h(
    const __half* __restrict__ Ag,
    const __half* __restrict__ Bhg, const __half* __restrict__ Blg,
    int nb, int k0, const int* rowmap, char* st, int tid)
{
#pragma unroll
    for (int i = 0; i < 2; i++) {
        int id = tid + i * 256;
        int row = id >> 2, q = id & 3;
        int r = rowmap[row];
        char* da = st + H_OFF_A + row * (LDA * 2) + q * 16;
        if (r >= 0)
            __pipeline_memcpy_async(da, Ag + (size_t)r * 1024 + k0 + q * 8, 16);
        else
            *(uint4*)da = make_uint4(0u, 0u, 0u, 0u);
    }
#pragma unroll
    for (int i = 0; i < 2; i++) {
        int id = tid + i * 256;
        int k = id >> 4, q = id & 15;
        __pipeline_memcpy_async(st + H_OFF_BH + k * (LDB * 2) + q * 16,
                                Bhg + (size_t)(k0 + k) * 1024 + nb + q * 8, 16);
        __pipeline_memcpy_async(st + H_OFF_BL + k * (LDB * 2) + q * 16,
                                Blg + (size_t)(k0 + k) * 1024 + nb + q * 8, 16);
    }
}

__device__ __forceinline__ void wm_mainloop_h(
    const __half* __restrict__ Ag,
    const __half* __restrict__ Bhg, const __half* __restrict__ Blg,
    int nb, const int* rowmap, char* sm, FragC accs[4][2])
{
    int tid = threadIdx.x, wid = tid >> 5;
    int wm = wid & 1, wn = wid >> 1;
#pragma unroll
    for (int mt = 0; mt < 4; mt++)
#pragma unroll
        for (int nt = 0; nt < 2; nt++)
            wmma::fill_fragment(accs[mt][nt], 0.0f);

    stage_fill_h(Ag, Bhg, Blg, nb, 0, rowmap, sm, tid);
    __pipeline_commit();

    for (int t = 0; t < 32; t++) {
        char* cur = sm + (t & 1) * H_STAGE;
        if (t < 31) {
            stage_fill_h(Ag, Bhg, Blg, nb, (t + 1) * 32, rowmap,
                         sm + ((t + 1) & 1) * H_STAGE, tid);
            __pipeline_commit();
            __pipeline_wait_prior(1);
        } else {
            __pipeline_wait_prior(0);
        }
        __syncthreads();
        const __half* Ah = (const __half*)(cur + H_OFF_A);
        const __half* Bh = (const __half*)(cur + H_OFF_BH);
        const __half* Bl = (const __half*)(cur + H_OFF_BL);
#pragma unroll
        for (int ks = 0; ks < 2; ks++) {
            FragBH bh0, bh1, bl0, bl1;
            const __half* bbase = Bh + (ks * 16) * LDB + wn * 32;
            const __half* bbasl = Bl + (ks * 16) * LDB + wn * 32;
            wmma::load_matrix_sync(bh0, bbase,      LDB);
            wmma::load_matrix_sync(bh1, bbase + 16, LDB);
            wmma::load_matrix_sync(bl0, bbasl,      LDB);
            wmma::load_matrix_sync(bl1, bbasl + 16, LDB);
#pragma unroll
            for (int mt = 0; mt < 4; mt++) {
                FragAH ah;
                wmma::load_matrix_sync(ah, Ah + (wm * 64 + mt * 16) * LDA + ks * 16, LDA);
                wmma::mma_sync(accs[mt][0], ah, bh0, accs[mt][0]);
                wmma::mma_sync(accs[mt][0], ah, bl0, accs[mt][0]);
                wmma::mma_sync(accs[mt][1], ah, bh1, accs[mt][1]);
                wmma::mma_sync(accs[mt][1], ah, bl1, accs[mt][1]);
            }
        }
        __syncthreads();
    }
    float* Cs = (float*)sm;
#pragma unroll
    for (int mt = 0; mt < 4; mt++)
#pragma unroll
        for (int nt = 0; nt < 2; nt++)
            wmma::store_matrix_sync(Cs + (wm * 64 + mt * 16) * LDC + wn * 32 + nt * 16,
                                    accs[mt][nt], LDC, wmma::mem_row_major);
    __syncthreads();
}

#define WM_PROLOGUE(ROWEXPR)                                                   \
    extern __shared__ __align__(16) char dynsm[];                              \
    __shared__ int s_rowmap[128];                                              \
    int tid = threadIdx.x;                                                     \
    if (tid < 128) s_rowmap[tid] = (ROWEXPR);                                  \
    __syncthreads();                                                           \
    FragC accs[4][2];

#define EPI_VARS                                                               \
    float* Cs = (float*)dynsm;                                                 \
    int em = tid >> 1;                                                         \
    int en = (tid & 1) * 64;                                                   \
    const float* crow = Cs + em * LDC + en;

// ---------------- dense GEMM: mode 0 plain->Cf, 1 gelu->Chf, 2 +res->Cf ---
__global__ __launch_bounds__(256, 2) void wm_gemm_h_kernel(
    const __half* __restrict__ Ag,
    const __half* __restrict__ Bhg, const __half* __restrict__ Blg,
    const float* __restrict__ bias, int mode,
    const float* __restrict__ res1, const float* __restrict__ res2,
    float* __restrict__ Cf, __half* __restrict__ Chf)
{
    int mb = blockIdx.y * 128, nb = blockIdx.x * 128;
    WM_PROLOGUE(mb + tid)
    wm_mainloop_h(Ag, Bhg, Blg, nb, s_rowmap, dynsm, accs);
    EPI_VARS
    int m = mb + em;
    if (mode == 1) {
        __half2* orow = (__half2*)(Chf + (size_t)m * 1024 + nb + en);
#pragma unroll
        for (int j = 0; j < 64; j += 2) {
            int n = nb + en + j;
            float v0 = gelu_f(crow[j]     + bias[n]);
            float v1 = gelu_f(crow[j + 1] + bias[n + 1]);
            orow[j >> 1] = __floats2half2_rn(v0, v1);
        }
    } else {
        float* orow = Cf + (size_t)m * 1024 + nb + en;
#pragma unroll
        for (int j = 0; j < 64; j += 4) {
            int n = nb + en + j;
            float4 v;
            v.x = crow[j+0] + bias[n+0];
            v.y = crow[j+1] + bias[n+1];
            v.z = crow[j+2] + bias[n+2];
            v.w = crow[j+3] + bias[n+3];
            if (mode == 2) {
                float4 r = *(const float4*)(res1 + (size_t)m * 1024 + n);
                v.x += r.x; v.y += r.y; v.z += r.z; v.w += r.w;
                if (res2) {
                    float4 r2 = *(const float4*)(res2 + (size_t)m * 1024 + n);
                    v.x += r2.x; v.y += r2.y; v.z += r2.z; v.w += r2.w;
                }
            }
            *(float4*)(orow + j) = v;
        }
    }
}

// ---------------- fused QKV GEMM + RoPE; q,k,v -> split bf16 ----------------
__global__ __launch_bounds__(256, 2) void wm_qkv_h_kernel(
    const float* __restrict__ qbias, const float* __restrict__ kbias,
    const float* __restrict__ vbias, const float* __restrict__ theta)
{
    const __half *Bh_, *Bl_; const float* bias;
    if (blockIdx.z == 0)      { Bh_ = g_qwh; Bl_ = g_qwl; bias = qbias; }
    else if (blockIdx.z == 1) { Bh_ = g_kwh; Bl_ = g_kwl; bias = kbias; }
    else                      { Bh_ = g_vwh; Bl_ = g_vwl; bias = vbias; }
    int mb = blockIdx.y * 128, nb = blockIdx.x * 128;
    WM_PROLOGUE(mb + tid)
    wm_mainloop_h(g_xnf, Bh_, Bl_, nb, s_rowmap, dynsm, accs);
    EPI_VARS
    int m = mb + em;
    int b = m >> 10, s = m & 1023;
    int n0 = nb + en;
    int hh = n0 >> 6;
    size_t base = ((size_t)(b * Hh + hh) * Ss + s) * 64;
    if (blockIdx.z == 2) {
#pragma unroll
        for (int j = 0; j < 64; j += 2) {
            int n = n0 + j;
            float v0 = crow[j]     + bias[n];
            float v1 = crow[j + 1] + bias[n + 1];
            uint32_t h, l; split2(v0, v1, h, l);
            *(uint32_t*)&g_vsh[base + j] = h;
            *(uint32_t*)&g_vsl[base + j] = l;
        }
    } else {
        bf16* oh = (blockIdx.z == 0) ? g_qsh : g_ksh;
        bf16* ol = (blockIdx.z == 0) ? g_qsl : g_ksl;
        float outv[64];
#pragma unroll
        for (int i = 0; i < 32; i++) {
            float x1 = crow[2 * i]     + bias[n0 + 2 * i];
            float x2 = crow[2 * i + 1] + bias[n0 + 2 * i + 1];
            float sn, c;
            sincosf((float)s * theta[i], &sn, &c);
            outv[i]      = x1 * c - x2 * sn;
            outv[32 + i] = x1 * sn + x2 * c;
        }
#pragma unroll
        for (int j = 0; j < 64; j += 2) {
            uint32_t h, l; split2(outv[j], outv[j + 1], h, l);
            *(uint32_t*)&oh[base + j] = h;
            *(uint32_t*)&ol[base + j] = l;
        }
    }
}

// ---------------- expert GEMM 1: h = gelu(an @ W1[e]) ------
__global__ __launch_bounds__(256, 2) void wm_egemm1h_kernel(const float* __restrict__ re_b1)
{
    int e = blockIdx.z;
    int cnt = g_cnt[e];
    int mb = blockIdx.y * 128;
    if (mb >= cnt) return;
    int off = g_off[e];
    int nb = blockIdx.x * 128;
    WM_PROLOGUE((mb + tid < cnt) ? g_slot_tok[off + mb + tid] : -1)
    wm_mainloop_h(g_anf,
                  g_r1hh + (size_t)e * (Dd * INTERi), g_r1hl + (size_t)e * (Dd * INTERi),
                  nb, s_rowmap, dynsm, accs);
    const float* bias = re_b1 + e * INTERi;
    EPI_VARS
    int row = mb + em;
    if (row < cnt) {
        __half2* hrow = (__half2*)(g_hf + (size_t)(off + row) * INTERi + nb + en);
#pragma unroll
        for (int j = 0; j < 64; j += 2) {
            int n = nb + en + j;
            float v0 = gelu_f(crow[j]     + bias[n]);
            float v1 = gelu_f(crow[j + 1] + bias[n + 1]);
            hrow[j >> 1] = __floats2half2_rn(v0, v1);
        }
    }
}

// ---------------- expert GEMM 2 ----------------
__global__ __launch_bounds__(256, 2) void wm_egemm2h_kernel(const float* __restrict__ re_b2)
{
    int e = blockIdx.z;
    int cnt = g_cnt[e];
    int mb = blockIdx.y * 128;
    if (mb >= cnt) return;
    int off = g_off[e];
    int nb = blockIdx.x * 128;
    WM_PROLOGUE((mb + tid < cnt) ? (off + mb + tid) : -1)
    wm_mainloop_h(g_hf,
                  g_r2hh + (size_t)e * (INTERi * Dd), g_r2hl + (size_t)e * (INTERi * Dd),
                  nb, s_rowmap, dynsm, accs);
    const float* bias = re_b2 + e * Dd;
    EPI_VARS
    int row = mb + em;
    if (row < cnt) {
        int slot = off + row;
        int tok = g_slot_tok[slot];
        int rnk = g_slot_rank[slot];
        float gate = g_slot_gate[slot];
        float* outp = g_part + (size_t)(tok * 3 + rnk) * Dd + nb + en;
#pragma unroll
        for (int j = 0; j < 64; j += 4) {
            int n = nb + en + j;
            float4 v;
            v.x = gate * (crow[j+0] + bias[n+0]);
            v.y = gate * (crow[j+1] + bias[n+1]);
            v.z = gate * (crow[j+2] + bias[n+2]);
            v.w = gate * (crow[j+3] + bias[n+3]);
            *(float4*)(outp + j) = v;
        }
    }
}

// ================= tensor-core flash attention (unchanged math) ==========
#define LDT 72
#define LDS_ 68
#define AQ_H 0
#define AQ_L 18432
#define AKOF(s)  (36864 + (s)*36864)
#define AVOF(s)  (AKOF(s) + 18432)
#define AS_OFF 110592
#define AP_H   145408
#define AP_L   163840
#define AM_OFF 182272
#define AL_OFF 182784
#define AC_OFF 183296
#define ATTN_SMEM 183808

__device__ __forceinline__ void attn_fill_kv(char* sm, int s, int grow, int tid) {
    const bf16* srcs[4] = {g_ksh, g_ksl, g_vsh, g_vsl};
    uint32_t dsts[4] = {(uint32_t)AKOF(s), (uint32_t)(AKOF(s) + 9216),
                        (uint32_t)AVOF(s), (uint32_t)(AVOF(s) + 9216)};
#pragma unroll
    for (int j = 0; j < 8; j++) {
        int id = tid + j * 256;
        int sel = id >> 9, rc = id & 511;
        int row = rc >> 3, cq = rc & 7;
        __pipeline_memcpy_async(sm + dsts[sel] + row * 144 + cq * 16,
                                srcs[sel] + (size_t)(grow + row) * 64 + cq * 8, 16);
    }
}

__global__ __launch_bounds__(256) void attn2_kernel() {
    extern __shared__ __align__(16) char sm[];
    int tid = threadIdx.x, wid = tid >> 5, lane = tid & 31;
    int bh = blockIdx.y;
    int qbase = (int)(gridDim.x - 1 - blockIdx.x) * 128;
    int qrow0 = bh * Ss + qbase;
    uint32_t smb = s2u(sm);

#pragma unroll
    for (int j = 0; j < 8; j++) {
        int id = tid + j * 256;
        int sel = id >> 10, rc = id & 1023;
        int row = rc >> 3, cq = rc & 7;
        const bf16* src = sel ? g_qsl : g_qsh;
        __pipeline_memcpy_async(sm + (sel ? AQ_L : AQ_H) + row * 144 + cq * 16,
                                src + (size_t)(qrow0 + row) * 64 + cq * 8, 16);
    }
    attn_fill_kv(sm, 0, bh * Ss, tid);
    __pipeline_commit();

    float* s_m = (float*)(sm + AM_OFF);
    float* s_l = (float*)(sm + AL_OFF);
    float* s_c = (float*)(sm + AC_OFF);
    if (tid < 128) { s_m[tid] = -1e30f; s_l[tid] = 0.f; }

    float O[8][4];
#pragma unroll
    for (int i = 0; i < 8; i++)
#pragma unroll
        for (int j = 0; j < 4; j++) O[i][j] = 0.f;

    int ntiles = qbase / 64 + 2;
    int row_lo = lane >> 2, row_hi = row_lo + 8;

    for (int t = 0; t < ntiles; t++) {
        int stg = t & 1;
        if (t + 1 < ntiles) {
            attn_fill_kv(sm, (t + 1) & 1, bh * Ss + (t + 1) * 64, tid);
            __pipeline_commit();
            __pipeline_wait_prior(1);
        } else {
            __pipeline_wait_prior(0);
        }
        __syncthreads();

        float Sfr[8][4];
#pragma unroll
        for (int i = 0; i < 8; i++)
#pragma unroll
            for (int j = 0; j < 4; j++) Sfr[i][j] = 0.f;
        uint32_t arow = (uint32_t)(wid * 16 + (lane & 15)) * 144 + (uint32_t)(lane >> 4) * 16;
#pragma unroll
        for (int k = 0; k < 4; k++) {
            uint32_t ah0, ah1, ah2, ah3, al0, al1, al2, al3;
            ldsm4(ah0, ah1, ah2, ah3, smb + AQ_H + arow + k * 32);
            ldsm4(al0, al1, al2, al3, smb + AQ_L + arow + k * 32);
            uint32_t brow = (uint32_t)(lane & 15) * 144 + (uint32_t)(lane >> 4) * 16 + k * 32;
#pragma unroll
            for (int j = 0; j < 4; j++) {
                uint32_t kh0, kh1, kh2, kh3, kl0, kl1, kl2, kl3;
                ldsm4(kh0, kh1, kh2, kh3, smb + AKOF(stg) + brow + (uint32_t)j * 16 * 144);
                ldsm4(kl0, kl1, kl2, kl3, smb + AKOF(stg) + 9216 + brow + (uint32_t)j * 16 * 144);
                mma16816(Sfr[j*2],   ah0, ah1, ah2, ah3, kh0, kh2);
                mma16816(Sfr[j*2],   ah0, ah1, ah2, ah3, kl0, kl2);
                mma16816(Sfr[j*2],   al0, al1, al2, al3, kh0, kh2);
                mma16816(Sfr[j*2+1], ah0, ah1, ah2, ah3, kh1, kh3);
                mma16816(Sfr[j*2+1], ah0, ah1, ah2, ah3, kl1, kl3);
                mma16816(Sfr[j*2+1], al0, al1, al2, al3, kh1, kh3);
            }
        }
        float* sS = (float*)(sm + AS_OFF);
        {
            int r0 = wid * 16 + row_lo, r1 = wid * 16 + row_hi;
            int c0 = (lane & 3) * 2;
#pragma unroll
            for (int nf = 0; nf < 8; nf++) {
                sS[r0 * LDS_ + nf * 8 + c0]     = Sfr[nf][0] * 0.125f;
                sS[r0 * LDS_ + nf * 8 + c0 + 1] = Sfr[nf][1] * 0.125f;
                sS[r1 * LDS_ + nf * 8 + c0]     = Sfr[nf][2] * 0.125f;
                sS[r1 * LDS_ + nf * 8 + c0 + 1] = Sfr[nf][3] * 0.125f;
            }
        }
        __syncthreads();

        {
            int row = tid >> 1, half = tid & 1;
            float* srow = (float*)(sm + AS_OFF) + row * LDS_ + half * 32;
            int qglob = qbase + row;
            int kbase = t * 64 + half * 32;
            float sv[32];
#pragma unroll
            for (int c = 0; c < 32; c++) {
                float s_ = srow[c];
                if (kbase + c > qglob) s_ = -1e30f;
                sv[c] = s_;
            }
            float tmax = -1e30f;
#pragma unroll
            for (int c = 0; c < 32; c++) tmax = fmaxf(tmax, sv[c]);
            tmax = fmaxf(tmax, __shfl_xor_sync(0xffffffffu, tmax, 1));
            float mo = s_m[row];
            float nm = fmaxf(mo, tmax);
            float corr = __expf(mo - nm);
            float sum = 0.f;
            uint32_t* ph = (uint32_t*)(sm + AP_H) + (row * LDT + half * 32) / 2;
            uint32_t* pl = (uint32_t*)(sm + AP_L) + (row * LDT + half * 32) / 2;
#pragma unroll
            for (int c = 0; c < 32; c += 2) {
                float p0 = __expf(sv[c] - nm);
                float p1 = __expf(sv[c + 1] - nm);
                sum += p0 + p1;
                uint32_t h, l; split2(p0, p1, h, l);
                ph[c >> 1] = h; pl[c >> 1] = l;
            }
            sum += __shfl_xor_sync(0xffffffffu, sum, 1);
            if (half == 0) {
                s_m[row] = nm;
                s_l[row] = s_l[row] * corr + sum;
                s_c[row] = corr;
            }
        }
        __syncthreads();

        {
            float c_lo = s_c[wid * 16 + row_lo];
            float c_hi = s_c[wid * 16 + row_hi];
#pragma unroll
            for (int nf = 0; nf < 8; nf++) {
                O[nf][0] *= c_lo; O[nf][1] *= c_lo;
                O[nf][2] *= c_hi; O[nf][3] *= c_hi;
            }
        }
#pragma unroll
        for (int k = 0; k < 4; k++) {
            uint32_t ph0, ph1, ph2, ph3, pl0, pl1, pl2, pl3;
            ldsm4(ph0, ph1, ph2, ph3, smb + AP_H + arow + k * 32);
            ldsm4(pl0, pl1, pl2, pl3, smb + AP_L + arow + k * 32);
            uint32_t vrow = (uint32_t)(k * 16 + (lane & 7) + ((lane >> 3) & 1) * 8) * 144
                          + (uint32_t)((lane >> 4) & 1) * 16;
#pragma unroll
            for (int j = 0; j < 4; j++) {
                uint32_t vh0, vh1, vh2, vh3, vl0, vl1, vl2, vl3;
                ldsm4t(vh0, vh1, vh2, vh3, smb + AVOF(stg) + vrow + (uint32_t)j * 32);
                ldsm4t(vl0, vl1, vl2, vl3, smb + AVOF(stg) + 9216 + vrow + (uint32_t)j * 32);
                mma16816(O[j*2],   ph0, ph1, ph2, ph3, vh0, vh1);
                mma16816(O[j*2],   ph0, ph1, ph2, ph3, vl0, vl1);
                mma16816(O[j*2],   pl0, pl1, pl2, pl3, vh0, vh1);
                mma16816(O[j*2+1], ph0, ph1, ph2, ph3, vh2, vh3);
                mma16816(O[j*2+1], ph0, ph1, ph2, ph3, vl2, vl3);
                mma16816(O[j*2+1], pl0, pl1, pl2, pl3, vh2, vh3);
            }
        }
        __syncthreads();
    }

    // epilogue: O/l -> ctx fp16
    {
        int b = bh >> 4, h = bh & 15;
        float linv0 = 1.f / s_l[wid * 16 + row_lo];
        float linv1 = 1.f / s_l[wid * 16 + row_hi];
        int q0 = qbase + wid * 16 + row_lo;
        int q1 = qbase + wid * 16 + row_hi;
        size_t base0 = (size_t)(b * Ss + q0) * 1024 + h * 64;
        size_t base1 = (size_t)(b * Ss + q1) * 1024 + h * 64;
        int c0 = (lane & 3) * 2;
#pragma unroll
        for (int nf = 0; nf < 8; nf++) {
            int col = nf * 8 + c0;
            *(__half2*)&g_ctxf[base0 + col] = __floats2half2_rn(O[nf][0] * linv0, O[nf][1] * linv0);
            *(__half2*)&g_ctxf[base1 + col] = __floats2half2_rn(O[nf][2] * linv1, O[nf][3] * linv1);
        }
    }
}

// ---------------- small kernels ----------------
__global__ void reset_kernel() {
    int t = threadIdx.x;
    if (t < Ee) { g_cnt[t] = 0; g_cur[t] = 0; }
}

__global__ void rmsnorm_kernel(const float* __restrict__ in,
                               const float* __restrict__ gamma,
                               float* __restrict__ out,
                               __half* __restrict__ ofh) {
    int row = blockIdx.x;
    const float* p = in + row * Dd;
    float ss = 0.f;
    for (int d = threadIdx.x; d < Dd; d += blockDim.x) { float v = p[d]; ss += v * v; }
    for (int o = 16; o; o >>= 1) ss += __shfl_xor_sync(0xffffffffu, ss, o);
    __shared__ float red[8];
    int w = threadIdx.x >> 5;
    if ((threadIdx.x & 31) == 0) red[w] = ss;
    __syncthreads();
    if (threadIdx.x < 8) {
        float v = red[threadIdx.x];
        for (int o = 4; o; o >>= 1) v += __shfl_xor_sync(0xffu, v, o);
        if (threadIdx.x == 0) red[0] = v;
    }
    __syncthreads();
    float rinv = rsqrtf(red[0] * (1.0f / Dd) + EPSf);
    for (int d = threadIdx.x * 2; d < Dd; d += blockDim.x * 2) {
        float v0 = p[d] * rinv * gamma[d];
        float v1 = p[d + 1] * rinv * gamma[d + 1];
        out[row * Dd + d]     = v0;
        out[row * Dd + d + 1] = v1;
        *(__half2*)&ofh[row * Dd + d] = __floats2half2_rn(v0, v1);
    }
}

__global__ void router_kernel(const float* __restrict__ an, const float* __restrict__ W,
                              const float* __restrict__ bias) {
    int tkn = blockIdx.x;
    __shared__ float xs[Dd];
    for (int d = threadIdx.x; d < Dd; d += 32) xs[d] = an[tkn * Dd + d];
    __syncwarp();
    int e = threadIdx.x;
    float logit = -1e30f;
    if (e < Ee) {
        float acc = bias[e];
        for (int d = 0; d < Dd; d++) acc += xs[d] * W[d * Ee + e];
        logit = acc;
    }
    float mx = logit;
    for (int o = 16; o; o >>= 1) mx = fmaxf(mx, __shfl_xor_sync(0xffffffffu, mx, o));
    float ex = (e < Ee) ? __expf(logit - mx) : 0.f;
    float sm = ex;
    for (int o = 16; o; o >>= 1) sm += __shfl_xor_sync(0xffffffffu, sm, o);
    float pw = ex / sm;
    for (int it = 0; it < 3; it++) {
        float bv = pw; int bi = e;
        for (int o = 16; o; o >>= 1) {
            float ov = __shfl_xor_sync(0xffffffffu, bv, o);
            int   oi = __shfl_xor_sync(0xffffffffu, bi, o);
            if (ov > bv || (ov == bv && oi < bi)) { bv = ov; bi = oi; }
        }
        if (threadIdx.x == 0) {
            g_topi[tkn * 3 + it] = bi;
            g_topv[tkn * 3 + it] = bv;
            atomicAdd(&g_cnt[bi], 1);
        }
        if (e == bi) pw = -1.f;
    }
}

__global__ void scan_kernel() {
    if (threadIdx.x == 0) {
        int s = 0;
        for (int e = 0; e < Ee; e++) { g_off[e] = s; s += g_cnt[e]; }
    }
}

__global__ void fill_kernel() {
    int i = blockIdx.x * 256 + threadIdx.x;
    if (i >= SLOTS) return;
    int tkn = i / 3, r = i - tkn * 3;
    int e = g_topi[i];
    int pos = atomicAdd(&g_cur[e], 1);
    int slot = g_off[e] + pos;
    g_slot_tok[slot] = tkn;
    g_slot_rank[slot] = r;
    g_slot_gate[slot] = g_topv[i];
}

__global__ void final_kernel(float* __restrict__ out) {
    int i = blockIdx.x * 256 + threadIdx.x;
    int t = i >> 10, n = i & 1023;
    float v = out[i];
    v += g_part[(size_t)(t * 3 + 0) * Dd + n];
    v += g_part[(size_t)(t * 3 + 1) * Dd + n];
    v += g_part[(size_t)(t * 3 + 2) * Dd + n];
    out[i] = v;
}

// ---------------- launch ----------------
extern "C" void kernel_launch(void* const* d_in, const int* in_sizes, int n_in,
                              void* d_out, int out_size) {
    const float* x      = (const float*)d_in[0];
    const float* theta  = (const float*)d_in[2];
    const float* gamma1 = (const float*)d_in[3];
    const float* gamma2 = (const float*)d_in[4];
    const float* q_w  = (const float*)d_in[5];  const float* q_b  = (const float*)d_in[6];
    const float* k_w  = (const float*)d_in[7];  const float* k_b  = (const float*)d_in[8];
    const float* v_w  = (const float*)d_in[9];  const float* v_b  = (const float*)d_in[10];
    const float* o_w  = (const float*)d_in[11]; const float* o_b  = (const float*)d_in[12];
    const float* r_w  = (const float*)d_in[13]; const float* r_b  = (const float*)d_in[14];
    const float* sw1  = (const float*)d_in[15]; const float* sb1  = (const float*)d_in[16];
    const float* sw2  = (const float*)d_in[17]; const float* sb2  = (const float*)d_in[18];
    const float* rw1  = (const float*)d_in[19]; const float* rb1  = (const float*)d_in[20];
    const float* rw2  = (const float*)d_in[21]; const float* rb2  = (const float*)d_in[22];
    float* out = (float*)d_out;

    float *xn, *attn, *an;
    __half *xnf, *ctxf, *anf, *t1f;
    __half *qwh, *qwl, *kwh, *kwl, *vwh, *vwl, *owh, *owl, *s1h, *s1l, *s2h, *s2l;
    __half *r1hh, *r1hl, *r2hh, *r2hl;
    cudaGetSymbolAddress((void**)&xn,   g_xn);
    cudaGetSymbolAddress((void**)&attn, g_attn);
    cudaGetSymbolAddress((void**)&an,   g_an);
    cudaGetSymbolAddress((void**)&xnf,  g_xnf);
    cudaGetSymbolAddress((void**)&ctxf, g_ctxf);
    cudaGetSymbolAddress((void**)&anf,  g_anf);
    cudaGetSymbolAddress((void**)&t1f,  g_t1f);
    cudaGetSymbolAddress((void**)&qwh,  g_qwh);  cudaGetSymbolAddress((void**)&qwl, g_qwl);
    cudaGetSymbolAddress((void**)&kwh,  g_kwh);  cudaGetSymbolAddress((void**)&kwl, g_kwl);
    cudaGetSymbolAddress((void**)&vwh,  g_vwh);  cudaGetSymbolAddress((void**)&vwl, g_vwl);
    cudaGetSymbolAddress((void**)&owh,  g_owh);  cudaGetSymbolAddress((void**)&owl, g_owl);
    cudaGetSymbolAddress((void**)&s1h,  g_s1h);  cudaGetSymbolAddress((void**)&s1l, g_s1l);
    cudaGetSymbolAddress((void**)&s2h,  g_s2h);  cudaGetSymbolAddress((void**)&s2l, g_s2l);
    cudaGetSymbolAddress((void**)&r1hh, g_r1hh); cudaGetSymbolAddress((void**)&r1hl, g_r1hl);
    cudaGetSymbolAddress((void**)&r2hh, g_r2hh); cudaGetSymbolAddress((void**)&r2hl, g_r2hl);

    cudaFuncSetAttribute(wm_gemm_h_kernel,   cudaFuncAttributeMaxDynamicSharedMemorySize, DYN_SMEM);
    cudaFuncSetAttribute(wm_qkv_h_kernel,    cudaFuncAttributeMaxDynamicSharedMemorySize, DYN_SMEM);
    cudaFuncSetAttribute(wm_egemm1h_kernel,  cudaFuncAttributeMaxDynamicSharedMemorySize, DYN_SMEM);
    cudaFuncSetAttribute(wm_egemm2h_kernel,  cudaFuncAttributeMaxDynamicSharedMemorySize, DYN_SMEM);
    cudaFuncSetAttribute(attn2_kernel,       cudaFuncAttributeMaxDynamicSharedMemorySize, ATTN_SMEM);

    static cudaStream_t s1 = nullptr;
    static cudaEvent_t evFork = nullptr, evOW = nullptr, evAN = nullptr, evPART = nullptr;
    if (!s1) {
        cudaStreamCreateWithFlags(&s1, cudaStreamNonBlocking);
        cudaEventCreateWithFlags(&evFork, cudaEventDisableTiming);
        cudaEventCreateWithFlags(&evOW,   cudaEventDisableTiming);
        cudaEventCreateWithFlags(&evAN,   cudaEventDisableTiming);
        cudaEventCreateWithFlags(&evPART, cudaEventDisableTiming);
    }

    dim3 thr(256);
    dim3 grid8x16(8, 16);

    // ---- fork: o/sh1/sh2 + expert conversions on s1 ----
    cudaEventRecord(evFork, 0);
    cudaStreamWaitEvent(s1, evFork, 0);
    convh3_kernel<<<dim3(D4 / 1024, 3), 256, 0, s1>>>(
        (const float4*)o_w, (const float4*)sw1, (const float4*)sw2,
        (uint2*)owh, (uint2*)s1h, (uint2*)s2h,
        (uint2*)owl, (uint2*)s1l, (uint2*)s2l);
    cudaEventRecord(evOW, s1);
    convh_kernel<<<(E4 + 1023) / 1024, 256, 0, s1>>>((const float4*)rw1, (uint2*)r1hh, (uint2*)r1hl, E4);
    convh_kernel<<<(E4 + 1023) / 1024, 256, 0, s1>>>((const float4*)rw2, (uint2*)r2hh, (uint2*)r2hl, E4);

    // ---- main path ----
    convh3_kernel<<<dim3(D4 / 1024, 3), 256>>>(
        (const float4*)q_w, (const float4*)k_w, (const float4*)v_w,
        (uint2*)qwh, (uint2*)kwh, (uint2*)vwh,
        (uint2*)qwl, (uint2*)kwl, (uint2*)vwl);
    reset_kernel<<<1, 32>>>();
    rmsnorm_kernel<<<NT, 256>>>(x, gamma1, xn, xnf);

    wm_qkv_h_kernel<<<dim3(8, 16, 3), thr, DYN_SMEM>>>(q_b, k_b, v_b, theta);

    attn2_kernel<<<dim3(8, Bb * Hh), 256, ATTN_SMEM>>>();

    cudaStreamWaitEvent(0, evOW, 0);
    wm_gemm_h_kernel<<<grid8x16, thr, DYN_SMEM>>>(ctxf, owh, owl, o_b, 2, xn, nullptr,
                                                  attn, nullptr);
    rmsnorm_kernel<<<NT, 256>>>(attn, gamma2, an, anf);
    cudaEventRecord(evAN, 0);

    // ---- expert path on s1 ----
    cudaStreamWaitEvent(s1, evAN, 0);
    router_kernel<<<NT, 32, 0, s1>>>(an, r_w, r_b);
    scan_kernel<<<1, 32, 0, s1>>>();
    fill_kernel<<<(SLOTS + 255) / 256, 256, 0, s1>>>();
    wm_egemm1h_kernel<<<dim3(8, 16, Ee), thr, DYN_SMEM, s1>>>(rb1);
    wm_egemm2h_kernel<<<dim3(8, 16, Ee), thr, DYN_SMEM, s1>>>(rb2);
    cudaEventRecord(evPART, s1);

    // ---- shared MLP concurrent on s0 ----
    wm_gemm_h_kernel<<<grid8x16, thr, DYN_SMEM>>>(anf, s1h, s1l, sb1, 1, nullptr, nullptr,
                                                  nullptr, t1f);
    wm_gemm_h_kernel<<<grid8x16, thr, DYN_SMEM>>>(t1f, s2h, s2l, sb2, 2, an, attn,
                                                  out, nullptr);

    // ---- join + final ----
    cudaStreamWaitEvent(0, evPART, 0);
    final_kernel<<<(NT * Dd) / 256, 256>>>(out);
}

// round 17
// speedup vs baseline: 4.7536x; 1.3417x over previous
#include <cuda_runtime.h>
#include <cuda_bf16.h>
#include <cuda_fp16.h>
#include <cuda_pipeline.h>
#include <mma.h>
#include <cstdint>

using namespace nvcuda;

#define Bb     2
#define Ss     1024
#define Dd     1024
#define Hh     16
#define HDh    64
#define NT     (Bb*Ss)
#define Ee     31
#define INTERi 1024
#define EPSf   1e-5f
#define SLOTS  (NT*3)

typedef __nv_bfloat16 bf16;

// ---------------- fp32 scratch ----------------
__device__ float g_xn  [NT*Dd];
__device__ float g_attn[NT*Dd];
__device__ float g_an  [NT*Dd];
__device__ float g_part[SLOTS*Dd];
__device__ int   g_topi[SLOTS];
__device__ float g_topv[SLOTS];
__device__ int   g_cnt[Ee];
__device__ int   g_off[Ee];
__device__ int   g_cur[Ee];
__device__ int   g_slot_tok [SLOTS];
__device__ int   g_slot_rank[SLOTS];
__device__ float g_slot_gate[SLOTS];

// ---------------- bf16 hi/lo attention activations ----------------
__device__ bf16 g_qsh[NT*Dd],  g_qsl[NT*Dd];
__device__ bf16 g_ksh[NT*Dd],  g_ksl[NT*Dd];
__device__ bf16 g_vsh[NT*Dd],  g_vsl[NT*Dd];

// ---------------- fp16 activations ----------------
__device__ __half g_xnf[NT*Dd];
__device__ __half g_ctxf[NT*Dd];
__device__ __half g_anf[NT*Dd];
__device__ __half g_t1f[NT*INTERi];
__device__ __half g_hf [SLOTS*INTERi];

// ---------------- plain fp16 weights ----------------
__device__ __half g_qw[Dd*Dd], g_kw[Dd*Dd], g_vw[Dd*Dd], g_ow[Dd*Dd];
__device__ __half g_s1[Dd*INTERi], g_s2[INTERi*Dd];
__device__ __half g_r1[Ee*Dd*INTERi];
__device__ __half g_r2[Ee*INTERi*Dd];

__device__ __forceinline__ float gelu_f(float v) {
    return 0.5f * v * (1.0f + erff(v * 0.70710678118654752f));
}

__device__ __forceinline__ void split2(float x, float y, uint32_t& hi, uint32_t& lo) {
    bf16 hx = __float2bfloat16(x), hy = __float2bfloat16(y);
    bf16 lx = __float2bfloat16(x - __bfloat162float(hx));
    bf16 ly = __float2bfloat16(y - __bfloat162float(hy));
    __nv_bfloat162 H = __halves2bfloat162(hx, hy);
    __nv_bfloat162 L = __halves2bfloat162(lx, ly);
    hi = *(uint32_t*)&H; lo = *(uint32_t*)&L;
}

__device__ __forceinline__ uint32_t s2u(const void* p) {
    uint32_t a;
    asm("{ .reg .u64 t; cvta.to.shared.u64 t, %1; cvt.u32.u64 %0, t; }" : "=r"(a) : "l"(p));
    return a;
}

// ---------------- raw mma/ldmatrix helpers (attention) ----------------
__device__ __forceinline__ void ldsm4(uint32_t& r0, uint32_t& r1, uint32_t& r2, uint32_t& r3, uint32_t addr) {
    asm volatile("ldmatrix.sync.aligned.m8n8.x4.shared.b16 {%0,%1,%2,%3}, [%4];"
        : "=r"(r0), "=r"(r1), "=r"(r2), "=r"(r3) : "r"(addr));
}
__device__ __forceinline__ void ldsm4t(uint32_t& r0, uint32_t& r1, uint32_t& r2, uint32_t& r3, uint32_t addr) {
    asm volatile("ldmatrix.sync.aligned.m8n8.x4.trans.shared.b16 {%0,%1,%2,%3}, [%4];"
        : "=r"(r0), "=r"(r1), "=r"(r2), "=r"(r3) : "r"(addr));
}
__device__ __forceinline__ void mma16816(float* c, uint32_t a0, uint32_t a1, uint32_t a2, uint32_t a3,
                                         uint32_t b0, uint32_t b1) {
    asm volatile("mma.sync.aligned.m16n8k16.row.col.f32.bf16.bf16.f32 "
        "{%0,%1,%2,%3},{%4,%5,%6,%7},{%8,%9},{%0,%1,%2,%3};"
        : "+f"(c[0]), "+f"(c[1]), "+f"(c[2]), "+f"(c[3])
        : "r"(a0), "r"(a1), "r"(a2), "r"(a3), "r"(b0), "r"(b1));
}

// ---------------- weight conversion (plain fp16) ----------------
#define D4 (Dd*Dd/4)
#define E4 (Ee*Dd*INTERi/4)

__global__ void convf_kernel(const float4* __restrict__ src,
                             uint2* __restrict__ dst, int n4) {
    int base = blockIdx.x * 1024 + threadIdx.x;
    float4 v[4]; int idx[4]; bool ok[4];
#pragma unroll
    for (int j = 0; j < 4; j++) {
        idx[j] = base + j * 256;
        ok[j] = idx[j] < n4;
        if (ok[j]) v[j] = src[idx[j]];
    }
#pragma unroll
    for (int j = 0; j < 4; j++) {
        if (!ok[j]) continue;
        __half2 a = __floats2half2_rn(v[j].x, v[j].y);
        __half2 b = __floats2half2_rn(v[j].z, v[j].w);
        dst[idx[j]] = make_uint2(*(uint32_t*)&a, *(uint32_t*)&b);
    }
}

__global__ void convf3_kernel(
    const float4* s0, const float4* s1, const float4* s2,
    uint2* d0, uint2* d1, uint2* d2)
{
    const float4* srcs[3] = {s0, s1, s2};
    uint2* ds[3] = {d0, d1, d2};
    int w = blockIdx.y;
    const float4* src = srcs[w];
    uint2* dst = ds[w];
    int base = blockIdx.x * 1024 + threadIdx.x;
    float4 v[4];
#pragma unroll
    for (int j = 0; j < 4; j++) v[j] = src[base + j * 256];
#pragma unroll
    for (int j = 0; j < 4; j++) {
        __half2 a = __floats2half2_rn(v[j].x, v[j].y);
        __half2 b = __floats2half2_rn(v[j].z, v[j].w);
        dst[base + j * 256] = make_uint2(*(uint32_t*)&a, *(uint32_t*)&b);
    }
}

// ================= plain fp16 GEMM core =================
typedef wmma::fragment<wmma::accumulator, 16, 16, 16, float> FragC;
typedef wmma::fragment<wmma::matrix_a, 16, 16, 16, __half, wmma::row_major> FragAH;
typedef wmma::fragment<wmma::matrix_b, 16, 16, 16, __half, wmma::row_major> FragBH;

#define LDA 40
#define LDB 136
#define LDC 132
#define F_OFF_A 0
#define F_OFF_B 10240
#define F_STAGE 18944
#define DYN_SMEM 67584     // epilogue staging (128*132*4) dominates

__device__ __forceinline__ void stage_fill_f(
    const __half* __restrict__ Ag, const __half* __restrict__ Bg,
    int nb, int k0, const int* rowmap, char* st, int tid)
{
#pragma unroll
    for (int i = 0; i < 2; i++) {
        int id = tid + i * 256;
        int row = id >> 2, q = id & 3;
        int r = rowmap[row];
        char* da = st + F_OFF_A + row * (LDA * 2) + q * 16;
        if (r >= 0)
            __pipeline_memcpy_async(da, Ag + (size_t)r * 1024 + k0 + q * 8, 16);
        else
            *(uint4*)da = make_uint4(0u, 0u, 0u, 0u);
    }
#pragma unroll
    for (int i = 0; i < 2; i++) {
        int id = tid + i * 256;
        int k = id >> 4, q = id & 15;
        __pipeline_memcpy_async(st + F_OFF_B + k * (LDB * 2) + q * 16,
                                Bg + (size_t)(k0 + k) * 1024 + nb + q * 8, 16);
    }
}

__device__ __forceinline__ void wm_mainloop_f(
    const __half* __restrict__ Ag, const __half* __restrict__ Bg,
    int nb, const int* rowmap, char* sm, FragC accs[4][2])
{
    int tid = threadIdx.x, wid = tid >> 5;
    int wm = wid & 1, wn = wid >> 1;
#pragma unroll
    for (int mt = 0; mt < 4; mt++)
#pragma unroll
        for (int nt = 0; nt < 2; nt++)
            wmma::fill_fragment(accs[mt][nt], 0.0f);

    stage_fill_f(Ag, Bg, nb, 0, rowmap, sm, tid);
    __pipeline_commit();

    for (int t = 0; t < 32; t++) {
        char* cur = sm + (t & 1) * F_STAGE;
        if (t < 31) {
            stage_fill_f(Ag, Bg, nb, (t + 1) * 32, rowmap,
                         sm + ((t + 1) & 1) * F_STAGE, tid);
            __pipeline_commit();
            __pipeline_wait_prior(1);
        } else {
            __pipeline_wait_prior(0);
        }
        __syncthreads();
        const __half* Ah = (const __half*)(cur + F_OFF_A);
        const __half* Bh = (const __half*)(cur + F_OFF_B);
#pragma unroll
        for (int ks = 0; ks < 2; ks++) {
            FragBH b0, b1;
            const __half* bbase = Bh + (ks * 16) * LDB + wn * 32;
            wmma::load_matrix_sync(b0, bbase,      LDB);
            wmma::load_matrix_sync(b1, bbase + 16, LDB);
#pragma unroll
            for (int mt = 0; mt < 4; mt++) {
                FragAH ah;
                wmma::load_matrix_sync(ah, Ah + (wm * 64 + mt * 16) * LDA + ks * 16, LDA);
                wmma::mma_sync(accs[mt][0], ah, b0, accs[mt][0]);
                wmma::mma_sync(accs[mt][1], ah, b1, accs[mt][1]);
            }
        }
        __syncthreads();
    }
    float* Cs = (float*)sm;
#pragma unroll
    for (int mt = 0; mt < 4; mt++)
#pragma unroll
        for (int nt = 0; nt < 2; nt++)
            wmma::store_matrix_sync(Cs + (wm * 64 + mt * 16) * LDC + wn * 32 + nt * 16,
                                    accs[mt][nt], LDC, wmma::mem_row_major);
    __syncthreads();
}

#define WM_PROLOGUE(ROWEXPR)                                                   \
    extern __shared__ __align__(16) char dynsm[];                              \
    __shared__ int s_rowmap[128];                                              \
    int tid = threadIdx.x;                                                     \
    if (tid < 128) s_rowmap[tid] = (ROWEXPR);                                  \
    __syncthreads();                                                           \
    FragC accs[4][2];

#define EPI_VARS                                                               \
    float* Cs = (float*)dynsm;                                                 \
    int em = tid >> 1;                                                         \
    int en = (tid & 1) * 64;                                                   \
    const float* crow = Cs + em * LDC + en;

// ---------------- dense GEMM: mode 0 plain->Cf, 1 gelu->Chf, 2 +res->Cf ---
__global__ __launch_bounds__(256, 2) void wm_gemm_f_kernel(
    const __half* __restrict__ Ag, const __half* __restrict__ Bg,
    const float* __restrict__ bias, int mode,
    const float* __restrict__ res1, const float* __restrict__ res2,
    float* __restrict__ Cf, __half* __restrict__ Chf)
{
    int mb = blockIdx.y * 128, nb = blockIdx.x * 128;
    WM_PROLOGUE(mb + tid)
    wm_mainloop_f(Ag, Bg, nb, s_rowmap, dynsm, accs);
    EPI_VARS
    int m = mb + em;
    if (mode == 1) {
        __half2* orow = (__half2*)(Chf + (size_t)m * 1024 + nb + en);
#pragma unroll
        for (int j = 0; j < 64; j += 2) {
            int n = nb + en + j;
            float v0 = gelu_f(crow[j]     + bias[n]);
            float v1 = gelu_f(crow[j + 1] + bias[n + 1]);
            orow[j >> 1] = __floats2half2_rn(v0, v1);
        }
    } else {
        float* orow = Cf + (size_t)m * 1024 + nb + en;
#pragma unroll
        for (int j = 0; j < 64; j += 4) {
            int n = nb + en + j;
            float4 v;
            v.x = crow[j+0] + bias[n+0];
            v.y = crow[j+1] + bias[n+1];
            v.z = crow[j+2] + bias[n+2];
            v.w = crow[j+3] + bias[n+3];
            if (mode == 2) {
                float4 r = *(const float4*)(res1 + (size_t)m * 1024 + n);
                v.x += r.x; v.y += r.y; v.z += r.z; v.w += r.w;
                if (res2) {
                    float4 r2 = *(const float4*)(res2 + (size_t)m * 1024 + n);
                    v.x += r2.x; v.y += r2.y; v.z += r2.z; v.w += r2.w;
                }
            }
            *(float4*)(orow + j) = v;
        }
    }
}

// ---------------- fused QKV GEMM + RoPE ----------------
__global__ __launch_bounds__(256, 2) void wm_qkv_f_kernel(
    const float* __restrict__ qbias, const float* __restrict__ kbias,
    const float* __restrict__ vbias, const float* __restrict__ theta)
{
    const __half* Bg; const float* bias;
    if (blockIdx.z == 0)      { Bg = g_qw; bias = qbias; }
    else if (blockIdx.z == 1) { Bg = g_kw; bias = kbias; }
    else                      { Bg = g_vw; bias = vbias; }
    int mb = blockIdx.y * 128, nb = blockIdx.x * 128;
    WM_PROLOGUE(mb + tid)
    wm_mainloop_f(g_xnf, Bg, nb, s_rowmap, dynsm, accs);
    EPI_VARS
    int m = mb + em;
    int b = m >> 10, s = m & 1023;
    int n0 = nb + en;
    int hh = n0 >> 6;
    size_t base = ((size_t)(b * Hh + hh) * Ss + s) * 64;
    if (blockIdx.z == 2) {
#pragma unroll
        for (int j = 0; j < 64; j += 2) {
            int n = n0 + j;
            float v0 = crow[j]     + bias[n];
            float v1 = crow[j + 1] + bias[n + 1];
            uint32_t h, l; split2(v0, v1, h, l);
            *(uint32_t*)&g_vsh[base + j] = h;
            *(uint32_t*)&g_vsl[base + j] = l;
        }
    } else {
        bf16* oh = (blockIdx.z == 0) ? g_qsh : g_ksh;
        bf16* ol = (blockIdx.z == 0) ? g_qsl : g_ksl;
        float outv[64];
#pragma unroll
        for (int i = 0; i < 32; i++) {
            float x1 = crow[2 * i]     + bias[n0 + 2 * i];
            float x2 = crow[2 * i + 1] + bias[n0 + 2 * i + 1];
            float sn, c;
            sincosf((float)s * theta[i], &sn, &c);
            outv[i]      = x1 * c - x2 * sn;
            outv[32 + i] = x1 * sn + x2 * c;
        }
#pragma unroll
        for (int j = 0; j < 64; j += 2) {
            uint32_t h, l; split2(outv[j], outv[j + 1], h, l);
            *(uint32_t*)&oh[base + j] = h;
            *(uint32_t*)&ol[base + j] = l;
        }
    }
}

// ---------------- expert GEMM 1 ----------------
__global__ __launch_bounds__(256, 2) void wm_egemm1f_kernel(const float* __restrict__ re_b1)
{
    int e = blockIdx.z;
    int cnt = g_cnt[e];
    int mb = blockIdx.y * 128;
    if (mb >= cnt) return;
    int off = g_off[e];
    int nb = blockIdx.x * 128;
    WM_PROLOGUE((mb + tid < cnt) ? g_slot_tok[off + mb + tid] : -1)
    wm_mainloop_f(g_anf, g_r1 + (size_t)e * (Dd * INTERi), nb, s_rowmap, dynsm, accs);
    const float* bias = re_b1 + e * INTERi;
    EPI_VARS
    int row = mb + em;
    if (row < cnt) {
        __half2* hrow = (__half2*)(g_hf + (size_t)(off + row) * INTERi + nb + en);
#pragma unroll
        for (int j = 0; j < 64; j += 2) {
            int n = nb + en + j;
            float v0 = gelu_f(crow[j]     + bias[n]);
            float v1 = gelu_f(crow[j + 1] + bias[n + 1]);
            hrow[j >> 1] = __floats2half2_rn(v0, v1);
        }
    }
}

// ---------------- expert GEMM 2 ----------------
__global__ __launch_bounds__(256, 2) void wm_egemm2f_kernel(const float* __restrict__ re_b2)
{
    int e = blockIdx.z;
    int cnt = g_cnt[e];
    int mb = blockIdx.y * 128;
    if (mb >= cnt) return;
    int off = g_off[e];
    int nb = blockIdx.x * 128;
    WM_PROLOGUE((mb + tid < cnt) ? (off + mb + tid) : -1)
    wm_mainloop_f(g_hf, g_r2 + (size_t)e * (INTERi * Dd), nb, s_rowmap, dynsm, accs);
    const float* bias = re_b2 + e * Dd;
    EPI_VARS
    int row = mb + em;
    if (row < cnt) {
        int slot = off + row;
        int tok = g_slot_tok[slot];
        int rnk = g_slot_rank[slot];
        float gate = g_slot_gate[slot];
        float* outp = g_part + (size_t)(tok * 3 + rnk) * Dd + nb + en;
#pragma unroll
        for (int j = 0; j < 64; j += 4) {
            int n = nb + en + j;
            float4 v;
            v.x = gate * (crow[j+0] + bias[n+0]);
            v.y = gate * (crow[j+1] + bias[n+1]);
            v.z = gate * (crow[j+2] + bias[n+2]);
            v.w = gate * (crow[j+3] + bias[n+3]);
            *(float4*)(outp + j) = v;
        }
    }
}

// ================= tensor-core flash attention (unchanged) ==========
#define LDT 72
#define LDS_ 68
#define AQ_H 0
#define AQ_L 18432
#define AKOF(s)  (36864 + (s)*36864)
#define AVOF(s)  (AKOF(s) + 18432)
#define AS_OFF 110592
#define AP_H   145408
#define AP_L   163840
#define AM_OFF 182272
#define AL_OFF 182784
#define AC_OFF 183296
#define ATTN_SMEM 183808

__device__ __forceinline__ void attn_fill_kv(char* sm, int s, int grow, int tid) {
    const bf16* srcs[4] = {g_ksh, g_ksl, g_vsh, g_vsl};
    uint32_t dsts[4] = {(uint32_t)AKOF(s), (uint32_t)(AKOF(s) + 9216),
                        (uint32_t)AVOF(s), (uint32_t)(AVOF(s) + 9216)};
#pragma unroll
    for (int j = 0; j < 8; j++) {
        int id = tid + j * 256;
        int sel = id >> 9, rc = id & 511;
        int row = rc >> 3, cq = rc & 7;
        __pipeline_memcpy_async(sm + dsts[sel] + row * 144 + cq * 16,
                                srcs[sel] + (size_t)(grow + row) * 64 + cq * 8, 16);
    }
}

__global__ __launch_bounds__(256) void attn2_kernel() {
    extern __shared__ __align__(16) char sm[];
    int tid = threadIdx.x, wid = tid >> 5, lane = tid & 31;
    int bh = blockIdx.y;
    int qbase = (int)(gridDim.x - 1 - blockIdx.x) * 128;
    int qrow0 = bh * Ss + qbase;
    uint32_t smb = s2u(sm);

#pragma unroll
    for (int j = 0; j < 8; j++) {
        int id = tid + j * 256;
        int sel = id >> 10, rc = id & 1023;
        int row = rc >> 3, cq = rc & 7;
        const bf16* src = sel ? g_qsl : g_qsh;
        __pipeline_memcpy_async(sm + (sel ? AQ_L : AQ_H) + row * 144 + cq * 16,
                                src + (size_t)(qrow0 + row) * 64 + cq * 8, 16);
    }
    attn_fill_kv(sm, 0, bh * Ss, tid);
    __pipeline_commit();

    float* s_m = (float*)(sm + AM_OFF);
    float* s_l = (float*)(sm + AL_OFF);
    float* s_c = (float*)(sm + AC_OFF);
    if (tid < 128) { s_m[tid] = -1e30f; s_l[tid] = 0.f; }

    float O[8][4];
#pragma unroll
    for (int i = 0; i < 8; i++)
#pragma unroll
        for (int j = 0; j < 4; j++) O[i][j] = 0.f;

    int ntiles = qbase / 64 + 2;
    int row_lo = lane >> 2, row_hi = row_lo + 8;

    for (int t = 0; t < ntiles; t++) {
        int stg = t & 1;
        if (t + 1 < ntiles) {
            attn_fill_kv(sm, (t + 1) & 1, bh * Ss + (t + 1) * 64, tid);
            __pipeline_commit();
            __pipeline_wait_prior(1);
        } else {
            __pipeline_wait_prior(0);
        }
        __syncthreads();

        float Sfr[8][4];
#pragma unroll
        for (int i = 0; i < 8; i++)
#pragma unroll
            for (int j = 0; j < 4; j++) Sfr[i][j] = 0.f;
        uint32_t arow = (uint32_t)(wid * 16 + (lane & 15)) * 144 + (uint32_t)(lane >> 4) * 16;
#pragma unroll
        for (int k = 0; k < 4; k++) {
            uint32_t ah0, ah1, ah2, ah3, al0, al1, al2, al3;
            ldsm4(ah0, ah1, ah2, ah3, smb + AQ_H + arow + k * 32);
            ldsm4(al0, al1, al2, al3, smb + AQ_L + arow + k * 32);
            uint32_t brow = (uint32_t)(lane & 15) * 144 + (uint32_t)(lane >> 4) * 16 + k * 32;
#pragma unroll
            for (int j = 0; j < 4; j++) {
                uint32_t kh0, kh1, kh2, kh3, kl0, kl1, kl2, kl3;
                ldsm4(kh0, kh1, kh2, kh3, smb + AKOF(stg) + brow + (uint32_t)j * 16 * 144);
                ldsm4(kl0, kl1, kl2, kl3, smb + AKOF(stg) + 9216 + brow + (uint32_t)j * 16 * 144);
                mma16816(Sfr[j*2],   ah0, ah1, ah2, ah3, kh0, kh2);
                mma16816(Sfr[j*2],   ah0, ah1, ah2, ah3, kl0, kl2);
                mma16816(Sfr[j*2],   al0, al1, al2, al3, kh0, kh2);
                mma16816(Sfr[j*2+1], ah0, ah1, ah2, ah3, kh1, kh3);
                mma16816(Sfr[j*2+1], ah0, ah1, ah2, ah3, kl1, kl3);
                mma16816(Sfr[j*2+1], al0, al1, al2, al3, kh1, kh3);
            }
        }
        float* sS = (float*)(sm + AS_OFF);
        {
            int r0 = wid * 16 + row_lo, r1 = wid * 16 + row_hi;
            int c0 = (lane & 3) * 2;
#pragma unroll
            for (int nf = 0; nf < 8; nf++) {
                sS[r0 * LDS_ + nf * 8 + c0]     = Sfr[nf][0] * 0.125f;
                sS[r0 * LDS_ + nf * 8 + c0 + 1] = Sfr[nf][1] * 0.125f;
                sS[r1 * LDS_ + nf * 8 + c0]     = Sfr[nf][2] * 0.125f;
                sS[r1 * LDS_ + nf * 8 + c0 + 1] = Sfr[nf][3] * 0.125f;
            }
        }
        __syncthreads();

        {
            int row = tid >> 1, half = tid & 1;
            float* srow = (float*)(sm + AS_OFF) + row * LDS_ + half * 32;
            int qglob = qbase + row;
            int kbase = t * 64 + half * 32;
            float sv[32];
#pragma unroll
            for (int c = 0; c < 32; c++) {
                float s_ = srow[c];
                if (kbase + c > qglob) s_ = -1e30f;
                sv[c] = s_;
            }
            float tmax = -1e30f;
#pragma unroll
            for (int c = 0; c < 32; c++) tmax = fmaxf(tmax, sv[c]);
            tmax = fmaxf(tmax, __shfl_xor_sync(0xffffffffu, tmax, 1));
            float mo = s_m[row];
            float nm = fmaxf(mo, tmax);
            float corr = __expf(mo - nm);
            float sum = 0.f;
            uint32_t* ph = (uint32_t*)(sm + AP_H) + (row * LDT + half * 32) / 2;
            uint32_t* pl = (uint32_t*)(sm + AP_L) + (row * LDT + half * 32) / 2;
#pragma unroll
            for (int c = 0; c < 32; c += 2) {
                float p0 = __expf(sv[c] - nm);
                float p1 = __expf(sv[c + 1] - nm);
                sum += p0 + p1;
                uint32_t h, l; split2(p0, p1, h, l);
                ph[c >> 1] = h; pl[c >> 1] = l;
            }
            sum += __shfl_xor_sync(0xffffffffu, sum, 1);
            if (half == 0) {
                s_m[row] = nm;
                s_l[row] = s_l[row] * corr + sum;
                s_c[row] = corr;
            }
        }
        __syncthreads();

        {
            float c_lo = s_c[wid * 16 + row_lo];
            float c_hi = s_c[wid * 16 + row_hi];
#pragma unroll
            for (int nf = 0; nf < 8; nf++) {
                O[nf][0] *= c_lo; O[nf][1] *= c_lo;
                O[nf][2] *= c_hi; O[nf][3] *= c_hi;
            }
        }
#pragma unroll
        for (int k = 0; k < 4; k++) {
            uint32_t ph0, ph1, ph2, ph3, pl0, pl1, pl2, pl3;
            ldsm4(ph0, ph1, ph2, ph3, smb + AP_H + arow + k * 32);
            ldsm4(pl0, pl1, pl2, pl3, smb + AP_L + arow + k * 32);
            uint32_t vrow = (uint32_t)(k * 16 + (lane & 7) + ((lane >> 3) & 1) * 8) * 144
                          + (uint32_t)((lane >> 4) & 1) * 16;
#pragma unroll
            for (int j = 0; j < 4; j++) {
                uint32_t vh0, vh1, vh2, vh3, vl0, vl1, vl2, vl3;
                ldsm4t(vh0, vh1, vh2, vh3, smb + AVOF(stg) + vrow + (uint32_t)j * 32);
                ldsm4t(vl0, vl1, vl2, vl3, smb + AVOF(stg) + 9216 + vrow + (uint32_t)j * 32);
                mma16816(O[j*2],   ph0, ph1, ph2, ph3, vh0, vh1);
                mma16816(O[j*2],   ph0, ph1, ph2, ph3, vl0, vl1);
                mma16816(O[j*2],   pl0, pl1, pl2, pl3, vh0, vh1);
                mma16816(O[j*2+1], ph0, ph1, ph2, ph3, vh2, vh3);
                mma16816(O[j*2+1], ph0, ph1, ph2, ph3, vl2, vl3);
                mma16816(O[j*2+1], pl0, pl1, pl2, pl3, vh2, vh3);
            }
        }
        __syncthreads();
    }

    {
        int b = bh >> 4, h = bh & 15;
        float linv0 = 1.f / s_l[wid * 16 + row_lo];
        float linv1 = 1.f / s_l[wid * 16 + row_hi];
        int q0 = qbase + wid * 16 + row_lo;
        int q1 = qbase + wid * 16 + row_hi;
        size_t base0 = (size_t)(b * Ss + q0) * 1024 + h * 64;
        size_t base1 = (size_t)(b * Ss + q1) * 1024 + h * 64;
        int c0 = (lane & 3) * 2;
#pragma unroll
        for (int nf = 0; nf < 8; nf++) {
            int col = nf * 8 + c0;
            *(__half2*)&g_ctxf[base0 + col] = __floats2half2_rn(O[nf][0] * linv0, O[nf][1] * linv0);
            *(__half2*)&g_ctxf[base1 + col] = __floats2half2_rn(O[nf][2] * linv1, O[nf][3] * linv1);
        }
    }
}

// ---------------- small kernels ----------------
__global__ void reset_kernel() {
    int t = threadIdx.x;
    if (t < Ee) { g_cnt[t] = 0; g_cur[t] = 0; }
}

__global__ void rmsnorm_kernel(const float* __restrict__ in,
                               const float* __restrict__ gamma,
                               float* __restrict__ out,
                               __half* __restrict__ ofh) {
    int row = blockIdx.x;
    const float* p = in + row * Dd;
    float ss = 0.f;
    for (int d = threadIdx.x; d < Dd; d += blockDim.x) { float v = p[d]; ss += v * v; }
    for (int o = 16; o; o >>= 1) ss += __shfl_xor_sync(0xffffffffu, ss, o);
    __shared__ float red[8];
    int w = threadIdx.x >> 5;
    if ((threadIdx.x & 31) == 0) red[w] = ss;
    __syncthreads();
    if (threadIdx.x < 8) {
        float v = red[threadIdx.x];
        for (int o = 4; o; o >>= 1) v += __shfl_xor_sync(0xffu, v, o);
        if (threadIdx.x == 0) red[0] = v;
    }
    __syncthreads();
    float rinv = rsqrtf(red[0] * (1.0f / Dd) + EPSf);
    for (int d = threadIdx.x * 2; d < Dd; d += blockDim.x * 2) {
        float v0 = p[d] * rinv * gamma[d];
        float v1 = p[d + 1] * rinv * gamma[d + 1];
        out[row * Dd + d]     = v0;
        out[row * Dd + d + 1] = v1;
        *(__half2*)&ofh[row * Dd + d] = __floats2half2_rn(v0, v1);
    }
}

__global__ void router_kernel(const float* __restrict__ an, const float* __restrict__ W,
                              const float* __restrict__ bias) {
    int tkn = blockIdx.x;
    __shared__ float xs[Dd];
    for (int d = threadIdx.x; d < Dd; d += 32) xs[d] = an[tkn * Dd + d];
    __syncwarp();
    int e = threadIdx.x;
    float logit = -1e30f;
    if (e < Ee) {
        float acc = bias[e];
        for (int d = 0; d < Dd; d++) acc += xs[d] * W[d * Ee + e];
        logit = acc;
    }
    float mx = logit;
    for (int o = 16; o; o >>= 1) mx = fmaxf(mx, __shfl_xor_sync(0xffffffffu, mx, o));
    float ex = (e < Ee) ? __expf(logit - mx) : 0.f;
    float sm = ex;
    for (int o = 16; o; o >>= 1) sm += __shfl_xor_sync(0xffffffffu, sm, o);
    float pw = ex / sm;
    for (int it = 0; it < 3; it++) {
        float bv = pw; int bi = e;
        for (int o = 16; o; o >>= 1) {
            float ov = __shfl_xor_sync(0xffffffffu, bv, o);
            int   oi = __shfl_xor_sync(0xffffffffu, bi, o);
            if (ov > bv || (ov == bv && oi < bi)) { bv = ov; bi = oi; }
        }
        if (threadIdx.x == 0) {
            g_topi[tkn * 3 + it] = bi;
            g_topv[tkn * 3 + it] = bv;
            atomicAdd(&g_cnt[bi], 1);
        }
        if (e == bi) pw = -1.f;
    }
}

__global__ void scan_kernel() {
    if (threadIdx.x == 0) {
        int s = 0;
        for (int e = 0; e < Ee; e++) { g_off[e] = s; s += g_cnt[e]; }
    }
}

__global__ void fill_kernel() {
    int i = blockIdx.x * 256 + threadIdx.x;
    if (i >= SLOTS) return;
    int tkn = i / 3, r = i - tkn * 3;
    int e = g_topi[i];
    int pos = atomicAdd(&g_cur[e], 1);
    int slot = g_off[e] + pos;
    g_slot_tok[slot] = tkn;
    g_slot_rank[slot] = r;
    g_slot_gate[slot] = g_topv[i];
}

__global__ void final_kernel(float* __restrict__ out) {
    int i = blockIdx.x * 256 + threadIdx.x;
    int t = i >> 10, n = i & 1023;
    float v = out[i];
    v += g_part[(size_t)(t * 3 + 0) * Dd + n];
    v += g_part[(size_t)(t * 3 + 1) * Dd + n];
    v += g_part[(size_t)(t * 3 + 2) * Dd + n];
    out[i] = v;
}

// ---------------- launch ----------------
extern "C" void kernel_launch(void* const* d_in, const int* in_sizes, int n_in,
                              void* d_out, int out_size) {
    const float* x      = (const float*)d_in[0];
    const float* theta  = (const float*)d_in[2];
    const float* gamma1 = (const float*)d_in[3];
    const float* gamma2 = (const float*)d_in[4];
    const float* q_w  = (const float*)d_in[5];  const float* q_b  = (const float*)d_in[6];
    const float* k_w  = (const float*)d_in[7];  const float* k_b  = (const float*)d_in[8];
    const float* v_w  = (const float*)d_in[9];  const float* v_b  = (const float*)d_in[10];
    const float* o_w  = (const float*)d_in[11]; const float* o_b  = (const float*)d_in[12];
    const float* r_w  = (const float*)d_in[13]; const float* r_b  = (const float*)d_in[14];
    const float* sw1  = (const float*)d_in[15]; const float* sb1  = (const float*)d_in[16];
    const float* sw2  = (const float*)d_in[17]; const float* sb2  = (const float*)d_in[18];
    const float* rw1  = (const float*)d_in[19]; const float* rb1  = (const float*)d_in[20];
    const float* rw2  = (const float*)d_in[21]; const float* rb2  = (const float*)d_in[22];
    float* out = (float*)d_out;

    float *xn, *attn, *an;
    __half *xnf, *ctxf, *anf, *t1f;
    __half *qw, *kw, *vw, *ow, *s1w, *s2w, *r1w, *r2w;
    cudaGetSymbolAddress((void**)&xn,   g_xn);
    cudaGetSymbolAddress((void**)&attn, g_attn);
    cudaGetSymbolAddress((void**)&an,   g_an);
    cudaGetSymbolAddress((void**)&xnf,  g_xnf);
    cudaGetSymbolAddress((void**)&ctxf, g_ctxf);
    cudaGetSymbolAddress((void**)&anf,  g_anf);
    cudaGetSymbolAddress((void**)&t1f,  g_t1f);
    cudaGetSymbolAddress((void**)&qw,   g_qw);
    cudaGetSymbolAddress((void**)&kw,   g_kw);
    cudaGetSymbolAddress((void**)&vw,   g_vw);
    cudaGetSymbolAddress((void**)&ow,   g_ow);
    cudaGetSymbolAddress((void**)&s1w,  g_s1);
    cudaGetSymbolAddress((void**)&s2w,  g_s2);
    cudaGetSymbolAddress((void**)&r1w,  g_r1);
    cudaGetSymbolAddress((void**)&r2w,  g_r2);

    cudaFuncSetAttribute(wm_gemm_f_kernel,   cudaFuncAttributeMaxDynamicSharedMemorySize, DYN_SMEM);
    cudaFuncSetAttribute(wm_qkv_f_kernel,    cudaFuncAttributeMaxDynamicSharedMemorySize, DYN_SMEM);
    cudaFuncSetAttribute(wm_egemm1f_kernel,  cudaFuncAttributeMaxDynamicSharedMemorySize, DYN_SMEM);
    cudaFuncSetAttribute(wm_egemm2f_kernel,  cudaFuncAttributeMaxDynamicSharedMemorySize, DYN_SMEM);
    cudaFuncSetAttribute(attn2_kernel,       cudaFuncAttributeMaxDynamicSharedMemorySize, ATTN_SMEM);

    static cudaStream_t s1 = nullptr;
    static cudaEvent_t evFork = nullptr, evOW = nullptr, evAN = nullptr, evPART = nullptr;
    if (!s1) {
        cudaStreamCreateWithFlags(&s1, cudaStreamNonBlocking);
        cudaEventCreateWithFlags(&evFork, cudaEventDisableTiming);
        cudaEventCreateWithFlags(&evOW,   cudaEventDisableTiming);
        cudaEventCreateWithFlags(&evAN,   cudaEventDisableTiming);
        cudaEventCreateWithFlags(&evPART, cudaEventDisableTiming);
    }

    dim3 thr(256);
    dim3 grid8x16(8, 16);

    // ---- fork: o/sh1/sh2 + expert conversions on s1 ----
    cudaEventRecord(evFork, 0);
    cudaStreamWaitEvent(s1, evFork, 0);
    convf3_kernel<<<dim3(D4 / 1024, 3), 256, 0, s1>>>(
        (const float4*)o_w, (const float4*)sw1, (const float4*)sw2,
        (uint2*)ow, (uint2*)s1w, (uint2*)s2w);
    cudaEventRecord(evOW, s1);
    convf_kernel<<<(E4 + 1023) / 1024, 256, 0, s1>>>((const float4*)rw1, (uint2*)r1w, E4);
    convf_kernel<<<(E4 + 1023) / 1024, 256, 0, s1>>>((const float4*)rw2, (uint2*)r2w, E4);

    // ---- main path ----
    convf3_kernel<<<dim3(D4 / 1024, 3), 256>>>(
        (const float4*)q_w, (const float4*)k_w, (const float4*)v_w,
        (uint2*)qw, (uint2*)kw, (uint2*)vw);
    reset_kernel<<<1, 32>>>();
    rmsnorm_kernel<<<NT, 256>>>(x, gamma1, xn, xnf);

    wm_qkv_f_kernel<<<dim3(8, 16, 3), thr, DYN_SMEM>>>(q_b, k_b, v_b, theta);

    attn2_kernel<<<dim3(8, Bb * Hh), 256, ATTN_SMEM>>>();

    cudaStreamWaitEvent(0, evOW, 0);
    wm_gemm_f_kernel<<<grid8x16, thr, DYN_SMEM>>>(ctxf, ow, o_b, 2, xn, nullptr,
                                                  attn, nullptr);
    rmsnorm_kernel<<<NT, 256>>>(attn, gamma2, an, anf);
    cudaEventRecord(evAN, 0);

    // ---- expert path on s1 ----
    cudaStreamWaitEvent(s1, evAN, 0);
    router_kernel<<<NT, 32, 0, s1>>>(an, r_w, r_b);
    scan_kernel<<<1, 32, 0, s1>>>();
    fill_kernel<<<(SLOTS + 255) / 256, 256, 0, s1>>>();
    wm_egemm1f_kernel<<<dim3(8, 16, Ee), thr, DYN_SMEM, s1>>>(rb1);
    wm_egemm2f_kernel<<<dim3(8, 16, Ee), thr, DYN_SMEM, s1>>>(rb2);
    cudaEventRecord(evPART, s1);

    // ---- shared MLP concurrent on s0 ----
    wm_gemm_f_kernel<<<grid8x16, thr, DYN_SMEM>>>(anf, s1w, sb1, 1, nullptr, nullptr,
                                                  nullptr, t1f);
    wm_gemm_f_kernel<<<grid8x16, thr, DYN_SMEM>>>(t1f, s2w, sb2, 2, an, attn,
                                                  out, nullptr);

    // ---- join + final ----
    cudaStreamWaitEvent(0, evPART, 0);
    final_kernel<<<(NT * Dd) / 256, 256>>>(out);
}